// round 1
// baseline (speedup 1.0000x reference)
#include <cuda_runtime.h>
#include <math.h>

#define BB 64
#define TT 256
#define HH 1024
#define VV 128
#define NG 4096   // 4*H

// ---------------- device scratch (no allocations allowed) ----------------
__device__ float g_gx[BB * TT * NG];      // 256 MB  gate pre-activations (reused per layer)
__device__ float g_y0[BB * TT * HH];      // 64 MB   layer-0 output
__device__ float g_y1[BB * TT * HH];      // 64 MB   layer-1 output
__device__ float g_h[BB * HH];            // hidden state
__device__ float g_c[BB * HH];            // cell state
__device__ float g_part[8 * BB * NG];     // 8 MB    k-split partials
__device__ unsigned g_barc;               // barrier counter (self-resetting)
__device__ volatile unsigned g_bars;      // barrier sense

// ---------------- grid-wide sense-reversing barrier ----------------
// Counter resets to 0 inside every barrier -> deterministic across graph replays.
__device__ __forceinline__ void grid_bar(unsigned* sense) {
    __syncthreads();
    if (threadIdx.x == 0) {
        unsigned s = *sense ^ 1u;
        *sense = s;
        __threadfence();
        unsigned prev = atomicAdd(&g_barc, 1u);
        if (prev == gridDim.x - 1) {
            g_barc = 0u;
            __threadfence();
            g_bars = s;
        } else {
            while (g_bars != s) { __nanosleep(20); }
        }
    }
    __syncthreads();
}

// ---------------- generic SGEMM: C[M,N] = A[M,K] @ W[N,K]^T + bias[N] ----------------
// BM=128, BN=128, BK=16, 256 threads, 8x8 per thread. Dims must divide tiles.
// GATHER: A row m is emb row tok[m] (embedding lookup fused into the GEMM).
template <bool GATHER>
__global__ __launch_bounds__(256, 2)
void sgemm_bias(const float* __restrict__ A, const int* __restrict__ tok,
                const float* __restrict__ W, const float* __restrict__ bias,
                float* __restrict__ C, int M, int N, int K)
{
    __shared__ float As[16][128];
    __shared__ float Bs[16][128];

    const int m0 = blockIdx.y * 128;
    const int n0 = blockIdx.x * 128;
    const int tid = threadIdx.x;
    const int ty = tid >> 4;      // 0..15 -> rows ty*8
    const int tx = tid & 15;      // 0..15 -> cols tx*8

    // Each thread loads 8 consecutive floats (2 float4) of one row per tile.
    const int lrow = tid >> 1;          // 0..127
    const int lq   = (tid & 1) * 8;     // 0 or 8

    const float* arow;
    if (GATHER) arow = A + (size_t)tok[m0 + lrow] * K;
    else        arow = A + (size_t)(m0 + lrow) * K;
    const float* wrow = W + (size_t)(n0 + lrow) * K;

    float acc[8][8];
    #pragma unroll
    for (int i = 0; i < 8; i++)
        #pragma unroll
        for (int j = 0; j < 8; j++) acc[i][j] = 0.f;

    for (int k0 = 0; k0 < K; k0 += 16) {
        float4 a0 = *(const float4*)(arow + k0 + lq);
        float4 a1 = *(const float4*)(arow + k0 + lq + 4);
        float4 b0 = *(const float4*)(wrow + k0 + lq);
        float4 b1 = *(const float4*)(wrow + k0 + lq + 4);
        As[lq + 0][lrow] = a0.x; As[lq + 1][lrow] = a0.y;
        As[lq + 2][lrow] = a0.z; As[lq + 3][lrow] = a0.w;
        As[lq + 4][lrow] = a1.x; As[lq + 5][lrow] = a1.y;
        As[lq + 6][lrow] = a1.z; As[lq + 7][lrow] = a1.w;
        Bs[lq + 0][lrow] = b0.x; Bs[lq + 1][lrow] = b0.y;
        Bs[lq + 2][lrow] = b0.z; Bs[lq + 3][lrow] = b0.w;
        Bs[lq + 4][lrow] = b1.x; Bs[lq + 5][lrow] = b1.y;
        Bs[lq + 6][lrow] = b1.z; Bs[lq + 7][lrow] = b1.w;
        __syncthreads();

        #pragma unroll
        for (int k = 0; k < 16; k++) {
            float ra[8], rb[8];
            *(float4*)(ra)     = *(const float4*)&As[k][ty * 8];
            *(float4*)(ra + 4) = *(const float4*)&As[k][ty * 8 + 4];
            *(float4*)(rb)     = *(const float4*)&Bs[k][tx * 8];
            *(float4*)(rb + 4) = *(const float4*)&Bs[k][tx * 8 + 4];
            #pragma unroll
            for (int i = 0; i < 8; i++)
                #pragma unroll
                for (int j = 0; j < 8; j++)
                    acc[i][j] += ra[i] * rb[j];
        }
        __syncthreads();
    }

    float bv[8];
    #pragma unroll
    for (int j = 0; j < 8; j++) bv[j] = bias[n0 + tx * 8 + j];

    #pragma unroll
    for (int i = 0; i < 8; i++) {
        float* cp = C + (size_t)(m0 + ty * 8 + i) * N + n0 + tx * 8;
        float4 o0, o1;
        o0.x = acc[i][0] + bv[0]; o0.y = acc[i][1] + bv[1];
        o0.z = acc[i][2] + bv[2]; o0.w = acc[i][3] + bv[3];
        o1.x = acc[i][4] + bv[4]; o1.y = acc[i][5] + bv[5];
        o1.z = acc[i][6] + bv[6]; o1.w = acc[i][7] + bv[7];
        *(float4*)(cp)     = o0;
        *(float4*)(cp + 4) = o1;
    }
}

// ---------------- persistent LSTM layer kernel ----------------
// grid = 128 CTAs (16 column tiles of 256 cols x 8 K-splits of 128), 256 threads.
// Per step:
//   Phase A: partial[ks][b][col] = sum_{k in split} h[b][k] * Whh[col][k]
//   barrier
//   Phase B: reduce 8 partials + gx -> gates -> update c,h, write y[:,t,:]
//   barrier
__global__ __launch_bounds__(256, 1)
void lstm_layer(const float* __restrict__ gx, const float* __restrict__ Whh,
                const float* __restrict__ h0, const float* __restrict__ c0,
                float* __restrict__ y)
{
    __shared__ float hs[16][64];
    __shared__ float Ws[16][256];

    const int tid = threadIdx.x;
    const int bid = blockIdx.x;       // 0..127
    const int cs  = bid & 15;         // column tile (256 cols)
    const int ks  = bid >> 4;         // k-split (128 k)
    const int ty  = tid >> 5;         // 0..7  -> b rows ty*8
    const int tx  = tid & 31;         // 0..31 -> cols tx*8
    const int col0 = cs * 256;
    const int gtid = bid * 256 + tid;

    unsigned sense = g_bars;          // read initial sense before first arrival

    // init state from h0/c0 (inputs must not be modified)
    #pragma unroll
    for (int i = gtid; i < BB * HH; i += 128 * 256) {
        g_h[i] = h0[i];
        g_c[i] = c0[i];
    }
    grid_bar(&sense);

    const int hrow = tid >> 2;        // 0..63
    const int hq   = (tid & 3) * 4;   // 0,4,8,12
    const float* wbase = Whh + (size_t)(col0 + tid) * HH;

    for (int t = 0; t < TT; t++) {
        float acc[8][8];
        #pragma unroll
        for (int i = 0; i < 8; i++)
            #pragma unroll
            for (int j = 0; j < 8; j++) acc[i][j] = 0.f;

        #pragma unroll 1
        for (int kc = 0; kc < 8; kc++) {
            const int k0 = ks * 128 + kc * 16;
            // stage h chunk [64 b][16 k] -> hs[k][b]
            {
                float4 v = *(const float4*)&g_h[hrow * HH + k0 + hq];
                hs[hq + 0][hrow] = v.x; hs[hq + 1][hrow] = v.y;
                hs[hq + 2][hrow] = v.z; hs[hq + 3][hrow] = v.w;
            }
            // stage W chunk [256 cols][16 k] -> Ws[k][col] (one col per thread)
            {
                const float* wp = wbase + k0;
                float4 v0 = *(const float4*)(wp);
                float4 v1 = *(const float4*)(wp + 4);
                float4 v2 = *(const float4*)(wp + 8);
                float4 v3 = *(const float4*)(wp + 12);
                Ws[0][tid] = v0.x;  Ws[1][tid] = v0.y;  Ws[2][tid] = v0.z;  Ws[3][tid] = v0.w;
                Ws[4][tid] = v1.x;  Ws[5][tid] = v1.y;  Ws[6][tid] = v1.z;  Ws[7][tid] = v1.w;
                Ws[8][tid] = v2.x;  Ws[9][tid] = v2.y;  Ws[10][tid] = v2.z; Ws[11][tid] = v2.w;
                Ws[12][tid] = v3.x; Ws[13][tid] = v3.y; Ws[14][tid] = v3.z; Ws[15][tid] = v3.w;
            }
            __syncthreads();
            #pragma unroll
            for (int k = 0; k < 16; k++) {
                float ra[8], rb[8];
                *(float4*)(ra)     = *(const float4*)&hs[k][ty * 8];
                *(float4*)(ra + 4) = *(const float4*)&hs[k][ty * 8 + 4];
                *(float4*)(rb)     = *(const float4*)&Ws[k][tx * 8];
                *(float4*)(rb + 4) = *(const float4*)&Ws[k][tx * 8 + 4];
                #pragma unroll
                for (int i = 0; i < 8; i++)
                    #pragma unroll
                    for (int j = 0; j < 8; j++)
                        acc[i][j] += ra[i] * rb[j];
            }
            __syncthreads();
        }

        // write partials P[ks][b][col]
        #pragma unroll
        for (int i = 0; i < 8; i++) {
            const int b = ty * 8 + i;
            float* pp = &g_part[((size_t)ks * BB + b) * NG + col0 + tx * 8];
            float4 o0, o1;
            o0.x = acc[i][0]; o0.y = acc[i][1]; o0.z = acc[i][2]; o0.w = acc[i][3];
            o1.x = acc[i][4]; o1.y = acc[i][5]; o1.z = acc[i][6]; o1.w = acc[i][7];
            *(float4*)(pp)     = o0;
            *(float4*)(pp + 4) = o1;
        }
        __threadfence();
        grid_bar(&sense);

        // Phase B: 65536 (b,j) cells, 2 per thread
        #pragma unroll
        for (int it = 0; it < 2; it++) {
            const int cell = gtid + it * 32768;
            const int b = cell >> 10;
            const int j = cell & 1023;
            float gi = 0.f, gf = 0.f, gg = 0.f, go = 0.f;
            #pragma unroll
            for (int s = 0; s < 8; s++) {
                const float* pp = &g_part[((size_t)s * BB + b) * NG + j];
                gi += pp[0];
                gf += pp[1024];
                gg += pp[2048];
                go += pp[3072];
            }
            const float* gr = gx + ((size_t)b * TT + t) * NG;
            gi += gr[j];
            gf += gr[j + 1024];
            gg += gr[j + 2048];
            go += gr[j + 3072];

            float cv = g_c[cell];
            const float si = 1.f / (1.f + __expf(-gi));
            const float sf = 1.f / (1.f + __expf(-gf));
            const float so = 1.f / (1.f + __expf(-go));
            cv = sf * cv + si * tanhf(gg);
            const float hv = so * tanhf(cv);
            g_c[cell] = cv;
            g_h[cell] = hv;
            y[((size_t)b * TT + t) * HH + j] = hv;
        }
        __threadfence();
        grid_bar(&sense);
    }
}

// ---------------- launch ----------------
extern "C" void kernel_launch(void* const* d_in, const int* in_sizes, int n_in,
                              void* d_out, int out_size)
{
    const int*   x    = (const int*)  d_in[0];
    const float* emb  = (const float*)d_in[1];
    const float* Wih0 = (const float*)d_in[2];
    const float* Whh0 = (const float*)d_in[3];
    const float* b0   = (const float*)d_in[4];
    const float* Wih1 = (const float*)d_in[5];
    const float* Whh1 = (const float*)d_in[6];
    const float* b1   = (const float*)d_in[7];
    const float* fcW  = (const float*)d_in[8];
    const float* fcb  = (const float*)d_in[9];
    const float* h0   = (const float*)d_in[10];
    const float* c0   = (const float*)d_in[11];
    float* out = (float*)d_out;

    float *gx, *y0, *y1;
    cudaGetSymbolAddress((void**)&gx, g_gx);
    cudaGetSymbolAddress((void**)&y0, g_y0);
    cudaGetSymbolAddress((void**)&y1, g_y1);

    const int M = BB * TT;  // 16384

    // layer 0 input projection (embedding gather fused) -> gx
    sgemm_bias<true><<<dim3(NG / 128, M / 128), 256>>>(emb, x, Wih0, b0, gx, M, NG, HH);
    // layer 0 recurrence
    lstm_layer<<<128, 256>>>(gx, Whh0, h0, c0, y0);
    // layer 1 input projection -> gx (reuse)
    sgemm_bias<false><<<dim3(NG / 128, M / 128), 256>>>(y0, nullptr, Wih1, b1, gx, M, NG, HH);
    // layer 1 recurrence
    lstm_layer<<<128, 256>>>(gx, Whh1, h0 + BB * HH, c0 + BB * HH, y1);
    // final FC -> out
    sgemm_bias<false><<<dim3(VV / 128, M / 128), 256>>>(y1, nullptr, fcW, fcb, out, M, VV, HH);
}

// round 3
// speedup vs baseline: 1.0103x; 1.0103x over previous
#include <cuda_runtime.h>
#include <math.h>
#include <stdint.h>

#define BB 64
#define TT 256
#define HH 1024
#define VV 128
#define NG 4096   // 4*H

// ---------------- device scratch (no allocations allowed) ----------------
__device__ float g_gx[BB * TT * NG];        // gate pre-activations (fp32)
__device__ float g_y0b[BB * TT * HH];       // layer-0 output, tf32 big
__device__ float g_y0s[BB * TT * HH];       // layer-0 output, tf32 small
__device__ float g_y1b[BB * TT * HH];       // layer-1 output, tf32 big
__device__ float g_y1s[BB * TT * HH];       // layer-1 output, tf32 small
__device__ float g_h[BB * HH];              // hidden state (full fp32)
__device__ float g_c[BB * HH];              // cell state (fp32)
__device__ float g_part[8 * BB * NG];       // k-split partials
__device__ float g_wAb[NG * HH];            // W_ih / fc_W big
__device__ float g_wAs[NG * HH];            // W_ih / fc_W small
__device__ float g_wRb[NG * HH];            // W_hh big
__device__ float g_wRs[NG * HH];            // W_hh small
__device__ float g_embb[VV * HH];           // embedding big
__device__ float g_embs[VV * HH];           // embedding small
__device__ unsigned g_barc;                 // barrier counter (self-resetting)
__device__ volatile unsigned g_bars;        // barrier sense

// ---------------- helpers ----------------
__device__ __forceinline__ float tf32r(float x) {
    uint32_t u;
    asm("cvt.rna.tf32.f32 %0, %1;" : "=r"(u) : "f"(x));
    return __uint_as_float(u);
}

__device__ __forceinline__ void mma_tf32(float* d, const uint32_t* a, const uint32_t* b) {
    asm volatile(
        "mma.sync.aligned.m16n8k8.row.col.f32.tf32.tf32.f32 "
        "{%0,%1,%2,%3}, {%4,%5,%6,%7}, {%8,%9}, {%0,%1,%2,%3};\n"
        : "+f"(d[0]), "+f"(d[1]), "+f"(d[2]), "+f"(d[3])
        : "r"(a[0]), "r"(a[1]), "r"(a[2]), "r"(a[3]), "r"(b[0]), "r"(b[1]));
}

// Shared tiles are k-major with XOR swizzle: phys_col = c ^ (8*(k&3)).
// One BK=16 tile of mma work: acc[mf][nf] += A(64 rows from mbase) x B(32 cols from nbase)
template<int LDA, int LDB>
__device__ __forceinline__ void mma_tile16(const float* As, const float* Bs,
                                           float acc[4][4][4],
                                           int mbase, int nbase, int r, int q) {
    const uint32_t* A32 = (const uint32_t*)As;
    const uint32_t* B32 = (const uint32_t*)Bs;
    const int csw = 8 * r;
    #pragma unroll
    for (int kk = 0; kk < 2; kk++) {
        const int row0 = kk * 8 + r;
        const int row1 = row0 + 4;
        uint32_t af[4][4], bf[4][2];
        #pragma unroll
        for (int mf = 0; mf < 4; mf++) {
            const int c0 = (mbase + mf * 16 + q) ^ csw;
            const int c1 = (mbase + mf * 16 + 8 + q) ^ csw;
            af[mf][0] = A32[row0 * LDA + c0];
            af[mf][1] = A32[row0 * LDA + c1];
            af[mf][2] = A32[row1 * LDA + c0];
            af[mf][3] = A32[row1 * LDA + c1];
        }
        #pragma unroll
        for (int nf = 0; nf < 4; nf++) {
            const int cb = (nbase + nf * 8 + q) ^ csw;
            bf[nf][0] = B32[row0 * LDB + cb];
            bf[nf][1] = B32[row1 * LDB + cb];
        }
        #pragma unroll
        for (int mf = 0; mf < 4; mf++)
            #pragma unroll
            for (int nf = 0; nf < 4; nf++)
                mma_tf32(acc[mf][nf], af[mf], bf[nf]);
    }
}

// ---------------- grid-wide sense-reversing barrier ----------------
__device__ __forceinline__ void grid_bar(unsigned* sense) {
    __syncthreads();
    if (threadIdx.x == 0) {
        unsigned s = *sense ^ 1u;
        *sense = s;
        __threadfence();
        unsigned prev = atomicAdd(&g_barc, 1u);
        if (prev == gridDim.x - 1) {
            g_barc = 0u;
            __threadfence();
            g_bars = s;
        } else {
            while (g_bars != s) { __nanosleep(8); }
        }
    }
    __syncthreads();
}

// ---------------- fp32 -> (tf32 big, tf32 small) split ----------------
__global__ void cvt_split_kernel(const float* __restrict__ src,
                                 float* __restrict__ dstb, float* __restrict__ dsts, int n) {
    for (int i = blockIdx.x * blockDim.x + threadIdx.x; i < n; i += gridDim.x * blockDim.x) {
        const float x = src[i];
        const float b = tf32r(x);
        dstb[i] = b;
        dsts[i] = tf32r(x - b);
    }
}

// ---------------- 3xTF32 SGEMM: C[M,N] = A[M,K] @ W[N,K]^T + bias[N] ----------------
// BM=128, BN=128, BK=16, 256 threads = 8 warps (2m x 4n), warp tile 64x32.
// Computes Ab*Wb + Ab*Ws + As*Wb in fp32 accumulators (near-fp32 precision).
template <bool GATHER>
__global__ __launch_bounds__(256, 1)
void sgemm_3xtf32(const float* __restrict__ Ab, const float* __restrict__ As_,
                  const int* __restrict__ tok,
                  const float* __restrict__ Wb, const float* __restrict__ Ws_,
                  const float* __restrict__ bias,
                  float* __restrict__ C, int M, int N, int K)
{
    __shared__ float Atb[16 * 128];
    __shared__ float Ats[16 * 128];
    __shared__ float Btb[16 * 128];
    __shared__ float Bts[16 * 128];

    const int m0 = blockIdx.y * 128;
    const int n0 = blockIdx.x * 128;
    const int tid = threadIdx.x;
    const int warp = tid >> 5;
    const int lane = tid & 31;
    const int r = lane & 3;
    const int q = lane >> 2;
    const int wm = warp >> 2;          // 0..1
    const int wn = warp & 3;           // 0..3
    const int mbase = wm * 64;
    const int nbase = wn * 32;

    const int lrow = tid >> 1;          // 0..127
    const int lq   = (tid & 1) * 8;     // 0 or 8

    size_t aoff;
    if (GATHER) aoff = (size_t)tok[m0 + lrow] * K;
    else        aoff = (size_t)(m0 + lrow) * K;
    const float* arb = Ab  + aoff;
    const float* ars = As_ + aoff;
    const float* wrb = Wb  + (size_t)(n0 + lrow) * K;
    const float* wrs = Ws_ + (size_t)(n0 + lrow) * K;

    float acc[4][4][4];
    #pragma unroll
    for (int mf = 0; mf < 4; mf++)
        #pragma unroll
        for (int nf = 0; nf < 4; nf++)
            #pragma unroll
            for (int i = 0; i < 4; i++) acc[mf][nf][i] = 0.f;

    // prefetch tile 0
    float4 pab0 = *(const float4*)(arb + lq);
    float4 pab1 = *(const float4*)(arb + lq + 4);
    float4 pas0 = *(const float4*)(ars + lq);
    float4 pas1 = *(const float4*)(ars + lq + 4);
    float4 pwb0 = *(const float4*)(wrb + lq);
    float4 pwb1 = *(const float4*)(wrb + lq + 4);
    float4 pws0 = *(const float4*)(wrs + lq);
    float4 pws1 = *(const float4*)(wrs + lq + 4);

    for (int k0 = 0; k0 < K; k0 += 16) {
        {
            float ab[8] = {pab0.x, pab0.y, pab0.z, pab0.w, pab1.x, pab1.y, pab1.z, pab1.w};
            float as[8] = {pas0.x, pas0.y, pas0.z, pas0.w, pas1.x, pas1.y, pas1.z, pas1.w};
            float wb[8] = {pwb0.x, pwb0.y, pwb0.z, pwb0.w, pwb1.x, pwb1.y, pwb1.z, pwb1.w};
            float ws[8] = {pws0.x, pws0.y, pws0.z, pws0.w, pws1.x, pws1.y, pws1.z, pws1.w};
            #pragma unroll
            for (int j = 0; j < 8; j++) {
                const int k = lq + j;
                const int sc = lrow ^ (8 * (k & 3));
                Atb[k * 128 + sc] = ab[j];
                Ats[k * 128 + sc] = as[j];
                Btb[k * 128 + sc] = wb[j];
                Bts[k * 128 + sc] = ws[j];
            }
        }
        __syncthreads();

        if (k0 + 16 < K) {
            pab0 = *(const float4*)(arb + k0 + 16 + lq);
            pab1 = *(const float4*)(arb + k0 + 16 + lq + 4);
            pas0 = *(const float4*)(ars + k0 + 16 + lq);
            pas1 = *(const float4*)(ars + k0 + 16 + lq + 4);
            pwb0 = *(const float4*)(wrb + k0 + 16 + lq);
            pwb1 = *(const float4*)(wrb + k0 + 16 + lq + 4);
            pws0 = *(const float4*)(wrs + k0 + 16 + lq);
            pws1 = *(const float4*)(wrs + k0 + 16 + lq + 4);
        }

        mma_tile16<128, 128>(Atb, Btb, acc, mbase, nbase, r, q);
        mma_tile16<128, 128>(Atb, Bts, acc, mbase, nbase, r, q);
        mma_tile16<128, 128>(Ats, Btb, acc, mbase, nbase, r, q);
        __syncthreads();
    }

    #pragma unroll
    for (int nf = 0; nf < 4; nf++) {
        const int n = n0 + nbase + nf * 8 + 2 * r;
        const float b0v = bias[n];
        const float b1v = bias[n + 1];
        #pragma unroll
        for (int mf = 0; mf < 4; mf++) {
            const int m = m0 + mbase + mf * 16 + q;
            float2 o0 = {acc[mf][nf][0] + b0v, acc[mf][nf][1] + b1v};
            float2 o1 = {acc[mf][nf][2] + b0v, acc[mf][nf][3] + b1v};
            *(float2*)(C + (size_t)m * N + n)       = o0;
            *(float2*)(C + (size_t)(m + 8) * N + n) = o1;
        }
    }
}

// ---------------- persistent LSTM layer kernel (3xTF32 tensor cores) ----------------
// grid = 128 CTAs (16 column tiles of 256 cols x 8 K-splits of 128), 256 threads.
__global__ __launch_bounds__(256, 1)
void lstm_layer(const float* __restrict__ gx,
                const float* __restrict__ Wtb, const float* __restrict__ Wts,
                const float* __restrict__ h0, const float* __restrict__ c0,
                float* __restrict__ yb, float* __restrict__ ys)
{
    __shared__ float hsb[16 * 64];
    __shared__ float hss[16 * 64];
    __shared__ float Wsb[16 * 256];
    __shared__ float Wss[16 * 256];

    const int tid = threadIdx.x;
    const int bid = blockIdx.x;       // 0..127
    const int cs  = bid & 15;         // column tile (256 cols)
    const int ks  = bid >> 4;         // k-split (128 k)
    const int col0 = cs * 256;
    const int gtid = bid * 256 + tid;

    const int warp = tid >> 5;
    const int lane = tid & 31;
    const int r = lane & 3;
    const int q = lane >> 2;
    const int nbase = warp * 32;      // warp tile 64x32 within 64x256 CTA tile

    unsigned sense = g_bars;

    // init state (full fp32)
    for (int i = gtid; i < BB * HH; i += 128 * 256) {
        g_h[i] = h0[i];
        g_c[i] = c0[i];
    }
    grid_bar(&sense);

    const int hrow = tid >> 2;              // 0..63 (b)
    const int hq   = (tid & 3) * 4;         // 0,4,8,12 (k)
    const float* wbb = Wtb + (size_t)(col0 + tid) * HH + ks * 128;
    const float* wbs = Wts + (size_t)(col0 + tid) * HH + ks * 128;
    const float* hbase = g_h + (size_t)hrow * HH + ks * 128;

    for (int t = 0; t < TT; t++) {
        float acc[4][4][4];
        #pragma unroll
        for (int mf = 0; mf < 4; mf++)
            #pragma unroll
            for (int nf = 0; nf < 4; nf++)
                #pragma unroll
                for (int i = 0; i < 4; i++) acc[mf][nf][i] = 0.f;

        // prefetch chunk 0
        float4 hv  = *(const float4*)(hbase + hq);
        float4 wb0 = *(const float4*)(wbb + 0);
        float4 wb1 = *(const float4*)(wbb + 4);
        float4 wb2 = *(const float4*)(wbb + 8);
        float4 wb3 = *(const float4*)(wbb + 12);
        float4 ws0 = *(const float4*)(wbs + 0);
        float4 ws1 = *(const float4*)(wbs + 4);
        float4 ws2 = *(const float4*)(wbs + 8);
        float4 ws3 = *(const float4*)(wbs + 12);

        #pragma unroll 1
        for (int kc = 0; kc < 8; kc++) {
            // stage h chunk split on the fly: hsb/hss[k][b], swizzled
            {
                float hvv[4] = {hv.x, hv.y, hv.z, hv.w};
                #pragma unroll
                for (int j = 0; j < 4; j++) {
                    const float big = tf32r(hvv[j]);
                    const int idx = (hq + j) * 64 + (hrow ^ (8 * j));
                    hsb[idx] = big;
                    hss[idx] = tf32r(hvv[j] - big);
                }
            }
            // stage W chunks (pre-split): Wsb/Wss[k][col=tid], swizzled
            {
                float wbv[16] = {wb0.x, wb0.y, wb0.z, wb0.w, wb1.x, wb1.y, wb1.z, wb1.w,
                                 wb2.x, wb2.y, wb2.z, wb2.w, wb3.x, wb3.y, wb3.z, wb3.w};
                float wsv[16] = {ws0.x, ws0.y, ws0.z, ws0.w, ws1.x, ws1.y, ws1.z, ws1.w,
                                 ws2.x, ws2.y, ws2.z, ws2.w, ws3.x, ws3.y, ws3.z, ws3.w};
                #pragma unroll
                for (int k = 0; k < 16; k++) {
                    const int idx = k * 256 + (tid ^ (8 * (k & 3)));
                    Wsb[idx] = wbv[k];
                    Wss[idx] = wsv[k];
                }
            }
            __syncthreads();

            if (kc < 7) {
                const int k0 = (kc + 1) * 16;
                hv  = *(const float4*)(hbase + k0 + hq);
                wb0 = *(const float4*)(wbb + k0 + 0);
                wb1 = *(const float4*)(wbb + k0 + 4);
                wb2 = *(const float4*)(wbb + k0 + 8);
                wb3 = *(const float4*)(wbb + k0 + 12);
                ws0 = *(const float4*)(wbs + k0 + 0);
                ws1 = *(const float4*)(wbs + k0 + 4);
                ws2 = *(const float4*)(wbs + k0 + 8);
                ws3 = *(const float4*)(wbs + k0 + 12);
            }

            mma_tile16<64, 256>(hsb, Wsb, acc, 0, nbase, r, q);
            mma_tile16<64, 256>(hsb, Wss, acc, 0, nbase, r, q);
            mma_tile16<64, 256>(hss, Wsb, acc, 0, nbase, r, q);
            __syncthreads();
        }

        // write partials P[ks][b][col]
        #pragma unroll
        for (int nf = 0; nf < 4; nf++) {
            const int col = col0 + nbase + nf * 8 + 2 * r;
            #pragma unroll
            for (int mf = 0; mf < 4; mf++) {
                const int b = mf * 16 + q;
                float2 o0 = {acc[mf][nf][0], acc[mf][nf][1]};
                float2 o1 = {acc[mf][nf][2], acc[mf][nf][3]};
                *(float2*)(&g_part[((size_t)ks * BB + b) * NG + col])     = o0;
                *(float2*)(&g_part[((size_t)ks * BB + b + 8) * NG + col]) = o1;
            }
        }
        __threadfence();
        grid_bar(&sense);

        // Phase B: 65536 (b,j) cells, 2 per thread
        #pragma unroll
        for (int it = 0; it < 2; it++) {
            const int cell = gtid + it * 32768;
            const int b = cell >> 10;
            const int j = cell & 1023;
            float gi = 0.f, gf = 0.f, gg = 0.f, go = 0.f;
            #pragma unroll
            for (int s = 0; s < 8; s++) {
                const float* pp = &g_part[((size_t)s * BB + b) * NG + j];
                gi += pp[0];
                gf += pp[1024];
                gg += pp[2048];
                go += pp[3072];
            }
            const float* gr = gx + ((size_t)b * TT + t) * NG;
            gi += gr[j];
            gf += gr[j + 1024];
            gg += gr[j + 2048];
            go += gr[j + 3072];

            float cv = g_c[cell];
            const float si = 1.f / (1.f + __expf(-gi));
            const float sf = 1.f / (1.f + __expf(-gf));
            const float so = 1.f / (1.f + __expf(-go));
            cv = sf * cv + si * tanhf(gg);
            const float hvv = so * tanhf(cv);
            g_c[cell] = cv;
            g_h[cell] = hvv;
            const float hb = tf32r(hvv);
            const size_t yi = ((size_t)b * TT + t) * HH + j;
            yb[yi] = hb;
            ys[yi] = tf32r(hvv - hb);
        }
        __threadfence();
        grid_bar(&sense);
    }
}

// ---------------- launch ----------------
extern "C" void kernel_launch(void* const* d_in, const int* in_sizes, int n_in,
                              void* d_out, int out_size)
{
    const int*   x    = (const int*)  d_in[0];
    const float* emb  = (const float*)d_in[1];
    const float* Wih0 = (const float*)d_in[2];
    const float* Whh0 = (const float*)d_in[3];
    const float* b0   = (const float*)d_in[4];
    const float* Wih1 = (const float*)d_in[5];
    const float* Whh1 = (const float*)d_in[6];
    const float* b1   = (const float*)d_in[7];
    const float* fcW  = (const float*)d_in[8];
    const float* fcb  = (const float*)d_in[9];
    const float* h0   = (const float*)d_in[10];
    const float* c0   = (const float*)d_in[11];
    float* out = (float*)d_out;

    float *gx, *y0b, *y0s, *y1b, *y1s, *wAb, *wAs, *wRb, *wRs, *embb, *embs;
    cudaGetSymbolAddress((void**)&gx,   g_gx);
    cudaGetSymbolAddress((void**)&y0b,  g_y0b);
    cudaGetSymbolAddress((void**)&y0s,  g_y0s);
    cudaGetSymbolAddress((void**)&y1b,  g_y1b);
    cudaGetSymbolAddress((void**)&y1s,  g_y1s);
    cudaGetSymbolAddress((void**)&wAb,  g_wAb);
    cudaGetSymbolAddress((void**)&wAs,  g_wAs);
    cudaGetSymbolAddress((void**)&wRb,  g_wRb);
    cudaGetSymbolAddress((void**)&wRs,  g_wRs);
    cudaGetSymbolAddress((void**)&embb, g_embb);
    cudaGetSymbolAddress((void**)&embs, g_embs);

    const int M = BB * TT;  // 16384

    // splits
    cvt_split_kernel<<<512, 256>>>(emb, embb, embs, VV * HH);
    cvt_split_kernel<<<4096, 256>>>(Wih0, wAb, wAs, NG * HH);
    cvt_split_kernel<<<4096, 256>>>(Whh0, wRb, wRs, NG * HH);

    // layer 0 input projection (embedding gather fused) -> gx
    sgemm_3xtf32<true><<<dim3(NG / 128, M / 128), 256>>>(embb, embs, x, wAb, wAs, b0, gx, M, NG, HH);
    // layer 0 recurrence
    lstm_layer<<<128, 256>>>(gx, wRb, wRs, h0, c0, y0b, y0s);

    // layer 1 weights
    cvt_split_kernel<<<4096, 256>>>(Wih1, wAb, wAs, NG * HH);
    cvt_split_kernel<<<4096, 256>>>(Whh1, wRb, wRs, NG * HH);

    // layer 1 input projection -> gx (reuse)
    sgemm_3xtf32<false><<<dim3(NG / 128, M / 128), 256>>>(y0b, y0s, nullptr, wAb, wAs, b1, gx, M, NG, HH);
    // layer 1 recurrence
    lstm_layer<<<128, 256>>>(gx, wRb, wRs, h0 + BB * HH, c0 + BB * HH, y1b, y1s);

    // final FC -> out
    cvt_split_kernel<<<1024, 256>>>(fcW, wAb, wAs, VV * HH);
    sgemm_3xtf32<false><<<dim3(VV / 128, M / 128), 256>>>(y1b, y1s, nullptr, wAb, wAs, fcb, out, M, VV, HH);
}

// round 4
// speedup vs baseline: 1.5387x; 1.5230x over previous
#include <cuda_runtime.h>
#include <cuda_bf16.h>
#include <math.h>
#include <stdint.h>

#define BB 64
#define TT 256
#define HH 1024
#define VV 128
#define NG 4096   // 4*H

// ---------------- device scratch (no allocations allowed) ----------------
__device__ float g_gx[BB * TT * NG];              // gate pre-activations (fp32)
__device__ __nv_bfloat16 g_y0b[BB * TT * HH];     // layer-0 output big
__device__ __nv_bfloat16 g_y0s[BB * TT * HH];     // layer-0 output small
__device__ __nv_bfloat16 g_y1b[BB * TT * HH];     // layer-1 output big
__device__ __nv_bfloat16 g_y1s[BB * TT * HH];     // layer-1 output small
__device__ float g_h[BB * HH];                    // hidden state (fp32)
__device__ float g_c[BB * HH];                    // cell state (fp32)
__device__ float g_part[8 * BB * NG];             // k-split partials
__device__ __nv_bfloat16 g_wAb[NG * HH];          // W_ih / fc_W big
__device__ __nv_bfloat16 g_wAs[NG * HH];          // W_ih / fc_W small
__device__ __nv_bfloat16 g_wRb[NG * HH];          // W_hh big
__device__ __nv_bfloat16 g_wRs[NG * HH];          // W_hh small
__device__ __nv_bfloat16 g_embb[VV * HH];         // embedding big
__device__ __nv_bfloat16 g_embs[VV * HH];         // embedding small
__device__ unsigned g_barc;
__device__ volatile unsigned g_bars;

// ---------------- helpers ----------------
__device__ __forceinline__ void bf16_split(float x, __nv_bfloat16& b, __nv_bfloat16& s) {
    b = __float2bfloat16(x);
    s = __float2bfloat16(x - __bfloat162float(b));
}

__device__ __forceinline__ uint32_t pack_bf2(__nv_bfloat16 lo, __nv_bfloat16 hi) {
    __nv_bfloat162 t = __halves2bfloat162(lo, hi);
    return *reinterpret_cast<uint32_t*>(&t);
}

__device__ __forceinline__ int swz(int k2) {
    return 8 * (k2 & 3) + 16 * ((k2 >> 2) & 1);
}

__device__ __forceinline__ void mma_bf16(float* d, const uint32_t* a, const uint32_t* b) {
    asm volatile(
        "mma.sync.aligned.m16n8k16.row.col.f32.bf16.bf16.f32 "
        "{%0,%1,%2,%3}, {%4,%5,%6,%7}, {%8,%9}, {%0,%1,%2,%3};\n"
        : "+f"(d[0]), "+f"(d[1]), "+f"(d[2]), "+f"(d[3])
        : "r"(a[0]), "r"(a[1]), "r"(a[2]), "r"(a[3]), "r"(b[0]), "r"(b[1]));
}

// Smem chunk layout: uint32 [8 k2][LD] where word = bf16x2 of k=(2*k2, 2*k2+1),
// physical column = c ^ swz(k2).  One 16-k chunk: acc += A(64 rows) x B(32 cols).
template<int LDA, int LDB>
__device__ __forceinline__ void mma_tile_bf16(const uint32_t* A32, const uint32_t* B32,
                                              float acc[4][4][4],
                                              int mbase, int nbase, int r, int q) {
    const int s0 = 8 * r;
    const int s1 = 8 * r + 16;
    uint32_t af[4][4], bf[4][2];
    #pragma unroll
    for (int mf = 0; mf < 4; mf++) {
        const int c0 = mbase + mf * 16 + q;
        af[mf][0] = A32[r * LDA + (c0 ^ s0)];
        af[mf][1] = A32[r * LDA + ((c0 + 8) ^ s0)];
        af[mf][2] = A32[(r + 4) * LDA + (c0 ^ s1)];
        af[mf][3] = A32[(r + 4) * LDA + ((c0 + 8) ^ s1)];
    }
    #pragma unroll
    for (int nf = 0; nf < 4; nf++) {
        const int cb = nbase + nf * 8 + q;
        bf[nf][0] = B32[r * LDB + (cb ^ s0)];
        bf[nf][1] = B32[(r + 4) * LDB + (cb ^ s1)];
    }
    #pragma unroll
    for (int mf = 0; mf < 4; mf++)
        #pragma unroll
        for (int nf = 0; nf < 4; nf++)
            mma_bf16(acc[mf][nf], af[mf], bf[nf]);
}

// ---------------- grid-wide sense-reversing barrier ----------------
__device__ __forceinline__ void grid_bar(unsigned* sense) {
    __syncthreads();
    if (threadIdx.x == 0) {
        unsigned s = *sense ^ 1u;
        *sense = s;
        __threadfence();
        unsigned prev = atomicAdd(&g_barc, 1u);
        if (prev == gridDim.x - 1) {
            g_barc = 0u;
            __threadfence();
            g_bars = s;
        } else {
            while (g_bars != s) { __nanosleep(8); }
        }
    }
    __syncthreads();
}

// ---------------- fp32 -> (bf16 big, bf16 small) split ----------------
__global__ void cvt_split_kernel(const float* __restrict__ src,
                                 __nv_bfloat16* __restrict__ dstb,
                                 __nv_bfloat16* __restrict__ dsts, int n) {
    for (int i = blockIdx.x * blockDim.x + threadIdx.x; i < n; i += gridDim.x * blockDim.x) {
        __nv_bfloat16 b, s;
        bf16_split(src[i], b, s);
        dstb[i] = b;
        dsts[i] = s;
    }
}

// ---------------- split-bf16 SGEMM: C[M,N] = A[M,K] @ W[N,K]^T + bias[N] ----------------
// BM=128, BN=128, BK=16, 256 threads = 8 warps (2m x 4n), warp tile 64x32.
// Computes Ab*Wb + Ab*Ws + As*Wb with fp32 accumulators.
template <bool GATHER>
__global__ __launch_bounds__(256, 1)
void sgemm_sbf16(const __nv_bfloat16* __restrict__ Ab, const __nv_bfloat16* __restrict__ As_,
                 const int* __restrict__ tok,
                 const __nv_bfloat16* __restrict__ Wb, const __nv_bfloat16* __restrict__ Ws_,
                 const float* __restrict__ bias,
                 float* __restrict__ C, int M, int N, int K)
{
    __shared__ uint32_t Atb[8 * 128];
    __shared__ uint32_t Ats[8 * 128];
    __shared__ uint32_t Btb[8 * 128];
    __shared__ uint32_t Bts[8 * 128];

    const int m0 = blockIdx.y * 128;
    const int n0 = blockIdx.x * 128;
    const int tid = threadIdx.x;
    const int warp = tid >> 5;
    const int lane = tid & 31;
    const int r = lane & 3;
    const int q = lane >> 2;
    const int mbase = (warp >> 2) * 64;
    const int nbase = (warp & 3) * 32;

    const int lrow = tid >> 1;          // 0..127
    const int lq   = (tid & 1) * 8;     // 0 or 8 (k offset)
    const int k2q  = lq >> 1;           // 0 or 4

    size_t aoff;
    if (GATHER) aoff = (size_t)tok[m0 + lrow] * K;
    else        aoff = (size_t)(m0 + lrow) * K;
    const __nv_bfloat16* arb = Ab  + aoff + lq;
    const __nv_bfloat16* ars = As_ + aoff + lq;
    const __nv_bfloat16* wrb = Wb  + (size_t)(n0 + lrow) * K + lq;
    const __nv_bfloat16* wrs = Ws_ + (size_t)(n0 + lrow) * K + lq;

    float acc[4][4][4];
    #pragma unroll
    for (int mf = 0; mf < 4; mf++)
        #pragma unroll
        for (int nf = 0; nf < 4; nf++)
            #pragma unroll
            for (int i = 0; i < 4; i++) acc[mf][nf][i] = 0.f;

    uint4 pab = *(const uint4*)(arb);
    uint4 pas = *(const uint4*)(ars);
    uint4 pwb = *(const uint4*)(wrb);
    uint4 pws = *(const uint4*)(wrs);

    for (int k0 = 0; k0 < K; k0 += 16) {
        {
            const uint32_t ab[4] = {pab.x, pab.y, pab.z, pab.w};
            const uint32_t as[4] = {pas.x, pas.y, pas.z, pas.w};
            const uint32_t wb[4] = {pwb.x, pwb.y, pwb.z, pwb.w};
            const uint32_t ws[4] = {pws.x, pws.y, pws.z, pws.w};
            #pragma unroll
            for (int j2 = 0; j2 < 4; j2++) {
                const int k2 = k2q + j2;
                const int idx = k2 * 128 + (lrow ^ swz(k2));
                Atb[idx] = ab[j2];
                Ats[idx] = as[j2];
                Btb[idx] = wb[j2];
                Bts[idx] = ws[j2];
            }
        }
        __syncthreads();

        if (k0 + 16 < K) {
            pab = *(const uint4*)(arb + k0 + 16);
            pas = *(const uint4*)(ars + k0 + 16);
            pwb = *(const uint4*)(wrb + k0 + 16);
            pws = *(const uint4*)(wrs + k0 + 16);
        }

        mma_tile_bf16<128, 128>(Atb, Btb, acc, mbase, nbase, r, q);
        mma_tile_bf16<128, 128>(Atb, Bts, acc, mbase, nbase, r, q);
        mma_tile_bf16<128, 128>(Ats, Btb, acc, mbase, nbase, r, q);
        __syncthreads();
    }

    #pragma unroll
    for (int nf = 0; nf < 4; nf++) {
        const int n = n0 + nbase + nf * 8 + 2 * r;
        const float b0v = bias[n];
        const float b1v = bias[n + 1];
        #pragma unroll
        for (int mf = 0; mf < 4; mf++) {
            const int m = m0 + mbase + mf * 16 + q;
            float2 o0 = {acc[mf][nf][0] + b0v, acc[mf][nf][1] + b1v};
            float2 o1 = {acc[mf][nf][2] + b0v, acc[mf][nf][3] + b1v};
            *(float2*)(C + (size_t)m * N + n)       = o0;
            *(float2*)(C + (size_t)(m + 8) * N + n) = o1;
        }
    }
}

// ---------------- persistent LSTM layer kernel (split-bf16 tensor cores) ----------------
// grid = 128 CTAs (16 column tiles of 256 cols x 8 K-splits of 128), 256 threads.
__global__ __launch_bounds__(256, 1)
void lstm_layer(const float* __restrict__ gx,
                const __nv_bfloat16* __restrict__ Wtb, const __nv_bfloat16* __restrict__ Wts,
                const float* __restrict__ h0, const float* __restrict__ c0,
                __nv_bfloat16* __restrict__ yb, __nv_bfloat16* __restrict__ ys)
{
    __shared__ uint32_t hsb[8 * 64];
    __shared__ uint32_t hss[8 * 64];
    __shared__ uint32_t Wsb[8 * 256];
    __shared__ uint32_t Wss[8 * 256];

    const int tid = threadIdx.x;
    const int bid = blockIdx.x;       // 0..127
    const int cs  = bid & 15;         // column tile (256 cols)
    const int ks  = bid >> 4;         // k-split (128 k)
    const int col0 = cs * 256;
    const int gtid = bid * 256 + tid;

    const int warp = tid >> 5;
    const int lane = tid & 31;
    const int r = lane & 3;
    const int q = lane >> 2;
    const int nbase = warp * 32;      // warp tile 64x32 within 64x256 CTA tile

    unsigned sense = g_bars;

    for (int i = gtid; i < BB * HH; i += 128 * 256) {
        g_h[i] = h0[i];
        g_c[i] = c0[i];
    }
    grid_bar(&sense);

    const int hrow = tid >> 2;              // 0..63 (b)
    const int hq   = (tid & 3) * 4;         // 0,4,8,12 (k within chunk)
    const int hk2  = hq >> 1;               // 0,2,4,6
    const __nv_bfloat16* wbb = Wtb + (size_t)(col0 + tid) * HH + ks * 128;
    const __nv_bfloat16* wbs = Wts + (size_t)(col0 + tid) * HH + ks * 128;
    const float* hbase = g_h + (size_t)hrow * HH + ks * 128;

    for (int t = 0; t < TT; t++) {
        float acc[4][4][4];
        #pragma unroll
        for (int mf = 0; mf < 4; mf++)
            #pragma unroll
            for (int nf = 0; nf < 4; nf++)
                #pragma unroll
                for (int i = 0; i < 4; i++) acc[mf][nf][i] = 0.f;

        float4 hv  = *(const float4*)(hbase + hq);
        uint4 wb0 = *(const uint4*)(wbb);       // k 0..7
        uint4 wb1 = *(const uint4*)(wbb + 8);   // k 8..15
        uint4 ws0 = *(const uint4*)(wbs);
        uint4 ws1 = *(const uint4*)(wbs + 8);

        #pragma unroll 1
        for (int kc = 0; kc < 8; kc++) {
            // stage h chunk, splitting fp32 -> (big, small) bf16 pairs
            {
                __nv_bfloat16 b0, s0v, b1, s1v, b2, s2v, b3, s3v;
                bf16_split(hv.x, b0, s0v);
                bf16_split(hv.y, b1, s1v);
                bf16_split(hv.z, b2, s2v);
                bf16_split(hv.w, b3, s3v);
                const int i0 = hk2 * 64 + (hrow ^ swz(hk2));
                const int i1 = (hk2 + 1) * 64 + (hrow ^ swz(hk2 + 1));
                hsb[i0] = pack_bf2(b0, b1);
                hss[i0] = pack_bf2(s0v, s1v);
                hsb[i1] = pack_bf2(b2, b3);
                hss[i1] = pack_bf2(s2v, s3v);
            }
            // stage W chunk (one col per thread, 16 k = 8 words per array)
            {
                const uint32_t wbv[8] = {wb0.x, wb0.y, wb0.z, wb0.w, wb1.x, wb1.y, wb1.z, wb1.w};
                const uint32_t wsv[8] = {ws0.x, ws0.y, ws0.z, ws0.w, ws1.x, ws1.y, ws1.z, ws1.w};
                #pragma unroll
                for (int k2 = 0; k2 < 8; k2++) {
                    const int idx = k2 * 256 + (tid ^ swz(k2));
                    Wsb[idx] = wbv[k2];
                    Wss[idx] = wsv[k2];
                }
            }
            __syncthreads();

            if (kc < 7) {
                const int k0 = (kc + 1) * 16;
                hv  = *(const float4*)(hbase + k0 + hq);
                wb0 = *(const uint4*)(wbb + k0);
                wb1 = *(const uint4*)(wbb + k0 + 8);
                ws0 = *(const uint4*)(wbs + k0);
                ws1 = *(const uint4*)(wbs + k0 + 8);
            }

            mma_tile_bf16<64, 256>(hsb, Wsb, acc, 0, nbase, r, q);
            mma_tile_bf16<64, 256>(hsb, Wss, acc, 0, nbase, r, q);
            mma_tile_bf16<64, 256>(hss, Wsb, acc, 0, nbase, r, q);
            __syncthreads();
        }

        // write partials P[ks][b][col]
        #pragma unroll
        for (int nf = 0; nf < 4; nf++) {
            const int col = col0 + nbase + nf * 8 + 2 * r;
            #pragma unroll
            for (int mf = 0; mf < 4; mf++) {
                const int b = mf * 16 + q;
                float2 o0 = {acc[mf][nf][0], acc[mf][nf][1]};
                float2 o1 = {acc[mf][nf][2], acc[mf][nf][3]};
                *(float2*)(&g_part[((size_t)ks * BB + b) * NG + col])     = o0;
                *(float2*)(&g_part[((size_t)ks * BB + b + 8) * NG + col]) = o1;
            }
        }
        __threadfence();
        grid_bar(&sense);

        // Phase B: 65536 (b,j) cells, 2 per thread
        #pragma unroll
        for (int it = 0; it < 2; it++) {
            const int cell = gtid + it * 32768;
            const int b = cell >> 10;
            const int j = cell & 1023;
            float gi = 0.f, gf = 0.f, gg = 0.f, go = 0.f;
            #pragma unroll
            for (int s = 0; s < 8; s++) {
                const float* pp = &g_part[((size_t)s * BB + b) * NG + j];
                gi += pp[0];
                gf += pp[1024];
                gg += pp[2048];
                go += pp[3072];
            }
            const float* gr = gx + ((size_t)b * TT + t) * NG;
            gi += gr[j];
            gf += gr[j + 1024];
            gg += gr[j + 2048];
            go += gr[j + 3072];

            float cv = g_c[cell];
            const float si = 1.f / (1.f + __expf(-gi));
            const float sf = 1.f / (1.f + __expf(-gf));
            const float so = 1.f / (1.f + __expf(-go));
            cv = sf * cv + si * tanhf(gg);
            const float hvv = so * tanhf(cv);
            g_c[cell] = cv;
            g_h[cell] = hvv;
            __nv_bfloat16 hb, hs;
            bf16_split(hvv, hb, hs);
            const size_t yi = ((size_t)b * TT + t) * HH + j;
            yb[yi] = hb;
            ys[yi] = hs;
        }
        __threadfence();
        grid_bar(&sense);
    }
}

// ---------------- launch ----------------
extern "C" void kernel_launch(void* const* d_in, const int* in_sizes, int n_in,
                              void* d_out, int out_size)
{
    const int*   x    = (const int*)  d_in[0];
    const float* emb  = (const float*)d_in[1];
    const float* Wih0 = (const float*)d_in[2];
    const float* Whh0 = (const float*)d_in[3];
    const float* b0   = (const float*)d_in[4];
    const float* Wih1 = (const float*)d_in[5];
    const float* Whh1 = (const float*)d_in[6];
    const float* b1   = (const float*)d_in[7];
    const float* fcW  = (const float*)d_in[8];
    const float* fcb  = (const float*)d_in[9];
    const float* h0   = (const float*)d_in[10];
    const float* c0   = (const float*)d_in[11];
    float* out = (float*)d_out;

    float *gx;
    __nv_bfloat16 *y0b, *y0s, *y1b, *y1s, *wAb, *wAs, *wRb, *wRs, *embb, *embs;
    cudaGetSymbolAddress((void**)&gx,   g_gx);
    cudaGetSymbolAddress((void**)&y0b,  g_y0b);
    cudaGetSymbolAddress((void**)&y0s,  g_y0s);
    cudaGetSymbolAddress((void**)&y1b,  g_y1b);
    cudaGetSymbolAddress((void**)&y1s,  g_y1s);
    cudaGetSymbolAddress((void**)&wAb,  g_wAb);
    cudaGetSymbolAddress((void**)&wAs,  g_wAs);
    cudaGetSymbolAddress((void**)&wRb,  g_wRb);
    cudaGetSymbolAddress((void**)&wRs,  g_wRs);
    cudaGetSymbolAddress((void**)&embb, g_embb);
    cudaGetSymbolAddress((void**)&embs, g_embs);

    const int M = BB * TT;  // 16384

    cvt_split_kernel<<<512, 256>>>(emb, embb, embs, VV * HH);
    cvt_split_kernel<<<4096, 256>>>(Wih0, wAb, wAs, NG * HH);
    cvt_split_kernel<<<4096, 256>>>(Whh0, wRb, wRs, NG * HH);

    sgemm_sbf16<true><<<dim3(NG / 128, M / 128), 256>>>(embb, embs, x, wAb, wAs, b0, gx, M, NG, HH);
    lstm_layer<<<128, 256>>>(gx, wRb, wRs, h0, c0, y0b, y0s);

    cvt_split_kernel<<<4096, 256>>>(Wih1, wAb, wAs, NG * HH);
    cvt_split_kernel<<<4096, 256>>>(Whh1, wRb, wRs, NG * HH);

    sgemm_sbf16<false><<<dim3(NG / 128, M / 128), 256>>>(y0b, y0s, nullptr, wAb, wAs, b1, gx, M, NG, HH);
    lstm_layer<<<128, 256>>>(gx, wRb, wRs, h0 + BB * HH, c0 + BB * HH, y1b, y1s);

    cvt_split_kernel<<<1024, 256>>>(fcW, wAb, wAs, VV * HH);
    sgemm_sbf16<false><<<dim3(VV / 128, M / 128), 256>>>(y1b, y1s, nullptr, wAb, wAs, fcb, out, M, VV, HH);
}

// round 5
// speedup vs baseline: 1.9396x; 1.2606x over previous
#include <cuda_runtime.h>
#include <cuda_bf16.h>
#include <math.h>
#include <stdint.h>

#define BB 64
#define TT 256
#define HH 1024
#define VV 128
#define NG 4096   // 4*H

// ---------------- device scratch (no allocations allowed) ----------------
__device__ float g_gx[BB * TT * NG];              // gate pre-activations (fp32)
__device__ __nv_bfloat16 g_y0b[BB * TT * HH];     // layer-0 output big
__device__ __nv_bfloat16 g_y0s[BB * TT * HH];     // layer-0 output small
__device__ __nv_bfloat16 g_y1b[BB * TT * HH];     // layer-1 output big
__device__ __nv_bfloat16 g_y1s[BB * TT * HH];     // layer-1 output small
__device__ float g_h[BB * HH];                    // hidden state (fp32)
__device__ float g_c[BB * HH];                    // cell state (fp32)
__device__ float g_part[8 * BB * NG];             // k-split partials
__device__ __nv_bfloat16 g_wAb[NG * HH];          // W_ih / fc_W big
__device__ __nv_bfloat16 g_wAs[NG * HH];          // W_ih / fc_W small
__device__ __nv_bfloat16 g_wRb[NG * HH];          // W_hh big
__device__ __nv_bfloat16 g_wRs[NG * HH];          // W_hh small
__device__ __nv_bfloat16 g_embb[VV * HH];         // embedding big
__device__ __nv_bfloat16 g_embs[VV * HH];         // embedding small
__device__ unsigned g_barc;
__device__ volatile unsigned g_bars;

// ---------------- helpers ----------------
__device__ __forceinline__ void bf16_split(float x, __nv_bfloat16& b, __nv_bfloat16& s) {
    b = __float2bfloat16(x);
    s = __float2bfloat16(x - __bfloat162float(b));
}

__device__ __forceinline__ uint32_t pack_bf2(__nv_bfloat16 lo, __nv_bfloat16 hi) {
    __nv_bfloat162 t = __halves2bfloat162(lo, hi);
    return *reinterpret_cast<uint32_t*>(&t);
}

__device__ __forceinline__ int swz(int k2) {
    return 8 * (k2 & 3) + 16 * ((k2 >> 2) & 1);
}

__device__ __forceinline__ void mma_bf16(float* d, const uint32_t* a, const uint32_t* b) {
    asm volatile(
        "mma.sync.aligned.m16n8k16.row.col.f32.bf16.bf16.f32 "
        "{%0,%1,%2,%3}, {%4,%5,%6,%7}, {%8,%9}, {%0,%1,%2,%3};\n"
        : "+f"(d[0]), "+f"(d[1]), "+f"(d[2]), "+f"(d[3])
        : "r"(a[0]), "r"(a[1]), "r"(a[2]), "r"(a[3]), "r"(b[0]), "r"(b[1]));
}

// Fused 3-product 16-k chunk: acc += Ab*Bb + Ab*Bs + As*Bb.
// A chunk buffers: [8 k2][LDA] swizzled. B buffers: [.. k2][ldb] swizzled, rows k2b..k2b+7.
template<int LDA>
__device__ __forceinline__ void mma_chunk3(const uint32_t* Ab32, const uint32_t* As32,
                                           const uint32_t* Bb32, const uint32_t* Bs32,
                                           int ldb, int k2b,
                                           float acc[4][4][4],
                                           int mbase, int nbase, int r, int q)
{
    const int s0 = 8 * r;
    const int s1 = 8 * r + 16;
    uint32_t ab[4][4], as[4][4], bb[4][2], bs[4][2];
    #pragma unroll
    for (int mf = 0; mf < 4; mf++) {
        const int c0 = mbase + mf * 16 + q;
        ab[mf][0] = Ab32[r * LDA + (c0 ^ s0)];
        ab[mf][1] = Ab32[r * LDA + ((c0 + 8) ^ s0)];
        ab[mf][2] = Ab32[(r + 4) * LDA + (c0 ^ s1)];
        ab[mf][3] = Ab32[(r + 4) * LDA + ((c0 + 8) ^ s1)];
        as[mf][0] = As32[r * LDA + (c0 ^ s0)];
        as[mf][1] = As32[r * LDA + ((c0 + 8) ^ s0)];
        as[mf][2] = As32[(r + 4) * LDA + (c0 ^ s1)];
        as[mf][3] = As32[(r + 4) * LDA + ((c0 + 8) ^ s1)];
    }
    #pragma unroll
    for (int nf = 0; nf < 4; nf++) {
        const int cb = nbase + nf * 8 + q;
        bb[nf][0] = Bb32[(k2b + r) * ldb + (cb ^ s0)];
        bb[nf][1] = Bb32[(k2b + r + 4) * ldb + (cb ^ s1)];
        bs[nf][0] = Bs32[(k2b + r) * ldb + (cb ^ s0)];
        bs[nf][1] = Bs32[(k2b + r + 4) * ldb + (cb ^ s1)];
    }
    #pragma unroll
    for (int mf = 0; mf < 4; mf++)
        #pragma unroll
        for (int nf = 0; nf < 4; nf++)
            mma_bf16(acc[mf][nf], ab[mf], bb[nf]);
    #pragma unroll
    for (int mf = 0; mf < 4; mf++)
        #pragma unroll
        for (int nf = 0; nf < 4; nf++)
            mma_bf16(acc[mf][nf], ab[mf], bs[nf]);
    #pragma unroll
    for (int mf = 0; mf < 4; mf++)
        #pragma unroll
        for (int nf = 0; nf < 4; nf++)
            mma_bf16(acc[mf][nf], as[mf], bb[nf]);
}

// ---------------- grid-wide sense-reversing barrier ----------------
__device__ __forceinline__ void grid_bar(unsigned* sense) {
    __syncthreads();
    if (threadIdx.x == 0) {
        unsigned s = *sense ^ 1u;
        *sense = s;
        __threadfence();
        unsigned prev = atomicAdd(&g_barc, 1u);
        if (prev == gridDim.x - 1) {
            g_barc = 0u;
            __threadfence();
            g_bars = s;
        } else {
            while (g_bars != s) { }
        }
    }
    __syncthreads();
}

// ---------------- fp32 -> (bf16 big, bf16 small) split ----------------
__global__ void cvt_split_kernel(const float* __restrict__ src,
                                 __nv_bfloat16* __restrict__ dstb,
                                 __nv_bfloat16* __restrict__ dsts, int n) {
    for (int i = blockIdx.x * blockDim.x + threadIdx.x; i < n; i += gridDim.x * blockDim.x) {
        __nv_bfloat16 b, s;
        bf16_split(src[i], b, s);
        dstb[i] = b;
        dsts[i] = s;
    }
}

// ---------------- split-bf16 SGEMM (double-buffered): C = A @ W^T + bias ----------------
// BM=128, BN=128, BK=16, 256 threads = 8 warps (2m x 4n), warp tile 64x32.
template <bool GATHER>
__global__ __launch_bounds__(256, 1)
void sgemm_sbf16(const __nv_bfloat16* __restrict__ Ab, const __nv_bfloat16* __restrict__ As_,
                 const int* __restrict__ tok,
                 const __nv_bfloat16* __restrict__ Wb, const __nv_bfloat16* __restrict__ Ws_,
                 const float* __restrict__ bias,
                 float* __restrict__ C, int M, int N, int K)
{
    __shared__ uint32_t Atb[2][8 * 128];
    __shared__ uint32_t Ats[2][8 * 128];
    __shared__ uint32_t Btb[2][8 * 128];
    __shared__ uint32_t Bts[2][8 * 128];

    const int m0 = blockIdx.y * 128;
    const int n0 = blockIdx.x * 128;
    const int tid = threadIdx.x;
    const int warp = tid >> 5;
    const int lane = tid & 31;
    const int r = lane & 3;
    const int q = lane >> 2;
    const int mbase = (warp >> 2) * 64;
    const int nbase = (warp & 3) * 32;

    const int lrow = tid >> 1;          // 0..127
    const int lq   = (tid & 1) * 8;     // 0 or 8 (k offset)
    const int k2q  = lq >> 1;           // 0 or 4

    size_t aoff;
    if (GATHER) aoff = (size_t)tok[m0 + lrow] * K;
    else        aoff = (size_t)(m0 + lrow) * K;
    const __nv_bfloat16* arb = Ab  + aoff + lq;
    const __nv_bfloat16* ars = As_ + aoff + lq;
    const __nv_bfloat16* wrb = Wb  + (size_t)(n0 + lrow) * K + lq;
    const __nv_bfloat16* wrs = Ws_ + (size_t)(n0 + lrow) * K + lq;

    float acc[4][4][4];
    #pragma unroll
    for (int mf = 0; mf < 4; mf++)
        #pragma unroll
        for (int nf = 0; nf < 4; nf++)
            #pragma unroll
            for (int i = 0; i < 4; i++) acc[mf][nf][i] = 0.f;

    uint4 pab = *(const uint4*)(arb);
    uint4 pas = *(const uint4*)(ars);
    uint4 pwb = *(const uint4*)(wrb);
    uint4 pws = *(const uint4*)(wrs);

    const int niter = K / 16;
    for (int it = 0; it < niter; it++) {
        const int buf = it & 1;
        {
            const uint32_t ab[4] = {pab.x, pab.y, pab.z, pab.w};
            const uint32_t as[4] = {pas.x, pas.y, pas.z, pas.w};
            const uint32_t wb[4] = {pwb.x, pwb.y, pwb.z, pwb.w};
            const uint32_t ws[4] = {pws.x, pws.y, pws.z, pws.w};
            #pragma unroll
            for (int j2 = 0; j2 < 4; j2++) {
                const int k2 = k2q + j2;
                const int idx = k2 * 128 + (lrow ^ swz(k2));
                Atb[buf][idx] = ab[j2];
                Ats[buf][idx] = as[j2];
                Btb[buf][idx] = wb[j2];
                Bts[buf][idx] = ws[j2];
            }
        }
        if (it + 1 < niter) {
            const int k0 = (it + 1) * 16;
            pab = *(const uint4*)(arb + k0);
            pas = *(const uint4*)(ars + k0);
            pwb = *(const uint4*)(wrb + k0);
            pws = *(const uint4*)(wrs + k0);
        }
        __syncthreads();
        mma_chunk3<128>(Atb[buf], Ats[buf], Btb[buf], Bts[buf], 128, 0,
                        acc, mbase, nbase, r, q);
    }

    #pragma unroll
    for (int nf = 0; nf < 4; nf++) {
        const int n = n0 + nbase + nf * 8 + 2 * r;
        const float b0v = bias[n];
        const float b1v = bias[n + 1];
        #pragma unroll
        for (int mf = 0; mf < 4; mf++) {
            const int m = m0 + mbase + mf * 16 + q;
            float2 o0 = {acc[mf][nf][0] + b0v, acc[mf][nf][1] + b1v};
            float2 o1 = {acc[mf][nf][2] + b0v, acc[mf][nf][3] + b1v};
            *(float2*)(C + (size_t)m * N + n)       = o0;
            *(float2*)(C + (size_t)(m + 8) * N + n) = o1;
        }
    }
}

// ---------------- persistent LSTM layer kernel (W stationary in smem) ----------------
// grid = 128 CTAs (16 column tiles of 256 cols x 8 K-splits of 128), 256 threads.
// Dynamic smem: W slice big [64 k2][256] + small [64 k2][256] = 128 KB, loaded once.
__global__ __launch_bounds__(256, 1)
void lstm_layer(const float* __restrict__ gx,
                const __nv_bfloat16* __restrict__ Wtb, const __nv_bfloat16* __restrict__ Wts,
                const float* __restrict__ h0, const float* __restrict__ c0,
                __nv_bfloat16* __restrict__ yb, __nv_bfloat16* __restrict__ ys)
{
    extern __shared__ uint32_t dynsm[];
    uint32_t* Wb_sm = dynsm;              // [64 * 256]
    uint32_t* Ws_sm = dynsm + 64 * 256;   // [64 * 256]
    __shared__ uint32_t hsb[2][8 * 64];
    __shared__ uint32_t hss[2][8 * 64];

    const int tid = threadIdx.x;
    const int bid = blockIdx.x;       // 0..127
    const int cs  = bid & 15;         // column tile (256 cols)
    const int ks  = bid >> 4;         // k-split (128 k)
    const int col0 = cs * 256;
    const int gtid = bid * 256 + tid;

    const int warp = tid >> 5;
    const int lane = tid & 31;
    const int r = lane & 3;
    const int q = lane >> 2;
    const int nbase = warp * 32;      // warp tile 64x32 within 64x256 CTA tile

    unsigned sense = g_bars;

    // ---- one-time W slice load into smem (this CTA's 256 cols x 128 k) ----
    {
        const __nv_bfloat16* wbb = Wtb + (size_t)(col0 + tid) * HH + ks * 128;
        const __nv_bfloat16* wbs = Wts + (size_t)(col0 + tid) * HH + ks * 128;
        #pragma unroll
        for (int g = 0; g < 16; g++) {
            uint4 vb = *(const uint4*)(wbb + 8 * g);
            uint4 vs = *(const uint4*)(wbs + 8 * g);
            const uint32_t wbv[4] = {vb.x, vb.y, vb.z, vb.w};
            const uint32_t wsv[4] = {vs.x, vs.y, vs.z, vs.w};
            #pragma unroll
            for (int j = 0; j < 4; j++) {
                const int k2 = 4 * g + j;
                const int idx = k2 * 256 + (tid ^ swz(k2));
                Wb_sm[idx] = wbv[j];
                Ws_sm[idx] = wsv[j];
            }
        }
    }

    // init state (full fp32)
    for (int i = gtid; i < BB * HH; i += 128 * 256) {
        g_h[i] = h0[i];
        g_c[i] = c0[i];
    }
    grid_bar(&sense);

    const int hrow = tid >> 2;              // 0..63 (b)
    const int hq   = (tid & 3) * 4;         // 0,4,8,12 (k within chunk)
    const int hk2  = hq >> 1;               // 0,2,4,6
    const float* hbase = g_h + (size_t)hrow * HH + ks * 128;

    // phase-B cell indices for this thread (2 cells)
    const int cell0 = gtid;
    const int cell1 = gtid + 32768;

    for (int t = 0; t < TT; t++) {
        float acc[4][4][4];
        #pragma unroll
        for (int mf = 0; mf < 4; mf++)
            #pragma unroll
            for (int nf = 0; nf < 4; nf++)
                #pragma unroll
                for (int i = 0; i < 4; i++) acc[mf][nf][i] = 0.f;

        float4 hv = *(const float4*)(hbase + hq);   // chunk 0

        #pragma unroll 1
        for (int kc = 0; kc < 8; kc++) {
            const int buf = kc & 1;
            // stage h chunk, splitting fp32 -> (big, small) bf16 pairs
            {
                __nv_bfloat16 b0, s0v, b1, s1v, b2, s2v, b3, s3v;
                bf16_split(hv.x, b0, s0v);
                bf16_split(hv.y, b1, s1v);
                bf16_split(hv.z, b2, s2v);
                bf16_split(hv.w, b3, s3v);
                const int i0 = hk2 * 64 + (hrow ^ swz(hk2));
                const int i1 = (hk2 + 1) * 64 + (hrow ^ swz(hk2 + 1));
                hsb[buf][i0] = pack_bf2(b0, b1);
                hss[buf][i0] = pack_bf2(s0v, s1v);
                hsb[buf][i1] = pack_bf2(b2, b3);
                hss[buf][i1] = pack_bf2(s2v, s3v);
            }
            if (kc < 7)
                hv = *(const float4*)(hbase + (kc + 1) * 16 + hq);
            __syncthreads();
            mma_chunk3<64>(hsb[buf], hss[buf], Wb_sm, Ws_sm, 256, kc * 8,
                           acc, 0, nbase, r, q);
        }

        // write partials P[ks][b][col]
        #pragma unroll
        for (int nf = 0; nf < 4; nf++) {
            const int col = col0 + nbase + nf * 8 + 2 * r;
            #pragma unroll
            for (int mf = 0; mf < 4; mf++) {
                const int b = mf * 16 + q;
                float2 o0 = {acc[mf][nf][0], acc[mf][nf][1]};
                float2 o1 = {acc[mf][nf][2], acc[mf][nf][3]};
                *(float2*)(&g_part[((size_t)ks * BB + b) * NG + col])     = o0;
                *(float2*)(&g_part[((size_t)ks * BB + b + 8) * NG + col]) = o1;
            }
        }
        __threadfence();
        grid_bar(&sense);

        // Phase B: 65536 (b,j) cells, 2 per thread
        #pragma unroll
        for (int it = 0; it < 2; it++) {
            const int cell = (it == 0) ? cell0 : cell1;
            const int b = cell >> 10;
            const int j = cell & 1023;
            const float* gr = gx + ((size_t)b * TT + t) * NG;
            const float xg0 = gr[j];
            const float xg1 = gr[j + 1024];
            const float xg2 = gr[j + 2048];
            const float xg3 = gr[j + 3072];
            float gi = 0.f, gf = 0.f, gg = 0.f, go = 0.f;
            #pragma unroll
            for (int s = 0; s < 8; s++) {
                const float* pp = &g_part[((size_t)s * BB + b) * NG + j];
                gi += pp[0];
                gf += pp[1024];
                gg += pp[2048];
                go += pp[3072];
            }
            gi += xg0; gf += xg1; gg += xg2; go += xg3;

            float cv = g_c[cell];
            const float si = 1.f / (1.f + __expf(-gi));
            const float sf = 1.f / (1.f + __expf(-gf));
            const float so = 1.f / (1.f + __expf(-go));
            cv = sf * cv + si * tanhf(gg);
            const float hvv = so * tanhf(cv);
            g_c[cell] = cv;
            g_h[cell] = hvv;
            __nv_bfloat16 hb, hs;
            bf16_split(hvv, hb, hs);
            const size_t yi = ((size_t)b * TT + t) * HH + j;
            yb[yi] = hb;
            ys[yi] = hs;
        }
        __threadfence();
        grid_bar(&sense);
    }
}

// ---------------- launch ----------------
extern "C" void kernel_launch(void* const* d_in, const int* in_sizes, int n_in,
                              void* d_out, int out_size)
{
    const int*   x    = (const int*)  d_in[0];
    const float* emb  = (const float*)d_in[1];
    const float* Wih0 = (const float*)d_in[2];
    const float* Whh0 = (const float*)d_in[3];
    const float* b0   = (const float*)d_in[4];
    const float* Wih1 = (const float*)d_in[5];
    const float* Whh1 = (const float*)d_in[6];
    const float* b1   = (const float*)d_in[7];
    const float* fcW  = (const float*)d_in[8];
    const float* fcb  = (const float*)d_in[9];
    const float* h0   = (const float*)d_in[10];
    const float* c0   = (const float*)d_in[11];
    float* out = (float*)d_out;

    float *gx;
    __nv_bfloat16 *y0b, *y0s, *y1b, *y1s, *wAb, *wAs, *wRb, *wRs, *embb, *embs;
    cudaGetSymbolAddress((void**)&gx,   g_gx);
    cudaGetSymbolAddress((void**)&y0b,  g_y0b);
    cudaGetSymbolAddress((void**)&y0s,  g_y0s);
    cudaGetSymbolAddress((void**)&y1b,  g_y1b);
    cudaGetSymbolAddress((void**)&y1s,  g_y1s);
    cudaGetSymbolAddress((void**)&wAb,  g_wAb);
    cudaGetSymbolAddress((void**)&wAs,  g_wAs);
    cudaGetSymbolAddress((void**)&wRb,  g_wRb);
    cudaGetSymbolAddress((void**)&wRs,  g_wRs);
    cudaGetSymbolAddress((void**)&embb, g_embb);
    cudaGetSymbolAddress((void**)&embs, g_embs);

    const int LSTM_SMEM = 64 * 256 * 2 * (int)sizeof(uint32_t);  // 128 KB
    cudaFuncSetAttribute(lstm_layer, cudaFuncAttributeMaxDynamicSharedMemorySize, LSTM_SMEM);

    const int M = BB * TT;  // 16384

    cvt_split_kernel<<<512, 256>>>(emb, embb, embs, VV * HH);
    cvt_split_kernel<<<4096, 256>>>(Wih0, wAb, wAs, NG * HH);
    cvt_split_kernel<<<4096, 256>>>(Whh0, wRb, wRs, NG * HH);

    sgemm_sbf16<true><<<dim3(NG / 128, M / 128), 256>>>(embb, embs, x, wAb, wAs, b0, gx, M, NG, HH);
    lstm_layer<<<128, 256, LSTM_SMEM>>>(gx, wRb, wRs, h0, c0, y0b, y0s);

    cvt_split_kernel<<<4096, 256>>>(Wih1, wAb, wAs, NG * HH);
    cvt_split_kernel<<<4096, 256>>>(Whh1, wRb, wRs, NG * HH);

    sgemm_sbf16<false><<<dim3(NG / 128, M / 128), 256>>>(y0b, y0s, nullptr, wAb, wAs, b1, gx, M, NG, HH);
    lstm_layer<<<128, 256, LSTM_SMEM>>>(gx, wRb, wRs, h0 + BB * HH, c0 + BB * HH, y1b, y1s);

    cvt_split_kernel<<<1024, 256>>>(fcW, wAb, wAs, VV * HH);
    sgemm_sbf16<false><<<dim3(VV / 128, M / 128), 256>>>(y1b, y1s, nullptr, wAb, wAs, fcb, out, M, VV, HH);
}

// round 7
// speedup vs baseline: 2.1297x; 1.0980x over previous
#include <cuda_runtime.h>
#include <cuda_bf16.h>
#include <math.h>
#include <stdint.h>

#define BB 64
#define TT 256
#define HH 1024
#define VV 128
#define NG 4096   // 4*H

// ---------------- device scratch (no allocations allowed) ----------------
__device__ float g_gx[BB * TT * NG];              // gate pre-activations (fp32)
__device__ __nv_bfloat16 g_y0b[BB * TT * HH];     // layer-0 output big
__device__ __nv_bfloat16 g_y0s[BB * TT * HH];     // layer-0 output small
__device__ __nv_bfloat16 g_y1b[BB * TT * HH];     // layer-1 output big
__device__ __nv_bfloat16 g_y1s[BB * TT * HH];     // layer-1 output small
__device__ float g_h[BB * HH];                    // hidden state (fp32)
__device__ float g_c[BB * HH];                    // cell state (fp32)
__device__ float g_part[8 * BB * NG];             // k-split partials
__device__ __nv_bfloat16 g_wAb[NG * HH];          // W_ih / fc_W big
__device__ __nv_bfloat16 g_wAs[NG * HH];          // W_ih / fc_W small
__device__ __nv_bfloat16 g_embb[VV * HH];         // embedding big
__device__ __nv_bfloat16 g_embs[VV * HH];         // embedding small
__device__ unsigned g_barc;
__device__ volatile unsigned g_bars;

// ---------------- helpers ----------------
__device__ __forceinline__ void bf16_split(float x, __nv_bfloat16& b, __nv_bfloat16& s) {
    b = __float2bfloat16(x);
    s = __float2bfloat16(x - __bfloat162float(b));
}

__device__ __forceinline__ uint32_t pack_bf2(__nv_bfloat16 lo, __nv_bfloat16 hi) {
    __nv_bfloat162 t = __halves2bfloat162(lo, hi);
    return *reinterpret_cast<uint32_t*>(&t);
}

__device__ __forceinline__ int swz(int k2) {
    return 8 * (k2 & 3) + 16 * ((k2 >> 2) & 1);
}

__device__ __forceinline__ void mma_bf16(float* d, const uint32_t* a, const uint32_t* b) {
    asm volatile(
        "mma.sync.aligned.m16n8k16.row.col.f32.bf16.bf16.f32 "
        "{%0,%1,%2,%3}, {%4,%5,%6,%7}, {%8,%9}, {%0,%1,%2,%3};\n"
        : "+f"(d[0]), "+f"(d[1]), "+f"(d[2]), "+f"(d[3])
        : "r"(a[0]), "r"(a[1]), "r"(a[2]), "r"(a[3]), "r"(b[0]), "r"(b[1]));
}

// fast reciprocal: bit-trick seed + 2 Newton iterations (~1.3e-6 rel err), FMA pipe only
__device__ __forceinline__ float fast_rcp(float d) {
    float r = __int_as_float(0x7EF311C3 - __float_as_int(d));
    r = r * (2.f - d * r);
    r = r * (2.f - d * r);
    return r;
}

__device__ __forceinline__ float fast_sigmoid(float x) {   // 1/(1+e^-x)
    const float a = fmaxf(fminf(-x, 40.f), -40.f);
    return fast_rcp(1.f + __expf(a));
}

__device__ __forceinline__ float fast_tanh(float x) {      // 1 - 2/(e^{2x}+1)
    const float a = fmaxf(fminf(2.f * x, 40.f), -40.f);
    return 1.f - 2.f * fast_rcp(__expf(a) + 1.f);
}

// Fused 3-product 16-k chunk with reduced register pressure:
// acc += Ab*Bb + Ab*Bs + As*Bb.  A-big frags released before A-small loaded.
template<int LDA>
__device__ __forceinline__ void mma_chunk3(const uint32_t* Ab32, const uint32_t* As32,
                                           const uint32_t* Bb32, const uint32_t* Bs32,
                                           int ldb, int k2b,
                                           float acc[4][4][4],
                                           int mbase, int nbase, int r, int q)
{
    const int s0 = 8 * r;
    const int s1 = 8 * r + 16;
    uint32_t bb[4][2], bs[4][2];
    #pragma unroll
    for (int nf = 0; nf < 4; nf++) {
        const int cb = nbase + nf * 8 + q;
        bb[nf][0] = Bb32[(k2b + r) * ldb + (cb ^ s0)];
        bb[nf][1] = Bb32[(k2b + r + 4) * ldb + (cb ^ s1)];
        bs[nf][0] = Bs32[(k2b + r) * ldb + (cb ^ s0)];
        bs[nf][1] = Bs32[(k2b + r + 4) * ldb + (cb ^ s1)];
    }
    {
        uint32_t ab[4][4];
        #pragma unroll
        for (int mf = 0; mf < 4; mf++) {
            const int c0 = mbase + mf * 16 + q;
            ab[mf][0] = Ab32[r * LDA + (c0 ^ s0)];
            ab[mf][1] = Ab32[r * LDA + ((c0 + 8) ^ s0)];
            ab[mf][2] = Ab32[(r + 4) * LDA + (c0 ^ s1)];
            ab[mf][3] = Ab32[(r + 4) * LDA + ((c0 + 8) ^ s1)];
        }
        #pragma unroll
        for (int mf = 0; mf < 4; mf++)
            #pragma unroll
            for (int nf = 0; nf < 4; nf++)
                mma_bf16(acc[mf][nf], ab[mf], bb[nf]);
        #pragma unroll
        for (int mf = 0; mf < 4; mf++)
            #pragma unroll
            for (int nf = 0; nf < 4; nf++)
                mma_bf16(acc[mf][nf], ab[mf], bs[nf]);
    }
    {
        uint32_t as[4][4];
        #pragma unroll
        for (int mf = 0; mf < 4; mf++) {
            const int c0 = mbase + mf * 16 + q;
            as[mf][0] = As32[r * LDA + (c0 ^ s0)];
            as[mf][1] = As32[r * LDA + ((c0 + 8) ^ s0)];
            as[mf][2] = As32[(r + 4) * LDA + (c0 ^ s1)];
            as[mf][3] = As32[(r + 4) * LDA + ((c0 + 8) ^ s1)];
        }
        #pragma unroll
        for (int mf = 0; mf < 4; mf++)
            #pragma unroll
            for (int nf = 0; nf < 4; nf++)
                mma_bf16(acc[mf][nf], as[mf], bb[nf]);
    }
}

// ---------------- grid-wide sense-reversing barrier (leader-only fences) ----------------
// Sound per the CUDA memory model: __syncthreads orders all CTA threads' prior
// stores before the leader's release fence+atomic; the waiting leader performs
// an acquire fence after the spin; the trailing __syncthreads propagates.
__device__ __forceinline__ void grid_bar(unsigned* sense) {
    __syncthreads();
    if (threadIdx.x == 0) {
        unsigned s = *sense ^ 1u;
        *sense = s;
        __threadfence();                       // release
        unsigned prev = atomicAdd(&g_barc, 1u);
        if (prev == gridDim.x - 1) {
            g_barc = 0u;
            __threadfence();
            g_bars = s;
        } else {
            while (g_bars != s) { }
            __threadfence();                   // acquire
        }
    }
    __syncthreads();
}

// ---------------- fp32 -> (bf16 big, bf16 small) split ----------------
__global__ void cvt_split_kernel(const float* __restrict__ src,
                                 __nv_bfloat16* __restrict__ dstb,
                                 __nv_bfloat16* __restrict__ dsts, int n) {
    for (int i = blockIdx.x * blockDim.x + threadIdx.x; i < n; i += gridDim.x * blockDim.x) {
        __nv_bfloat16 b, s;
        bf16_split(src[i], b, s);
        dstb[i] = b;
        dsts[i] = s;
    }
}

// ---------------- split-bf16 SGEMM (double-buffered, 2 CTAs/SM): C = A @ W^T + bias ----------------
// BM=128, BN=128, BK=16, 256 threads = 8 warps (2m x 4n), warp tile 64x32.
template <bool GATHER>
__global__ __launch_bounds__(256, 2)
void sgemm_sbf16(const __nv_bfloat16* __restrict__ Ab, const __nv_bfloat16* __restrict__ As_,
                 const int* __restrict__ tok,
                 const __nv_bfloat16* __restrict__ Wb, const __nv_bfloat16* __restrict__ Ws_,
                 const float* __restrict__ bias,
                 float* __restrict__ C, int M, int N, int K)
{
    __shared__ uint32_t Atb[2][8 * 128];
    __shared__ uint32_t Ats[2][8 * 128];
    __shared__ uint32_t Btb[2][8 * 128];
    __shared__ uint32_t Bts[2][8 * 128];

    const int m0 = blockIdx.y * 128;
    const int n0 = blockIdx.x * 128;
    const int tid = threadIdx.x;
    const int warp = tid >> 5;
    const int lane = tid & 31;
    const int r = lane & 3;
    const int q = lane >> 2;
    const int mbase = (warp >> 2) * 64;
    const int nbase = (warp & 3) * 32;

    const int lrow = tid >> 1;          // 0..127
    const int lq   = (tid & 1) * 8;     // 0 or 8 (k offset)
    const int k2q  = lq >> 1;           // 0 or 4

    size_t aoff;
    if (GATHER) aoff = (size_t)tok[m0 + lrow] * K;
    else        aoff = (size_t)(m0 + lrow) * K;
    const __nv_bfloat16* arb = Ab  + aoff + lq;
    const __nv_bfloat16* ars = As_ + aoff + lq;
    const __nv_bfloat16* wrb = Wb  + (size_t)(n0 + lrow) * K + lq;
    const __nv_bfloat16* wrs = Ws_ + (size_t)(n0 + lrow) * K + lq;

    float acc[4][4][4];
    #pragma unroll
    for (int mf = 0; mf < 4; mf++)
        #pragma unroll
        for (int nf = 0; nf < 4; nf++)
            #pragma unroll
            for (int i = 0; i < 4; i++) acc[mf][nf][i] = 0.f;

    uint4 pab = *(const uint4*)(arb);
    uint4 pas = *(const uint4*)(ars);
    uint4 pwb = *(const uint4*)(wrb);
    uint4 pws = *(const uint4*)(wrs);

    const int niter = K / 16;
    for (int it = 0; it < niter; it++) {
        const int buf = it & 1;
        {
            const uint32_t ab[4] = {pab.x, pab.y, pab.z, pab.w};
            const uint32_t as[4] = {pas.x, pas.y, pas.z, pas.w};
            const uint32_t wb[4] = {pwb.x, pwb.y, pwb.z, pwb.w};
            const uint32_t ws[4] = {pws.x, pws.y, pws.z, pws.w};
            #pragma unroll
            for (int j2 = 0; j2 < 4; j2++) {
                const int k2 = k2q + j2;
                const int idx = k2 * 128 + (lrow ^ swz(k2));
                Atb[buf][idx] = ab[j2];
                Ats[buf][idx] = as[j2];
                Btb[buf][idx] = wb[j2];
                Bts[buf][idx] = ws[j2];
            }
        }
        if (it + 1 < niter) {
            const int k0 = (it + 1) * 16;
            pab = *(const uint4*)(arb + k0);
            pas = *(const uint4*)(ars + k0);
            pwb = *(const uint4*)(wrb + k0);
            pws = *(const uint4*)(wrs + k0);
        }
        __syncthreads();
        mma_chunk3<128>(Atb[buf], Ats[buf], Btb[buf], Bts[buf], 128, 0,
                        acc, mbase, nbase, r, q);
    }

    #pragma unroll
    for (int nf = 0; nf < 4; nf++) {
        const int n = n0 + nbase + nf * 8 + 2 * r;
        const float b0v = bias[n];
        const float b1v = bias[n + 1];
        #pragma unroll
        for (int mf = 0; mf < 4; mf++) {
            const int m = m0 + mbase + mf * 16 + q;
            float2 o0 = {acc[mf][nf][0] + b0v, acc[mf][nf][1] + b1v};
            float2 o1 = {acc[mf][nf][2] + b0v, acc[mf][nf][3] + b1v};
            *(float2*)(C + (size_t)m * N + n)       = o0;
            *(float2*)(C + (size_t)(m + 8) * N + n) = o1;
        }
    }
}

// ---------------- persistent LSTM layer kernel (W stationary in smem) ----------------
// grid = 128 CTAs (16 column tiles of 256 cols x 8 K-splits of 128), 256 threads.
// W_hh taken as fp32 and split in-kernel during the one-time smem load.
__global__ __launch_bounds__(256, 1)
void lstm_layer(const float* __restrict__ gx, const float* __restrict__ Whh,
                const float* __restrict__ h0, const float* __restrict__ c0,
                __nv_bfloat16* __restrict__ yb, __nv_bfloat16* __restrict__ ys)
{
    extern __shared__ uint32_t dynsm[];
    uint32_t* Wb_sm = dynsm;              // [64 * 256]
    uint32_t* Ws_sm = dynsm + 64 * 256;   // [64 * 256]
    __shared__ uint32_t hsb[2][8 * 64];
    __shared__ uint32_t hss[2][8 * 64];

    const int tid = threadIdx.x;
    const int bid = blockIdx.x;       // 0..127
    const int cs  = bid & 15;
    const int ks  = bid >> 4;
    const int col0 = cs * 256;
    const int gtid = bid * 256 + tid;

    const int warp = tid >> 5;
    const int lane = tid & 31;
    const int r = lane & 3;
    const int q = lane >> 2;
    const int nbase = warp * 32;

    unsigned sense = g_bars;

    // ---- one-time W slice load + split (256 cols x 128 k, fp32 source) ----
    {
        const float* wsrc = Whh + (size_t)(col0 + tid) * HH + ks * 128;
        #pragma unroll
        for (int g = 0; g < 16; g++) {
            float4 v0 = *(const float4*)(wsrc + 8 * g);
            float4 v1 = *(const float4*)(wsrc + 8 * g + 4);
            const float wv[8] = {v0.x, v0.y, v0.z, v0.w, v1.x, v1.y, v1.z, v1.w};
            #pragma unroll
            for (int j = 0; j < 4; j++) {
                __nv_bfloat16 b0, s0, b1, s1;
                bf16_split(wv[2 * j], b0, s0);
                bf16_split(wv[2 * j + 1], b1, s1);
                const int k2 = 4 * g + j;
                const int idx = k2 * 256 + (tid ^ swz(k2));
                Wb_sm[idx] = pack_bf2(b0, b1);
                Ws_sm[idx] = pack_bf2(s0, s1);
            }
        }
    }

    for (int i = gtid; i < BB * HH; i += 128 * 256) {
        g_h[i] = h0[i];
        g_c[i] = c0[i];
    }
    grid_bar(&sense);

    const int hrow = tid >> 2;
    const int hq   = (tid & 3) * 4;
    const int hk2  = hq >> 1;
    const float* hbase = g_h + (size_t)hrow * HH + ks * 128;

    const int cell0 = gtid;
    const int cell1 = gtid + 32768;

    for (int t = 0; t < TT; t++) {
        float acc[4][4][4];
        #pragma unroll
        for (int mf = 0; mf < 4; mf++)
            #pragma unroll
            for (int nf = 0; nf < 4; nf++)
                #pragma unroll
                for (int i = 0; i < 4; i++) acc[mf][nf][i] = 0.f;

        float4 hv = *(const float4*)(hbase + hq);

        #pragma unroll 1
        for (int kc = 0; kc < 8; kc++) {
            const int buf = kc & 1;
            {
                __nv_bfloat16 b0, s0v, b1, s1v, b2, s2v, b3, s3v;
                bf16_split(hv.x, b0, s0v);
                bf16_split(hv.y, b1, s1v);
                bf16_split(hv.z, b2, s2v);
                bf16_split(hv.w, b3, s3v);
                const int i0 = hk2 * 64 + (hrow ^ swz(hk2));
                const int i1 = (hk2 + 1) * 64 + (hrow ^ swz(hk2 + 1));
                hsb[buf][i0] = pack_bf2(b0, b1);
                hss[buf][i0] = pack_bf2(s0v, s1v);
                hsb[buf][i1] = pack_bf2(b2, b3);
                hss[buf][i1] = pack_bf2(s2v, s3v);
            }
            if (kc < 7)
                hv = *(const float4*)(hbase + (kc + 1) * 16 + hq);
            __syncthreads();
            mma_chunk3<64>(hsb[buf], hss[buf], Wb_sm, Ws_sm, 256, kc * 8,
                           acc, 0, nbase, r, q);
        }

        // write partials P[ks][b][col]
        #pragma unroll
        for (int nf = 0; nf < 4; nf++) {
            const int col = col0 + nbase + nf * 8 + 2 * r;
            #pragma unroll
            for (int mf = 0; mf < 4; mf++) {
                const int b = mf * 16 + q;
                float2 o0 = {acc[mf][nf][0], acc[mf][nf][1]};
                float2 o1 = {acc[mf][nf][2], acc[mf][nf][3]};
                *(float2*)(&g_part[((size_t)ks * BB + b) * NG + col])     = o0;
                *(float2*)(&g_part[((size_t)ks * BB + b + 8) * NG + col]) = o1;
            }
        }
        grid_bar(&sense);

        // Phase B: 65536 (b,j) cells, 2 per thread
        #pragma unroll
        for (int it = 0; it < 2; it++) {
            const int cell = (it == 0) ? cell0 : cell1;
            const int b = cell >> 10;
            const int j = cell & 1023;
            const float* gr = gx + ((size_t)b * TT + t) * NG;
            float gi = gr[j];
            float gf = gr[j + 1024];
            float gg = gr[j + 2048];
            float go = gr[j + 3072];
            #pragma unroll
            for (int s = 0; s < 8; s++) {
                const float* pp = &g_part[((size_t)s * BB + b) * NG + j];
                gi += pp[0];
                gf += pp[1024];
                gg += pp[2048];
                go += pp[3072];
            }

            float cv = g_c[cell];
            const float si = fast_sigmoid(gi);
            const float sf = fast_sigmoid(gf);
            const float so = fast_sigmoid(go);
            cv = sf * cv + si * fast_tanh(gg);
            const float hvv = so * fast_tanh(cv);
            g_c[cell] = cv;
            g_h[cell] = hvv;
            __nv_bfloat16 hb, hs;
            bf16_split(hvv, hb, hs);
            const size_t yi = ((size_t)b * TT + t) * HH + j;
            yb[yi] = hb;
            ys[yi] = hs;
        }
        grid_bar(&sense);
    }
}

// ---------------- launch ----------------
extern "C" void kernel_launch(void* const* d_in, const int* in_sizes, int n_in,
                              void* d_out, int out_size)
{
    const int*   x    = (const int*)  d_in[0];
    const float* emb  = (const float*)d_in[1];
    const float* Wih0 = (const float*)d_in[2];
    const float* Whh0 = (const float*)d_in[3];
    const float* b0   = (const float*)d_in[4];
    const float* Wih1 = (const float*)d_in[5];
    const float* Whh1 = (const float*)d_in[6];
    const float* b1   = (const float*)d_in[7];
    const float* fcW  = (const float*)d_in[8];
    const float* fcb  = (const float*)d_in[9];
    const float* h0   = (const float*)d_in[10];
    const float* c0   = (const float*)d_in[11];
    float* out = (float*)d_out;

    float *gx;
    __nv_bfloat16 *y0b, *y0s, *y1b, *y1s, *wAb, *wAs, *embb, *embs;
    cudaGetSymbolAddress((void**)&gx,   g_gx);
    cudaGetSymbolAddress((void**)&y0b,  g_y0b);
    cudaGetSymbolAddress((void**)&y0s,  g_y0s);
    cudaGetSymbolAddress((void**)&y1b,  g_y1b);
    cudaGetSymbolAddress((void**)&y1s,  g_y1s);
    cudaGetSymbolAddress((void**)&wAb,  g_wAb);
    cudaGetSymbolAddress((void**)&wAs,  g_wAs);
    cudaGetSymbolAddress((void**)&embb, g_embb);
    cudaGetSymbolAddress((void**)&embs, g_embs);

    const int LSTM_SMEM = 64 * 256 * 2 * (int)sizeof(uint32_t);  // 128 KB
    cudaFuncSetAttribute(lstm_layer, cudaFuncAttributeMaxDynamicSharedMemorySize, LSTM_SMEM);

    const int M = BB * TT;  // 16384

    cvt_split_kernel<<<512, 256>>>(emb, embb, embs, VV * HH);
    cvt_split_kernel<<<4096, 256>>>(Wih0, wAb, wAs, NG * HH);

    sgemm_sbf16<true><<<dim3(NG / 128, M / 128), 256>>>(embb, embs, x, wAb, wAs, b0, gx, M, NG, HH);
    lstm_layer<<<128, 256, LSTM_SMEM>>>(gx, Whh0, h0, c0, y0b, y0s);

    cvt_split_kernel<<<4096, 256>>>(Wih1, wAb, wAs, NG * HH);

    sgemm_sbf16<false><<<dim3(NG / 128, M / 128), 256>>>(y0b, y0s, nullptr, wAb, wAs, b1, gx, M, NG, HH);
    lstm_layer<<<128, 256, LSTM_SMEM>>>(gx, Whh1, h0 + BB * HH, c0 + BB * HH, y1b, y1s);

    cvt_split_kernel<<<1024, 256>>>(fcW, wAb, wAs, VV * HH);
    sgemm_sbf16<false><<<dim3(VV / 128, M / 128), 256>>>(y1b, y1s, nullptr, wAb, wAs, fcb, out, M, VV, HH);
}

// round 8
// speedup vs baseline: 2.2601x; 1.0613x over previous
#include <cuda_runtime.h>
#include <cuda_bf16.h>
#include <math.h>
#include <stdint.h>

#define BB 64
#define TT 256
#define HH 1024
#define VV 128
#define NG 4096   // 4*H

// ---------------- device scratch (no allocations allowed) ----------------
__device__ float g_gx[BB * TT * NG];              // gate pre-activations, T-major [T][B][4H]
__device__ __nv_bfloat16 g_y0b[BB * TT * HH];     // layer-0 output big
__device__ __nv_bfloat16 g_y0s[BB * TT * HH];     // layer-0 output small
__device__ __nv_bfloat16 g_y1b[BB * TT * HH];     // layer-1 output big
__device__ __nv_bfloat16 g_y1s[BB * TT * HH];     // layer-1 output small
__device__ float g_h[BB * HH];                    // hidden state (fp32)
__device__ float g_c[BB * HH];                    // cell state (fp32)
__device__ float g_part[8 * BB * NG];             // k-split partials
__device__ __nv_bfloat16 g_wAb[NG * HH];          // W_ih / fc_W big
__device__ __nv_bfloat16 g_wAs[NG * HH];          // W_ih / fc_W small
__device__ __nv_bfloat16 g_embb[VV * HH];         // embedding big
__device__ __nv_bfloat16 g_embs[VV * HH];         // embedding small
__device__ unsigned g_barc;
__device__ volatile unsigned g_bars;

// ---------------- helpers ----------------
__device__ __forceinline__ void bf16_split(float x, __nv_bfloat16& b, __nv_bfloat16& s) {
    b = __float2bfloat16(x);
    s = __float2bfloat16(x - __bfloat162float(b));
}

__device__ __forceinline__ uint32_t pack_bf2(__nv_bfloat16 lo, __nv_bfloat16 hi) {
    __nv_bfloat162 t = __halves2bfloat162(lo, hi);
    return *reinterpret_cast<uint32_t*>(&t);
}

// swizzle depends only on k2 mod 8 (verified consistent with fragment-read offsets)
__device__ __forceinline__ int swz(int k2) {
    return 8 * (k2 & 3) + 16 * ((k2 >> 2) & 1);
}

__device__ __forceinline__ void mma_bf16(float* d, const uint32_t* a, const uint32_t* b) {
    asm volatile(
        "mma.sync.aligned.m16n8k16.row.col.f32.bf16.bf16.f32 "
        "{%0,%1,%2,%3}, {%4,%5,%6,%7}, {%8,%9}, {%0,%1,%2,%3};\n"
        : "+f"(d[0]), "+f"(d[1]), "+f"(d[2]), "+f"(d[3])
        : "r"(a[0]), "r"(a[1]), "r"(a[2]), "r"(a[3]), "r"(b[0]), "r"(b[1]));
}

// MUFU reciprocal (~1.9e-7 rel err), single op
__device__ __forceinline__ float rcp_approx(float d) {
    float r;
    asm("rcp.approx.f32 %0, %1;" : "=f"(r) : "f"(d));
    return r;
}

__device__ __forceinline__ float fast_sigmoid(float x) {   // 1/(1+e^-x)
    const float a = fmaxf(fminf(-x, 40.f), -40.f);
    return rcp_approx(1.f + __expf(a));
}

__device__ __forceinline__ float fast_tanh(float x) {      // 1 - 2/(e^{2x}+1)
    const float a = fmaxf(fminf(2.f * x, 40.f), -40.f);
    return 1.f - 2.f * rcp_approx(__expf(a) + 1.f);
}

// Fused 3-product 16-k chunk: acc += Ab*Bb + Ab*Bs + As*Bb.
// Both A and B are full k-major arrays; chunk selected via k2 base.
template<int LDA>
__device__ __forceinline__ void mma_chunk3(const uint32_t* Ab32, const uint32_t* As32,
                                           const uint32_t* Bb32, const uint32_t* Bs32,
                                           int ldb, int k2b,
                                           float acc[4][4][4],
                                           int mbase, int nbase, int r, int q)
{
    const int s0 = 8 * r;
    const int s1 = 8 * r + 16;
    const int ra0 = (k2b + r) * LDA;
    const int ra1 = (k2b + r + 4) * LDA;
    const int rb0 = (k2b + r) * ldb;
    const int rb1 = (k2b + r + 4) * ldb;
    uint32_t bb[4][2], bs[4][2];
    #pragma unroll
    for (int nf = 0; nf < 4; nf++) {
        const int cb = nbase + nf * 8 + q;
        bb[nf][0] = Bb32[rb0 + (cb ^ s0)];
        bb[nf][1] = Bb32[rb1 + (cb ^ s1)];
        bs[nf][0] = Bs32[rb0 + (cb ^ s0)];
        bs[nf][1] = Bs32[rb1 + (cb ^ s1)];
    }
    {
        uint32_t ab[4][4];
        #pragma unroll
        for (int mf = 0; mf < 4; mf++) {
            const int c0 = mbase + mf * 16 + q;
            ab[mf][0] = Ab32[ra0 + (c0 ^ s0)];
            ab[mf][1] = Ab32[ra0 + ((c0 + 8) ^ s0)];
            ab[mf][2] = Ab32[ra1 + (c0 ^ s1)];
            ab[mf][3] = Ab32[ra1 + ((c0 + 8) ^ s1)];
        }
        #pragma unroll
        for (int mf = 0; mf < 4; mf++)
            #pragma unroll
            for (int nf = 0; nf < 4; nf++)
                mma_bf16(acc[mf][nf], ab[mf], bb[nf]);
        #pragma unroll
        for (int mf = 0; mf < 4; mf++)
            #pragma unroll
            for (int nf = 0; nf < 4; nf++)
                mma_bf16(acc[mf][nf], ab[mf], bs[nf]);
    }
    {
        uint32_t as[4][4];
        #pragma unroll
        for (int mf = 0; mf < 4; mf++) {
            const int c0 = mbase + mf * 16 + q;
            as[mf][0] = As32[ra0 + (c0 ^ s0)];
            as[mf][1] = As32[ra0 + ((c0 + 8) ^ s0)];
            as[mf][2] = As32[ra1 + (c0 ^ s1)];
            as[mf][3] = As32[ra1 + ((c0 + 8) ^ s1)];
        }
        #pragma unroll
        for (int mf = 0; mf < 4; mf++)
            #pragma unroll
            for (int nf = 0; nf < 4; nf++)
                mma_bf16(acc[mf][nf], as[mf], bb[nf]);
    }
}

// ---------------- grid-wide sense-reversing barrier (leader-only fences) ----------------
__device__ __forceinline__ void grid_bar(unsigned* sense) {
    __syncthreads();
    if (threadIdx.x == 0) {
        unsigned s = *sense ^ 1u;
        *sense = s;
        __threadfence();                       // release
        unsigned prev = atomicAdd(&g_barc, 1u);
        if (prev == gridDim.x - 1) {
            g_barc = 0u;
            __threadfence();
            g_bars = s;
        } else {
            while (g_bars != s) { }
            __threadfence();                   // acquire
        }
    }
    __syncthreads();
}

// ---------------- fp32 -> (bf16 big, bf16 small) split ----------------
__global__ void cvt_split_kernel(const float* __restrict__ src,
                                 __nv_bfloat16* __restrict__ dstb,
                                 __nv_bfloat16* __restrict__ dsts, int n) {
    for (int i = blockIdx.x * blockDim.x + threadIdx.x; i < n; i += gridDim.x * blockDim.x) {
        __nv_bfloat16 b, s;
        bf16_split(src[i], b, s);
        dstb[i] = b;
        dsts[i] = s;
    }
}

// ---------------- split-bf16 SGEMM (double-buffered, 2 CTAs/SM): C = A @ W^T + bias ----------------
// BM=128, BN=128, BK=16, 256 threads = 8 warps (2m x 4n), warp tile 64x32.
// TMAJOR: write C rows as (t*BB + b) instead of m = b*TT + t (gate buffer layout).
template <bool GATHER, bool TMAJOR>
__global__ __launch_bounds__(256, 2)
void sgemm_sbf16(const __nv_bfloat16* __restrict__ Ab, const __nv_bfloat16* __restrict__ As_,
                 const int* __restrict__ tok,
                 const __nv_bfloat16* __restrict__ Wb, const __nv_bfloat16* __restrict__ Ws_,
                 const float* __restrict__ bias,
                 float* __restrict__ C, int M, int N, int K)
{
    __shared__ uint32_t Atb[2][8 * 128];
    __shared__ uint32_t Ats[2][8 * 128];
    __shared__ uint32_t Btb[2][8 * 128];
    __shared__ uint32_t Bts[2][8 * 128];

    const int m0 = blockIdx.y * 128;
    const int n0 = blockIdx.x * 128;
    const int tid = threadIdx.x;
    const int warp = tid >> 5;
    const int lane = tid & 31;
    const int r = lane & 3;
    const int q = lane >> 2;
    const int mbase = (warp >> 2) * 64;
    const int nbase = (warp & 3) * 32;

    const int lrow = tid >> 1;          // 0..127
    const int lq   = (tid & 1) * 8;     // 0 or 8 (k offset)
    const int k2q  = lq >> 1;           // 0 or 4

    size_t aoff;
    if (GATHER) aoff = (size_t)tok[m0 + lrow] * K;
    else        aoff = (size_t)(m0 + lrow) * K;
    const __nv_bfloat16* arb = Ab  + aoff + lq;
    const __nv_bfloat16* ars = As_ + aoff + lq;
    const __nv_bfloat16* wrb = Wb  + (size_t)(n0 + lrow) * K + lq;
    const __nv_bfloat16* wrs = Ws_ + (size_t)(n0 + lrow) * K + lq;

    float acc[4][4][4];
    #pragma unroll
    for (int mf = 0; mf < 4; mf++)
        #pragma unroll
        for (int nf = 0; nf < 4; nf++)
            #pragma unroll
            for (int i = 0; i < 4; i++) acc[mf][nf][i] = 0.f;

    uint4 pab = *(const uint4*)(arb);
    uint4 pas = *(const uint4*)(ars);
    uint4 pwb = *(const uint4*)(wrb);
    uint4 pws = *(const uint4*)(wrs);

    const int niter = K / 16;
    for (int it = 0; it < niter; it++) {
        const int buf = it & 1;
        {
            const uint32_t ab[4] = {pab.x, pab.y, pab.z, pab.w};
            const uint32_t as[4] = {pas.x, pas.y, pas.z, pas.w};
            const uint32_t wb[4] = {pwb.x, pwb.y, pwb.z, pwb.w};
            const uint32_t ws[4] = {pws.x, pws.y, pws.z, pws.w};
            #pragma unroll
            for (int j2 = 0; j2 < 4; j2++) {
                const int k2 = k2q + j2;
                const int idx = k2 * 128 + (lrow ^ swz(k2));
                Atb[buf][idx] = ab[j2];
                Ats[buf][idx] = as[j2];
                Btb[buf][idx] = wb[j2];
                Bts[buf][idx] = ws[j2];
            }
        }
        if (it + 1 < niter) {
            const int k0 = (it + 1) * 16;
            pab = *(const uint4*)(arb + k0);
            pas = *(const uint4*)(ars + k0);
            pwb = *(const uint4*)(wrb + k0);
            pws = *(const uint4*)(wrs + k0);
        }
        __syncthreads();
        mma_chunk3<128>(Atb[buf], Ats[buf], Btb[buf], Bts[buf], 128, 0,
                        acc, mbase, nbase, r, q);
    }

    #pragma unroll
    for (int nf = 0; nf < 4; nf++) {
        const int n = n0 + nbase + nf * 8 + 2 * r;
        const float b0v = bias[n];
        const float b1v = bias[n + 1];
        #pragma unroll
        for (int mf = 0; mf < 4; mf++) {
            const int m = m0 + mbase + mf * 16 + q;
            size_t row0, row1;
            if (TMAJOR) {
                row0 = (size_t)((m % TT) * BB + m / TT);
                const int m8 = m + 8;
                row1 = (size_t)((m8 % TT) * BB + m8 / TT);
            } else {
                row0 = (size_t)m;
                row1 = (size_t)(m + 8);
            }
            float2 o0 = {acc[mf][nf][0] + b0v, acc[mf][nf][1] + b1v};
            float2 o1 = {acc[mf][nf][2] + b0v, acc[mf][nf][3] + b1v};
            *(float2*)(C + row0 * N + n) = o0;
            *(float2*)(C + row1 * N + n) = o1;
        }
    }
}

// ---------------- persistent LSTM layer kernel ----------------
// grid = 128 CTAs (16 column tiles of 256 cols x 8 K-splits of 128), 256 threads.
// W slice stationary in 128 KB dyn smem; full h slice (64b x 128k) staged per step
// into 32 KB static smem with ONE syncthreads, then 384 mma straight-line.
// gx is T-major: [T][B][4H].
__global__ __launch_bounds__(256, 1)
void lstm_layer(const float* __restrict__ gx, const float* __restrict__ Whh,
                const float* __restrict__ h0, const float* __restrict__ c0,
                __nv_bfloat16* __restrict__ yb, __nv_bfloat16* __restrict__ ys)
{
    extern __shared__ uint32_t dynsm[];
    uint32_t* Wb_sm = dynsm;              // [64 k2][256]
    uint32_t* Ws_sm = dynsm + 64 * 256;
    __shared__ uint32_t hsb[64 * 64];     // [64 k2][64 b]
    __shared__ uint32_t hss[64 * 64];

    const int tid = threadIdx.x;
    const int bid = blockIdx.x;       // 0..127
    const int cs  = bid & 15;
    const int ks  = bid >> 4;
    const int col0 = cs * 256;
    const int gtid = bid * 256 + tid;

    const int warp = tid >> 5;
    const int lane = tid & 31;
    const int r = lane & 3;
    const int q = lane >> 2;
    const int nbase = warp * 32;

    unsigned sense = g_bars;

    // ---- one-time W slice load + split (256 cols x 128 k, fp32 source) ----
    {
        const float* wsrc = Whh + (size_t)(col0 + tid) * HH + ks * 128;
        #pragma unroll
        for (int g = 0; g < 16; g++) {
            float4 v0 = *(const float4*)(wsrc + 8 * g);
            float4 v1 = *(const float4*)(wsrc + 8 * g + 4);
            const float wv[8] = {v0.x, v0.y, v0.z, v0.w, v1.x, v1.y, v1.z, v1.w};
            #pragma unroll
            for (int j = 0; j < 4; j++) {
                __nv_bfloat16 b0, s0, b1, s1;
                bf16_split(wv[2 * j], b0, s0);
                bf16_split(wv[2 * j + 1], b1, s1);
                const int k2 = 4 * g + j;
                const int idx = k2 * 256 + (tid ^ swz(k2));
                Wb_sm[idx] = pack_bf2(b0, b1);
                Ws_sm[idx] = pack_bf2(s0, s1);
            }
        }
    }

    for (int i = gtid; i < BB * HH; i += 128 * 256) {
        g_h[i] = h0[i];
        g_c[i] = c0[i];
    }
    grid_bar(&sense);

    const int hrow = tid >> 2;              // b 0..63
    const int hq   = (tid & 3) * 4;         // k offset within 16-chunk
    const int hk2  = hq >> 1;               // local k2 offset {0,2,4,6}
    const float* hbase = g_h + (size_t)hrow * HH + ks * 128;

    const int cell0 = gtid;
    const int cell1 = gtid + 32768;

    for (int t = 0; t < TT; t++) {
        // ---- stage entire h slice (64 b x 128 k), split to bf16, one sync ----
        #pragma unroll
        for (int g8 = 0; g8 < 8; g8++) {
            float4 hv = *(const float4*)(hbase + g8 * 16 + hq);
            __nv_bfloat16 b0, s0v, b1, s1v, b2, s2v, b3, s3v;
            bf16_split(hv.x, b0, s0v);
            bf16_split(hv.y, b1, s1v);
            bf16_split(hv.z, b2, s2v);
            bf16_split(hv.w, b3, s3v);
            const int k2a = g8 * 8 + hk2;
            const int i0 = k2a * 64 + (hrow ^ swz(k2a));
            const int i1 = (k2a + 1) * 64 + (hrow ^ swz(k2a + 1));
            hsb[i0] = pack_bf2(b0, b1);
            hss[i0] = pack_bf2(s0v, s1v);
            hsb[i1] = pack_bf2(b2, b3);
            hss[i1] = pack_bf2(s2v, s3v);
        }
        __syncthreads();

        float acc[4][4][4];
        #pragma unroll
        for (int mf = 0; mf < 4; mf++)
            #pragma unroll
            for (int nf = 0; nf < 4; nf++)
                #pragma unroll
                for (int i = 0; i < 4; i++) acc[mf][nf][i] = 0.f;

        // ---- 8 chunks of mma back-to-back, no intervening syncs ----
        #pragma unroll
        for (int kc = 0; kc < 8; kc++)
            mma_chunk3<64>(hsb, hss, Wb_sm, Ws_sm, 256, kc * 8,
                           acc, 0, nbase, r, q);

        // write partials P[ks][b][col]
        #pragma unroll
        for (int nf = 0; nf < 4; nf++) {
            const int col = col0 + nbase + nf * 8 + 2 * r;
            #pragma unroll
            for (int mf = 0; mf < 4; mf++) {
                const int b = mf * 16 + q;
                float2 o0 = {acc[mf][nf][0], acc[mf][nf][1]};
                float2 o1 = {acc[mf][nf][2], acc[mf][nf][3]};
                *(float2*)(&g_part[((size_t)ks * BB + b) * NG + col])     = o0;
                *(float2*)(&g_part[((size_t)ks * BB + b + 8) * NG + col]) = o1;
            }
        }
        grid_bar(&sense);

        // ---- Phase B: 65536 (b,j) cells, 2 per thread; gx is T-major ----
        const float* gxt = gx + (size_t)t * BB * NG;
        #pragma unroll
        for (int it = 0; it < 2; it++) {
            const int cell = (it == 0) ? cell0 : cell1;
            const int b = cell >> 10;
            const int j = cell & 1023;
            const float* gr = gxt + (size_t)b * NG;
            float gi = gr[j];
            float gf = gr[j + 1024];
            float gg = gr[j + 2048];
            float go = gr[j + 3072];
            #pragma unroll
            for (int s = 0; s < 8; s++) {
                const float* pp = &g_part[((size_t)s * BB + b) * NG + j];
                gi += pp[0];
                gf += pp[1024];
                gg += pp[2048];
                go += pp[3072];
            }

            float cv = g_c[cell];
            const float si = fast_sigmoid(gi);
            const float sf = fast_sigmoid(gf);
            const float so = fast_sigmoid(go);
            cv = sf * cv + si * fast_tanh(gg);
            const float hvv = so * fast_tanh(cv);
            g_c[cell] = cv;
            g_h[cell] = hvv;
            __nv_bfloat16 hb, hs;
            bf16_split(hvv, hb, hs);
            const size_t yi = ((size_t)b * TT + t) * HH + j;
            yb[yi] = hb;
            ys[yi] = hs;
        }
        grid_bar(&sense);
    }
}

// ---------------- launch ----------------
extern "C" void kernel_launch(void* const* d_in, const int* in_sizes, int n_in,
                              void* d_out, int out_size)
{
    const int*   x    = (const int*)  d_in[0];
    const float* emb  = (const float*)d_in[1];
    const float* Wih0 = (const float*)d_in[2];
    const float* Whh0 = (const float*)d_in[3];
    const float* b0   = (const float*)d_in[4];
    const float* Wih1 = (const float*)d_in[5];
    const float* Whh1 = (const float*)d_in[6];
    const float* b1   = (const float*)d_in[7];
    const float* fcW  = (const float*)d_in[8];
    const float* fcb  = (const float*)d_in[9];
    const float* h0   = (const float*)d_in[10];
    const float* c0   = (const float*)d_in[11];
    float* out = (float*)d_out;

    float *gx;
    __nv_bfloat16 *y0b, *y0s, *y1b, *y1s, *wAb, *wAs, *embb, *embs;
    cudaGetSymbolAddress((void**)&gx,   g_gx);
    cudaGetSymbolAddress((void**)&y0b,  g_y0b);
    cudaGetSymbolAddress((void**)&y0s,  g_y0s);
    cudaGetSymbolAddress((void**)&y1b,  g_y1b);
    cudaGetSymbolAddress((void**)&y1s,  g_y1s);
    cudaGetSymbolAddress((void**)&wAb,  g_wAb);
    cudaGetSymbolAddress((void**)&wAs,  g_wAs);
    cudaGetSymbolAddress((void**)&embb, g_embb);
    cudaGetSymbolAddress((void**)&embs, g_embs);

    const int LSTM_SMEM = 64 * 256 * 2 * (int)sizeof(uint32_t);  // 128 KB dynamic
    cudaFuncSetAttribute(lstm_layer, cudaFuncAttributeMaxDynamicSharedMemorySize, LSTM_SMEM);

    const int M = BB * TT;  // 16384

    cvt_split_kernel<<<512, 256>>>(emb, embb, embs, VV * HH);
    cvt_split_kernel<<<4096, 256>>>(Wih0, wAb, wAs, NG * HH);

    sgemm_sbf16<true, true><<<dim3(NG / 128, M / 128), 256>>>(embb, embs, x, wAb, wAs, b0, gx, M, NG, HH);
    lstm_layer<<<128, 256, LSTM_SMEM>>>(gx, Whh0, h0, c0, y0b, y0s);

    cvt_split_kernel<<<4096, 256>>>(Wih1, wAb, wAs, NG * HH);

    sgemm_sbf16<false, true><<<dim3(NG / 128, M / 128), 256>>>(y0b, y0s, nullptr, wAb, wAs, b1, gx, M, NG, HH);
    lstm_layer<<<128, 256, LSTM_SMEM>>>(gx, Whh1, h0 + BB * HH, c0 + BB * HH, y1b, y1s);

    cvt_split_kernel<<<1024, 256>>>(fcW, wAb, wAs, VV * HH);
    sgemm_sbf16<false, false><<<dim3(VV / 128, M / 128), 256>>>(y1b, y1s, nullptr, wAb, wAs, fcb, out, M, VV, HH);
}

// round 9
// speedup vs baseline: 2.2679x; 1.0034x over previous
#include <cuda_runtime.h>
#include <cuda_bf16.h>
#include <math.h>
#include <stdint.h>

#define BB 64
#define TT 256
#define HH 1024
#define VV 128
#define NG 4096   // 4*H

// ---------------- device scratch (no allocations allowed) ----------------
__device__ float g_gx[BB * TT * NG];              // gate pre-activations, T-major [T][B][4H]
__device__ __nv_bfloat16 g_y0b[BB * TT * HH];     // layer-0 output big
__device__ __nv_bfloat16 g_y0s[BB * TT * HH];     // layer-0 output small
__device__ __nv_bfloat16 g_y1b[BB * TT * HH];     // layer-1 output big
__device__ __nv_bfloat16 g_y1s[BB * TT * HH];     // layer-1 output small
__device__ float g_h[BB * HH];                    // hidden state (fp32)
__device__ float g_c[BB * HH];                    // cell state (fp32)
__device__ float g_part[8 * BB * NG];             // k-split partials
__device__ __nv_bfloat16 g_wAb[NG * HH];          // W_ih / fc_W big
__device__ __nv_bfloat16 g_wAs[NG * HH];          // W_ih / fc_W small
__device__ __nv_bfloat16 g_embb[VV * HH];         // embedding big
__device__ __nv_bfloat16 g_embs[VV * HH];         // embedding small
__device__ unsigned g_barc1[16];                  // level-1 barrier counters (8 CTAs each)
__device__ unsigned g_barc0;                      // root counter (16 arrivals)
__device__ volatile unsigned g_bars;              // barrier sense flag

// ---------------- helpers ----------------
__device__ __forceinline__ void bf16_split(float x, __nv_bfloat16& b, __nv_bfloat16& s) {
    b = __float2bfloat16(x);
    s = __float2bfloat16(x - __bfloat162float(b));
}

__device__ __forceinline__ uint32_t pack_bf2(__nv_bfloat16 lo, __nv_bfloat16 hi) {
    __nv_bfloat162 t = __halves2bfloat162(lo, hi);
    return *reinterpret_cast<uint32_t*>(&t);
}

__device__ __forceinline__ int swz(int k2) {
    return 8 * (k2 & 3) + 16 * ((k2 >> 2) & 1);
}

__device__ __forceinline__ void mma_bf16(float* d, const uint32_t* a, const uint32_t* b) {
    asm volatile(
        "mma.sync.aligned.m16n8k16.row.col.f32.bf16.bf16.f32 "
        "{%0,%1,%2,%3}, {%4,%5,%6,%7}, {%8,%9}, {%0,%1,%2,%3};\n"
        : "+f"(d[0]), "+f"(d[1]), "+f"(d[2]), "+f"(d[3])
        : "r"(a[0]), "r"(a[1]), "r"(a[2]), "r"(a[3]), "r"(b[0]), "r"(b[1]));
}

__device__ __forceinline__ float rcp_approx(float d) {
    float r;
    asm("rcp.approx.f32 %0, %1;" : "=f"(r) : "f"(d));
    return r;
}

__device__ __forceinline__ float fast_sigmoid(float x) {   // 1/(1+e^-x)
    const float a = fmaxf(fminf(-x, 40.f), -40.f);
    return rcp_approx(1.f + __expf(a));
}

__device__ __forceinline__ float fast_tanh(float x) {      // 1 - 2/(e^{2x}+1)
    const float a = fmaxf(fminf(2.f * x, 40.f), -40.f);
    return 1.f - 2.f * rcp_approx(__expf(a) + 1.f);
}

// Fused 3-product 16-k chunk: acc += Ab*Bb + Ab*Bs + As*Bb.
template<int LDA>
__device__ __forceinline__ void mma_chunk3(const uint32_t* Ab32, const uint32_t* As32,
                                           const uint32_t* Bb32, const uint32_t* Bs32,
                                           int ldb, int k2b,
                                           float acc[4][4][4],
                                           int mbase, int nbase, int r, int q)
{
    const int s0 = 8 * r;
    const int s1 = 8 * r + 16;
    const int ra0 = (k2b + r) * LDA;
    const int ra1 = (k2b + r + 4) * LDA;
    const int rb0 = (k2b + r) * ldb;
    const int rb1 = (k2b + r + 4) * ldb;
    uint32_t bb[4][2], bs[4][2];
    #pragma unroll
    for (int nf = 0; nf < 4; nf++) {
        const int cb = nbase + nf * 8 + q;
        bb[nf][0] = Bb32[rb0 + (cb ^ s0)];
        bb[nf][1] = Bb32[rb1 + (cb ^ s1)];
        bs[nf][0] = Bs32[rb0 + (cb ^ s0)];
        bs[nf][1] = Bs32[rb1 + (cb ^ s1)];
    }
    {
        uint32_t ab[4][4];
        #pragma unroll
        for (int mf = 0; mf < 4; mf++) {
            const int c0 = mbase + mf * 16 + q;
            ab[mf][0] = Ab32[ra0 + (c0 ^ s0)];
            ab[mf][1] = Ab32[ra0 + ((c0 + 8) ^ s0)];
            ab[mf][2] = Ab32[ra1 + (c0 ^ s1)];
            ab[mf][3] = Ab32[ra1 + ((c0 + 8) ^ s1)];
        }
        #pragma unroll
        for (int mf = 0; mf < 4; mf++)
            #pragma unroll
            for (int nf = 0; nf < 4; nf++)
                mma_bf16(acc[mf][nf], ab[mf], bb[nf]);
        #pragma unroll
        for (int mf = 0; mf < 4; mf++)
            #pragma unroll
            for (int nf = 0; nf < 4; nf++)
                mma_bf16(acc[mf][nf], ab[mf], bs[nf]);
    }
    {
        uint32_t as[4][4];
        #pragma unroll
        for (int mf = 0; mf < 4; mf++) {
            const int c0 = mbase + mf * 16 + q;
            as[mf][0] = As32[ra0 + (c0 ^ s0)];
            as[mf][1] = As32[ra0 + ((c0 + 8) ^ s0)];
            as[mf][2] = As32[ra1 + (c0 ^ s1)];
            as[mf][3] = As32[ra1 + ((c0 + 8) ^ s1)];
        }
        #pragma unroll
        for (int mf = 0; mf < 4; mf++)
            #pragma unroll
            for (int nf = 0; nf < 4; nf++)
                mma_bf16(acc[mf][nf], as[mf], bb[nf]);
    }
}

// ---------------- two-level grid barrier (8x16 tree, leader-only) ----------------
// Arrival serialization: 8 atomics on a group line + 16 on the root
// (~800 cyc) instead of 128 on one line (~4000 cyc).
__device__ __forceinline__ void grid_bar(unsigned* sense) {
    __syncthreads();
    if (threadIdx.x == 0) {
        unsigned s = *sense ^ 1u;
        *sense = s;
        __threadfence();                                   // release
        const unsigned g = blockIdx.x >> 3;
        if (atomicAdd(&g_barc1[g], 1u) == 7u) {
            atomicExch(&g_barc1[g], 0u);
            if (atomicAdd(&g_barc0, 1u) == 15u) {
                atomicExch(&g_barc0, 0u);
                __threadfence();
                g_bars = s;
            } else {
                while (g_bars != s) { }
                __threadfence();                           // acquire
            }
        } else {
            while (g_bars != s) { }
            __threadfence();                               // acquire
        }
    }
    __syncthreads();
}

// ---------------- fp32 -> (bf16 big, bf16 small) split ----------------
__global__ void cvt_split_kernel(const float* __restrict__ src,
                                 __nv_bfloat16* __restrict__ dstb,
                                 __nv_bfloat16* __restrict__ dsts, int n) {
    for (int i = blockIdx.x * blockDim.x + threadIdx.x; i < n; i += gridDim.x * blockDim.x) {
        __nv_bfloat16 b, s;
        bf16_split(src[i], b, s);
        dstb[i] = b;
        dsts[i] = s;
    }
}

// ---------------- split-bf16 SGEMM (double-buffered, 2 CTAs/SM): C = A @ W^T + bias ----------------
template <bool GATHER, bool TMAJOR>
__global__ __launch_bounds__(256, 2)
void sgemm_sbf16(const __nv_bfloat16* __restrict__ Ab, const __nv_bfloat16* __restrict__ As_,
                 const int* __restrict__ tok,
                 const __nv_bfloat16* __restrict__ Wb, const __nv_bfloat16* __restrict__ Ws_,
                 const float* __restrict__ bias,
                 float* __restrict__ C, int M, int N, int K)
{
    __shared__ uint32_t Atb[2][8 * 128];
    __shared__ uint32_t Ats[2][8 * 128];
    __shared__ uint32_t Btb[2][8 * 128];
    __shared__ uint32_t Bts[2][8 * 128];

    const int m0 = blockIdx.y * 128;
    const int n0 = blockIdx.x * 128;
    const int tid = threadIdx.x;
    const int warp = tid >> 5;
    const int lane = tid & 31;
    const int r = lane & 3;
    const int q = lane >> 2;
    const int mbase = (warp >> 2) * 64;
    const int nbase = (warp & 3) * 32;

    const int lrow = tid >> 1;          // 0..127
    const int lq   = (tid & 1) * 8;     // 0 or 8 (k offset)
    const int k2q  = lq >> 1;           // 0 or 4

    size_t aoff;
    if (GATHER) aoff = (size_t)tok[m0 + lrow] * K;
    else        aoff = (size_t)(m0 + lrow) * K;
    const __nv_bfloat16* arb = Ab  + aoff + lq;
    const __nv_bfloat16* ars = As_ + aoff + lq;
    const __nv_bfloat16* wrb = Wb  + (size_t)(n0 + lrow) * K + lq;
    const __nv_bfloat16* wrs = Ws_ + (size_t)(n0 + lrow) * K + lq;

    float acc[4][4][4];
    #pragma unroll
    for (int mf = 0; mf < 4; mf++)
        #pragma unroll
        for (int nf = 0; nf < 4; nf++)
            #pragma unroll
            for (int i = 0; i < 4; i++) acc[mf][nf][i] = 0.f;

    uint4 pab = *(const uint4*)(arb);
    uint4 pas = *(const uint4*)(ars);
    uint4 pwb = *(const uint4*)(wrb);
    uint4 pws = *(const uint4*)(wrs);

    const int niter = K / 16;
    for (int it = 0; it < niter; it++) {
        const int buf = it & 1;
        {
            const uint32_t ab[4] = {pab.x, pab.y, pab.z, pab.w};
            const uint32_t as[4] = {pas.x, pas.y, pas.z, pas.w};
            const uint32_t wb[4] = {pwb.x, pwb.y, pwb.z, pwb.w};
            const uint32_t ws[4] = {pws.x, pws.y, pws.z, pws.w};
            #pragma unroll
            for (int j2 = 0; j2 < 4; j2++) {
                const int k2 = k2q + j2;
                const int idx = k2 * 128 + (lrow ^ swz(k2));
                Atb[buf][idx] = ab[j2];
                Ats[buf][idx] = as[j2];
                Btb[buf][idx] = wb[j2];
                Bts[buf][idx] = ws[j2];
            }
        }
        if (it + 1 < niter) {
            const int k0 = (it + 1) * 16;
            pab = *(const uint4*)(arb + k0);
            pas = *(const uint4*)(ars + k0);
            pwb = *(const uint4*)(wrb + k0);
            pws = *(const uint4*)(wrs + k0);
        }
        __syncthreads();
        mma_chunk3<128>(Atb[buf], Ats[buf], Btb[buf], Bts[buf], 128, 0,
                        acc, mbase, nbase, r, q);
    }

    #pragma unroll
    for (int nf = 0; nf < 4; nf++) {
        const int n = n0 + nbase + nf * 8 + 2 * r;
        const float b0v = bias[n];
        const float b1v = bias[n + 1];
        #pragma unroll
        for (int mf = 0; mf < 4; mf++) {
            const int m = m0 + mbase + mf * 16 + q;
            size_t row0, row1;
            if (TMAJOR) {
                row0 = (size_t)((m % TT) * BB + m / TT);
                const int m8 = m + 8;
                row1 = (size_t)((m8 % TT) * BB + m8 / TT);
            } else {
                row0 = (size_t)m;
                row1 = (size_t)(m + 8);
            }
            float2 o0 = {acc[mf][nf][0] + b0v, acc[mf][nf][1] + b1v};
            float2 o1 = {acc[mf][nf][2] + b0v, acc[mf][nf][3] + b1v};
            *(float2*)(C + row0 * N + n) = o0;
            *(float2*)(C + row1 * N + n) = o1;
        }
    }
}

// ---------------- persistent LSTM layer kernel ----------------
// grid = 128 CTAs (16 col tiles x 8 k-splits), 256 threads. W stationary in smem.
// Phase B: each thread owns 2 consecutive j's -> all global accesses 64-bit;
// gx[t] and c prefetched before barrier 1.
__global__ __launch_bounds__(256, 1)
void lstm_layer(const float* __restrict__ gx, const float* __restrict__ Whh,
                const float* __restrict__ h0, const float* __restrict__ c0,
                __nv_bfloat16* __restrict__ yb, __nv_bfloat16* __restrict__ ys)
{
    extern __shared__ uint32_t dynsm[];
    uint32_t* Wb_sm = dynsm;              // [64 k2][256]
    uint32_t* Ws_sm = dynsm + 64 * 256;
    __shared__ uint32_t hsb[64 * 64];     // [64 k2][64 b]
    __shared__ uint32_t hss[64 * 64];

    const int tid = threadIdx.x;
    const int bid = blockIdx.x;       // 0..127
    const int cs  = bid & 15;
    const int ks  = bid >> 4;
    const int col0 = cs * 256;
    const int gtid = bid * 256 + tid;

    const int warp = tid >> 5;
    const int lane = tid & 31;
    const int r = lane & 3;
    const int q = lane >> 2;
    const int nbase = warp * 32;

    unsigned sense = g_bars;

    // ---- one-time W slice load + split ----
    {
        const float* wsrc = Whh + (size_t)(col0 + tid) * HH + ks * 128;
        #pragma unroll
        for (int g = 0; g < 16; g++) {
            float4 v0 = *(const float4*)(wsrc + 8 * g);
            float4 v1 = *(const float4*)(wsrc + 8 * g + 4);
            const float wv[8] = {v0.x, v0.y, v0.z, v0.w, v1.x, v1.y, v1.z, v1.w};
            #pragma unroll
            for (int j = 0; j < 4; j++) {
                __nv_bfloat16 b0, s0, b1, s1;
                bf16_split(wv[2 * j], b0, s0);
                bf16_split(wv[2 * j + 1], b1, s1);
                const int k2 = 4 * g + j;
                const int idx = k2 * 256 + (tid ^ swz(k2));
                Wb_sm[idx] = pack_bf2(b0, b1);
                Ws_sm[idx] = pack_bf2(s0, s1);
            }
        }
    }

    for (int i = gtid; i < BB * HH; i += 128 * 256) {
        g_h[i] = h0[i];
        g_c[i] = c0[i];
    }
    grid_bar(&sense);

    const int hrow = tid >> 2;              // b 0..63
    const int hq   = (tid & 3) * 4;         // k offset within 16-chunk
    const int hk2  = hq >> 1;               // local k2 offset {0,2,4,6}
    const float* hbase = g_h + (size_t)hrow * HH + ks * 128;

    // phase-B: 2 consecutive j's per thread
    const int pb_b  = gtid >> 9;            // batch 0..63
    const int pb_j  = (gtid & 511) * 2;     // even j 0..1022
    const int cellp = pb_b * 1024 + pb_j;

    for (int t = 0; t < TT; t++) {
        // ---- stage entire h slice (64 b x 128 k), split to bf16, one sync ----
        #pragma unroll
        for (int g8 = 0; g8 < 8; g8++) {
            float4 hv = *(const float4*)(hbase + g8 * 16 + hq);
            __nv_bfloat16 b0, s0v, b1, s1v, b2, s2v, b3, s3v;
            bf16_split(hv.x, b0, s0v);
            bf16_split(hv.y, b1, s1v);
            bf16_split(hv.z, b2, s2v);
            bf16_split(hv.w, b3, s3v);
            const int k2a = g8 * 8 + hk2;
            const int i0 = k2a * 64 + (hrow ^ swz(k2a));
            const int i1 = (k2a + 1) * 64 + (hrow ^ swz(k2a + 1));
            hsb[i0] = pack_bf2(b0, b1);
            hss[i0] = pack_bf2(s0v, s1v);
            hsb[i1] = pack_bf2(b2, b3);
            hss[i1] = pack_bf2(s2v, s3v);
        }
        __syncthreads();

        float acc[4][4][4];
        #pragma unroll
        for (int mf = 0; mf < 4; mf++)
            #pragma unroll
            for (int nf = 0; nf < 4; nf++)
                #pragma unroll
                for (int i = 0; i < 4; i++) acc[mf][nf][i] = 0.f;

        #pragma unroll
        for (int kc = 0; kc < 8; kc++)
            mma_chunk3<64>(hsb, hss, Wb_sm, Ws_sm, 256, kc * 8,
                           acc, 0, nbase, r, q);

        // write partials P[ks][b][col]
        #pragma unroll
        for (int nf = 0; nf < 4; nf++) {
            const int col = col0 + nbase + nf * 8 + 2 * r;
            #pragma unroll
            for (int mf = 0; mf < 4; mf++) {
                const int b = mf * 16 + q;
                float2 o0 = {acc[mf][nf][0], acc[mf][nf][1]};
                float2 o1 = {acc[mf][nf][2], acc[mf][nf][3]};
                *(float2*)(&g_part[((size_t)ks * BB + b) * NG + col])     = o0;
                *(float2*)(&g_part[((size_t)ks * BB + b + 8) * NG + col]) = o1;
            }
        }

        // ---- prefetch gx[t] and c for phase B (independent of partials) ----
        const float* gr = gx + (size_t)t * BB * NG + (size_t)pb_b * NG + pb_j;
        const float2 xg0 = *(const float2*)(gr);
        const float2 xg1 = *(const float2*)(gr + 1024);
        const float2 xg2 = *(const float2*)(gr + 2048);
        const float2 xg3 = *(const float2*)(gr + 3072);
        float2 cv = *(const float2*)(&g_c[cellp]);

        grid_bar(&sense);

        // ---- Phase B: 2 consecutive cells per thread, all 64-bit accesses ----
        {
            float2 gi = xg0, gf = xg1, gg = xg2, go = xg3;
            #pragma unroll
            for (int s = 0; s < 8; s++) {
                const float* pp = &g_part[((size_t)s * BB + pb_b) * NG + pb_j];
                const float2 p0 = *(const float2*)(pp);
                const float2 p1 = *(const float2*)(pp + 1024);
                const float2 p2 = *(const float2*)(pp + 2048);
                const float2 p3 = *(const float2*)(pp + 3072);
                gi.x += p0.x; gi.y += p0.y;
                gf.x += p1.x; gf.y += p1.y;
                gg.x += p2.x; gg.y += p2.y;
                go.x += p3.x; go.y += p3.y;
            }

            const float si0 = fast_sigmoid(gi.x);
            const float si1 = fast_sigmoid(gi.y);
            const float sf0 = fast_sigmoid(gf.x);
            const float sf1 = fast_sigmoid(gf.y);
            const float so0 = fast_sigmoid(go.x);
            const float so1 = fast_sigmoid(go.y);
            cv.x = sf0 * cv.x + si0 * fast_tanh(gg.x);
            cv.y = sf1 * cv.y + si1 * fast_tanh(gg.y);
            const float hv0 = so0 * fast_tanh(cv.x);
            const float hv1 = so1 * fast_tanh(cv.y);
            *(float2*)(&g_c[cellp]) = cv;
            float2 hw = {hv0, hv1};
            *(float2*)(&g_h[cellp]) = hw;

            __nv_bfloat16 hb0, hs0, hb1, hs1;
            bf16_split(hv0, hb0, hs0);
            bf16_split(hv1, hb1, hs1);
            const size_t yi = ((size_t)pb_b * TT + t) * HH + pb_j;
            *(uint32_t*)(yb + yi) = pack_bf2(hb0, hb1);
            *(uint32_t*)(ys + yi) = pack_bf2(hs0, hs1);
        }
        grid_bar(&sense);
    }
}

// ---------------- launch ----------------
extern "C" void kernel_launch(void* const* d_in, const int* in_sizes, int n_in,
                              void* d_out, int out_size)
{
    const int*   x    = (const int*)  d_in[0];
    const float* emb  = (const float*)d_in[1];
    const float* Wih0 = (const float*)d_in[2];
    const float* Whh0 = (const float*)d_in[3];
    const float* b0   = (const float*)d_in[4];
    const float* Wih1 = (const float*)d_in[5];
    const float* Whh1 = (const float*)d_in[6];
    const float* b1   = (const float*)d_in[7];
    const float* fcW  = (const float*)d_in[8];
    const float* fcb  = (const float*)d_in[9];
    const float* h0   = (const float*)d_in[10];
    const float* c0   = (const float*)d_in[11];
    float* out = (float*)d_out;

    float *gx;
    __nv_bfloat16 *y0b, *y0s, *y1b, *y1s, *wAb, *wAs, *embb, *embs;
    cudaGetSymbolAddress((void**)&gx,   g_gx);
    cudaGetSymbolAddress((void**)&y0b,  g_y0b);
    cudaGetSymbolAddress((void**)&y0s,  g_y0s);
    cudaGetSymbolAddress((void**)&y1b,  g_y1b);
    cudaGetSymbolAddress((void**)&y1s,  g_y1s);
    cudaGetSymbolAddress((void**)&wAb,  g_wAb);
    cudaGetSymbolAddress((void**)&wAs,  g_wAs);
    cudaGetSymbolAddress((void**)&embb, g_embb);
    cudaGetSymbolAddress((void**)&embs, g_embs);

    const int LSTM_SMEM = 64 * 256 * 2 * (int)sizeof(uint32_t);  // 128 KB dynamic
    cudaFuncSetAttribute(lstm_layer, cudaFuncAttributeMaxDynamicSharedMemorySize, LSTM_SMEM);

    const int M = BB * TT;  // 16384

    cvt_split_kernel<<<512, 256>>>(emb, embb, embs, VV * HH);
    cvt_split_kernel<<<4096, 256>>>(Wih0, wAb, wAs, NG * HH);

    sgemm_sbf16<true, true><<<dim3(NG / 128, M / 128), 256>>>(embb, embs, x, wAb, wAs, b0, gx, M, NG, HH);
    lstm_layer<<<128, 256, LSTM_SMEM>>>(gx, Whh0, h0, c0, y0b, y0s);

    cvt_split_kernel<<<4096, 256>>>(Wih1, wAb, wAs, NG * HH);

    sgemm_sbf16<false, true><<<dim3(NG / 128, M / 128), 256>>>(y0b, y0s, nullptr, wAb, wAs, b1, gx, M, NG, HH);
    lstm_layer<<<128, 256, LSTM_SMEM>>>(gx, Whh1, h0 + BB * HH, c0 + BB * HH, y1b, y1s);

    cvt_split_kernel<<<1024, 256>>>(fcW, wAb, wAs, VV * HH);
    sgemm_sbf16<false, false><<<dim3(VV / 128, M / 128), 256>>>(y1b, y1s, nullptr, wAb, wAs, fcb, out, M, VV, HH);
}

// round 10
// speedup vs baseline: 2.3267x; 1.0260x over previous
#include <cuda_runtime.h>
#include <cuda_bf16.h>
#include <math.h>
#include <stdint.h>

#define BB 64
#define TT 256
#define HH 1024
#define VV 128
#define NG 4096   // 4*H

// ---------------- device scratch (no allocations allowed) ----------------
__device__ float g_gx[BB * TT * NG];              // gate pre-activations, T-major [T][B][4H]
__device__ __nv_bfloat16 g_y0b[BB * TT * HH];     // layer-0 output big
__device__ __nv_bfloat16 g_y0s[BB * TT * HH];     // layer-0 output small
__device__ __nv_bfloat16 g_y1b[BB * TT * HH];     // layer-1 output big
__device__ __nv_bfloat16 g_y1s[BB * TT * HH];     // layer-1 output small
__device__ float g_h[BB * HH];                    // hidden state (fp32)
__device__ float g_c[BB * HH];                    // cell state (fp32)
__device__ float g_part[8 * BB * NG];             // k-split partials
__device__ __nv_bfloat16 g_wAb[NG * HH];          // W_ih / fc_W big
__device__ __nv_bfloat16 g_wAs[NG * HH];          // W_ih / fc_W small
__device__ __nv_bfloat16 g_embb[VV * HH];         // embedding big
__device__ __nv_bfloat16 g_embs[VV * HH];         // embedding small
__device__ unsigned g_barc;                       // arrival counter (self-resetting)
__device__ volatile unsigned g_barsf[16 * 8];     // 16 release flags, 32B-spaced

// ---------------- helpers ----------------
__device__ __forceinline__ void bf16_split(float x, __nv_bfloat16& b, __nv_bfloat16& s) {
    b = __float2bfloat16(x);
    s = __float2bfloat16(x - __bfloat162float(b));
}

__device__ __forceinline__ uint32_t pack_bf2(__nv_bfloat16 lo, __nv_bfloat16 hi) {
    __nv_bfloat162 t = __halves2bfloat162(lo, hi);
    return *reinterpret_cast<uint32_t*>(&t);
}

__device__ __forceinline__ int swz(int k2) {
    return 8 * (k2 & 3) + 16 * ((k2 >> 2) & 1);
}

__device__ __forceinline__ void mma_bf16(float* d, const uint32_t* a, const uint32_t* b) {
    asm volatile(
        "mma.sync.aligned.m16n8k16.row.col.f32.bf16.bf16.f32 "
        "{%0,%1,%2,%3}, {%4,%5,%6,%7}, {%8,%9}, {%0,%1,%2,%3};\n"
        : "+f"(d[0]), "+f"(d[1]), "+f"(d[2]), "+f"(d[3])
        : "r"(a[0]), "r"(a[1]), "r"(a[2]), "r"(a[3]), "r"(b[0]), "r"(b[1]));
}

__device__ __forceinline__ float rcp_approx(float d) {
    float r;
    asm("rcp.approx.f32 %0, %1;" : "=f"(r) : "f"(d));
    return r;
}

__device__ __forceinline__ float fast_sigmoid(float x) {   // 1/(1+e^-x)
    const float a = fmaxf(fminf(-x, 40.f), -40.f);
    return rcp_approx(1.f + __expf(a));
}

__device__ __forceinline__ float fast_tanh(float x) {      // 1 - 2/(e^{2x}+1)
    const float a = fmaxf(fminf(2.f * x, 40.f), -40.f);
    return 1.f - 2.f * rcp_approx(__expf(a) + 1.f);
}

// Fused 3-product 16-k chunk: acc += Ab*Bb + Ab*Bs + As*Bb.
template<int LDA>
__device__ __forceinline__ void mma_chunk3(const uint32_t* Ab32, const uint32_t* As32,
                                           const uint32_t* Bb32, const uint32_t* Bs32,
                                           int ldb, int k2b,
                                           float acc[4][4][4],
                                           int mbase, int nbase, int r, int q)
{
    const int s0 = 8 * r;
    const int s1 = 8 * r + 16;
    const int ra0 = (k2b + r) * LDA;
    const int ra1 = (k2b + r + 4) * LDA;
    const int rb0 = (k2b + r) * ldb;
    const int rb1 = (k2b + r + 4) * ldb;
    uint32_t bb[4][2], bs[4][2];
    #pragma unroll
    for (int nf = 0; nf < 4; nf++) {
        const int cb = nbase + nf * 8 + q;
        bb[nf][0] = Bb32[rb0 + (cb ^ s0)];
        bb[nf][1] = Bb32[rb1 + (cb ^ s1)];
        bs[nf][0] = Bs32[rb0 + (cb ^ s0)];
        bs[nf][1] = Bs32[rb1 + (cb ^ s1)];
    }
    {
        uint32_t ab[4][4];
        #pragma unroll
        for (int mf = 0; mf < 4; mf++) {
            const int c0 = mbase + mf * 16 + q;
            ab[mf][0] = Ab32[ra0 + (c0 ^ s0)];
            ab[mf][1] = Ab32[ra0 + ((c0 + 8) ^ s0)];
            ab[mf][2] = Ab32[ra1 + (c0 ^ s1)];
            ab[mf][3] = Ab32[ra1 + ((c0 + 8) ^ s1)];
        }
        #pragma unroll
        for (int mf = 0; mf < 4; mf++)
            #pragma unroll
            for (int nf = 0; nf < 4; nf++)
                mma_bf16(acc[mf][nf], ab[mf], bb[nf]);
        #pragma unroll
        for (int mf = 0; mf < 4; mf++)
            #pragma unroll
            for (int nf = 0; nf < 4; nf++)
                mma_bf16(acc[mf][nf], ab[mf], bs[nf]);
    }
    {
        uint32_t as[4][4];
        #pragma unroll
        for (int mf = 0; mf < 4; mf++) {
            const int c0 = mbase + mf * 16 + q;
            as[mf][0] = As32[ra0 + (c0 ^ s0)];
            as[mf][1] = As32[ra0 + ((c0 + 8) ^ s0)];
            as[mf][2] = As32[ra1 + (c0 ^ s1)];
            as[mf][3] = As32[ra1 + ((c0 + 8) ^ s1)];
        }
        #pragma unroll
        for (int mf = 0; mf < 4; mf++)
            #pragma unroll
            for (int nf = 0; nf < 4; nf++)
                mma_bf16(acc[mf][nf], as[mf], bb[nf]);
    }
}

// ---------------- grid barrier: single-atomic arrival, 16-line distributed release ----
// Release contention fix: each CTA polls only flag[bid>>3] (<=8 pollers per
// 32B-spaced line) instead of 128 CTAs hammering one word.
__device__ __forceinline__ void grid_bar(unsigned* sense) {
    __syncthreads();
    if (threadIdx.x == 0) {
        unsigned s = *sense ^ 1u;
        *sense = s;
        __threadfence();                       // release
        unsigned prev = atomicAdd(&g_barc, 1u);
        if (prev == gridDim.x - 1) {
            g_barc = 0u;
            __threadfence();
            #pragma unroll
            for (int i = 0; i < 16; i++) g_barsf[i * 8] = s;
        } else {
            volatile unsigned* f = &g_barsf[(blockIdx.x >> 3) * 8];
            while (*f != s) { }
            __threadfence();                   // acquire
        }
    }
    __syncthreads();
}

// ---------------- fp32 -> (bf16 big, bf16 small) split ----------------
__global__ void cvt_split_kernel(const float* __restrict__ src,
                                 __nv_bfloat16* __restrict__ dstb,
                                 __nv_bfloat16* __restrict__ dsts, int n) {
    for (int i = blockIdx.x * blockDim.x + threadIdx.x; i < n; i += gridDim.x * blockDim.x) {
        __nv_bfloat16 b, s;
        bf16_split(src[i], b, s);
        dstb[i] = b;
        dsts[i] = s;
    }
}

// ---------------- split-bf16 SGEMM (double-buffered, 2 CTAs/SM): C = A @ W^T + bias ----------------
template <bool GATHER, bool TMAJOR>
__global__ __launch_bounds__(256, 2)
void sgemm_sbf16(const __nv_bfloat16* __restrict__ Ab, const __nv_bfloat16* __restrict__ As_,
                 const int* __restrict__ tok,
                 const __nv_bfloat16* __restrict__ Wb, const __nv_bfloat16* __restrict__ Ws_,
                 const float* __restrict__ bias,
                 float* __restrict__ C, int M, int N, int K)
{
    __shared__ uint32_t Atb[2][8 * 128];
    __shared__ uint32_t Ats[2][8 * 128];
    __shared__ uint32_t Btb[2][8 * 128];
    __shared__ uint32_t Bts[2][8 * 128];

    const int m0 = blockIdx.y * 128;
    const int n0 = blockIdx.x * 128;
    const int tid = threadIdx.x;
    const int warp = tid >> 5;
    const int lane = tid & 31;
    const int r = lane & 3;
    const int q = lane >> 2;
    const int mbase = (warp >> 2) * 64;
    const int nbase = (warp & 3) * 32;

    const int lrow = tid >> 1;          // 0..127
    const int lq   = (tid & 1) * 8;     // 0 or 8 (k offset)
    const int k2q  = lq >> 1;           // 0 or 4

    size_t aoff;
    if (GATHER) aoff = (size_t)tok[m0 + lrow] * K;
    else        aoff = (size_t)(m0 + lrow) * K;
    const __nv_bfloat16* arb = Ab  + aoff + lq;
    const __nv_bfloat16* ars = As_ + aoff + lq;
    const __nv_bfloat16* wrb = Wb  + (size_t)(n0 + lrow) * K + lq;
    const __nv_bfloat16* wrs = Ws_ + (size_t)(n0 + lrow) * K + lq;

    float acc[4][4][4];
    #pragma unroll
    for (int mf = 0; mf < 4; mf++)
        #pragma unroll
        for (int nf = 0; nf < 4; nf++)
            #pragma unroll
            for (int i = 0; i < 4; i++) acc[mf][nf][i] = 0.f;

    uint4 pab = *(const uint4*)(arb);
    uint4 pas = *(const uint4*)(ars);
    uint4 pwb = *(const uint4*)(wrb);
    uint4 pws = *(const uint4*)(wrs);

    const int niter = K / 16;
    for (int it = 0; it < niter; it++) {
        const int buf = it & 1;
        {
            const uint32_t ab[4] = {pab.x, pab.y, pab.z, pab.w};
            const uint32_t as[4] = {pas.x, pas.y, pas.z, pas.w};
            const uint32_t wb[4] = {pwb.x, pwb.y, pwb.z, pwb.w};
            const uint32_t ws[4] = {pws.x, pws.y, pws.z, pws.w};
            #pragma unroll
            for (int j2 = 0; j2 < 4; j2++) {
                const int k2 = k2q + j2;
                const int idx = k2 * 128 + (lrow ^ swz(k2));
                Atb[buf][idx] = ab[j2];
                Ats[buf][idx] = as[j2];
                Btb[buf][idx] = wb[j2];
                Bts[buf][idx] = ws[j2];
            }
        }
        if (it + 1 < niter) {
            const int k0 = (it + 1) * 16;
            pab = *(const uint4*)(arb + k0);
            pas = *(const uint4*)(ars + k0);
            pwb = *(const uint4*)(wrb + k0);
            pws = *(const uint4*)(wrs + k0);
        }
        __syncthreads();
        mma_chunk3<128>(Atb[buf], Ats[buf], Btb[buf], Bts[buf], 128, 0,
                        acc, mbase, nbase, r, q);
    }

    #pragma unroll
    for (int nf = 0; nf < 4; nf++) {
        const int n = n0 + nbase + nf * 8 + 2 * r;
        const float b0v = bias[n];
        const float b1v = bias[n + 1];
        #pragma unroll
        for (int mf = 0; mf < 4; mf++) {
            const int m = m0 + mbase + mf * 16 + q;
            size_t row0, row1;
            if (TMAJOR) {
                row0 = (size_t)((m % TT) * BB + m / TT);
                const int m8 = m + 8;
                row1 = (size_t)((m8 % TT) * BB + m8 / TT);
            } else {
                row0 = (size_t)m;
                row1 = (size_t)(m + 8);
            }
            float2 o0 = {acc[mf][nf][0] + b0v, acc[mf][nf][1] + b1v};
            float2 o1 = {acc[mf][nf][2] + b0v, acc[mf][nf][3] + b1v};
            *(float2*)(C + row0 * N + n) = o0;
            *(float2*)(C + row1 * N + n) = o1;
        }
    }
}

// ---------------- persistent LSTM layer kernel ----------------
// grid = 128 CTAs (16 col tiles x 8 k-splits), 256 threads. W stationary in smem.
__global__ __launch_bounds__(256, 1)
void lstm_layer(const float* __restrict__ gx, const float* __restrict__ Whh,
                const float* __restrict__ h0, const float* __restrict__ c0,
                __nv_bfloat16* __restrict__ yb, __nv_bfloat16* __restrict__ ys)
{
    extern __shared__ uint32_t dynsm[];
    uint32_t* Wb_sm = dynsm;              // [64 k2][256]
    uint32_t* Ws_sm = dynsm + 64 * 256;
    __shared__ uint32_t hsb[64 * 64];     // [64 k2][64 b]
    __shared__ uint32_t hss[64 * 64];

    const int tid = threadIdx.x;
    const int bid = blockIdx.x;       // 0..127
    const int cs  = bid & 15;
    const int ks  = bid >> 4;
    const int col0 = cs * 256;
    const int gtid = bid * 256 + tid;

    const int warp = tid >> 5;
    const int lane = tid & 31;
    const int r = lane & 3;
    const int q = lane >> 2;
    const int nbase = warp * 32;

    unsigned sense = g_barsf[(bid >> 3) * 8];

    // ---- one-time W slice load + split ----
    {
        const float* wsrc = Whh + (size_t)(col0 + tid) * HH + ks * 128;
        #pragma unroll
        for (int g = 0; g < 16; g++) {
            float4 v0 = *(const float4*)(wsrc + 8 * g);
            float4 v1 = *(const float4*)(wsrc + 8 * g + 4);
            const float wv[8] = {v0.x, v0.y, v0.z, v0.w, v1.x, v1.y, v1.z, v1.w};
            #pragma unroll
            for (int j = 0; j < 4; j++) {
                __nv_bfloat16 b0, s0, b1, s1;
                bf16_split(wv[2 * j], b0, s0);
                bf16_split(wv[2 * j + 1], b1, s1);
                const int k2 = 4 * g + j;
                const int idx = k2 * 256 + (tid ^ swz(k2));
                Wb_sm[idx] = pack_bf2(b0, b1);
                Ws_sm[idx] = pack_bf2(s0, s1);
            }
        }
    }

    for (int i = gtid; i < BB * HH; i += 128 * 256) {
        g_h[i] = h0[i];
        g_c[i] = c0[i];
    }
    grid_bar(&sense);

    const int hrow = tid >> 2;              // b 0..63
    const int hq   = (tid & 3) * 4;         // k offset within 16-chunk
    const int hk2  = hq >> 1;               // local k2 offset {0,2,4,6}
    const float* hbase = g_h + (size_t)hrow * HH + ks * 128;

    // phase-B: 2 consecutive j's per thread
    const int pb_b  = gtid >> 9;            // batch 0..63
    const int pb_j  = (gtid & 511) * 2;     // even j 0..1022
    const int cellp = pb_b * 1024 + pb_j;

    for (int t = 0; t < TT; t++) {
        // ---- stage entire h slice (64 b x 128 k), split to bf16, one sync ----
        #pragma unroll
        for (int g8 = 0; g8 < 8; g8++) {
            float4 hv = *(const float4*)(hbase + g8 * 16 + hq);
            __nv_bfloat16 b0, s0v, b1, s1v, b2, s2v, b3, s3v;
            bf16_split(hv.x, b0, s0v);
            bf16_split(hv.y, b1, s1v);
            bf16_split(hv.z, b2, s2v);
            bf16_split(hv.w, b3, s3v);
            const int k2a = g8 * 8 + hk2;
            const int i0 = k2a * 64 + (hrow ^ swz(k2a));
            const int i1 = (k2a + 1) * 64 + (hrow ^ swz(k2a + 1));
            hsb[i0] = pack_bf2(b0, b1);
            hss[i0] = pack_bf2(s0v, s1v);
            hsb[i1] = pack_bf2(b2, b3);
            hss[i1] = pack_bf2(s2v, s3v);
        }
        __syncthreads();

        float acc[4][4][4];
        #pragma unroll
        for (int mf = 0; mf < 4; mf++)
            #pragma unroll
            for (int nf = 0; nf < 4; nf++)
                #pragma unroll
                for (int i = 0; i < 4; i++) acc[mf][nf][i] = 0.f;

        #pragma unroll
        for (int kc = 0; kc < 8; kc++)
            mma_chunk3<64>(hsb, hss, Wb_sm, Ws_sm, 256, kc * 8,
                           acc, 0, nbase, r, q);

        // write partials P[ks][b][col]
        #pragma unroll
        for (int nf = 0; nf < 4; nf++) {
            const int col = col0 + nbase + nf * 8 + 2 * r;
            #pragma unroll
            for (int mf = 0; mf < 4; mf++) {
                const int b = mf * 16 + q;
                float2 o0 = {acc[mf][nf][0], acc[mf][nf][1]};
                float2 o1 = {acc[mf][nf][2], acc[mf][nf][3]};
                *(float2*)(&g_part[((size_t)ks * BB + b) * NG + col])     = o0;
                *(float2*)(&g_part[((size_t)ks * BB + b + 8) * NG + col]) = o1;
            }
        }

        // ---- prefetch gx[t] and c for phase B (independent of partials) ----
        const float* gr = gx + (size_t)t * BB * NG + (size_t)pb_b * NG + pb_j;
        const float2 xg0 = *(const float2*)(gr);
        const float2 xg1 = *(const float2*)(gr + 1024);
        const float2 xg2 = *(const float2*)(gr + 2048);
        const float2 xg3 = *(const float2*)(gr + 3072);
        float2 cv = *(const float2*)(&g_c[cellp]);

        grid_bar(&sense);

        // ---- Phase B: 2 consecutive cells per thread, all 64-bit accesses ----
        {
            float2 gi = xg0, gf = xg1, gg = xg2, go = xg3;
            #pragma unroll
            for (int s = 0; s < 8; s++) {
                const float* pp = &g_part[((size_t)s * BB + pb_b) * NG + pb_j];
                const float2 p0 = *(const float2*)(pp);
                const float2 p1 = *(const float2*)(pp + 1024);
                const float2 p2 = *(const float2*)(pp + 2048);
                const float2 p3 = *(const float2*)(pp + 3072);
                gi.x += p0.x; gi.y += p0.y;
                gf.x += p1.x; gf.y += p1.y;
                gg.x += p2.x; gg.y += p2.y;
                go.x += p3.x; go.y += p3.y;
            }

            const float si0 = fast_sigmoid(gi.x);
            const float si1 = fast_sigmoid(gi.y);
            const float sf0 = fast_sigmoid(gf.x);
            const float sf1 = fast_sigmoid(gf.y);
            const float so0 = fast_sigmoid(go.x);
            const float so1 = fast_sigmoid(go.y);
            cv.x = sf0 * cv.x + si0 * fast_tanh(gg.x);
            cv.y = sf1 * cv.y + si1 * fast_tanh(gg.y);
            const float hv0 = so0 * fast_tanh(cv.x);
            const float hv1 = so1 * fast_tanh(cv.y);
            *(float2*)(&g_c[cellp]) = cv;
            float2 hw = {hv0, hv1};
            *(float2*)(&g_h[cellp]) = hw;

            __nv_bfloat16 hb0, hs0, hb1, hs1;
            bf16_split(hv0, hb0, hs0);
            bf16_split(hv1, hb1, hs1);
            const size_t yi = ((size_t)pb_b * TT + t) * HH + pb_j;
            *(uint32_t*)(yb + yi) = pack_bf2(hb0, hb1);
            *(uint32_t*)(ys + yi) = pack_bf2(hs0, hs1);
        }
        grid_bar(&sense);
    }
}

// ---------------- launch ----------------
extern "C" void kernel_launch(void* const* d_in, const int* in_sizes, int n_in,
                              void* d_out, int out_size)
{
    const int*   x    = (const int*)  d_in[0];
    const float* emb  = (const float*)d_in[1];
    const float* Wih0 = (const float*)d_in[2];
    const float* Whh0 = (const float*)d_in[3];
    const float* b0   = (const float*)d_in[4];
    const float* Wih1 = (const float*)d_in[5];
    const float* Whh1 = (const float*)d_in[6];
    const float* b1   = (const float*)d_in[7];
    const float* fcW  = (const float*)d_in[8];
    const float* fcb  = (const float*)d_in[9];
    const float* h0   = (const float*)d_in[10];
    const float* c0   = (const float*)d_in[11];
    float* out = (float*)d_out;

    float *gx;
    __nv_bfloat16 *y0b, *y0s, *y1b, *y1s, *wAb, *wAs, *embb, *embs;
    cudaGetSymbolAddress((void**)&gx,   g_gx);
    cudaGetSymbolAddress((void**)&y0b,  g_y0b);
    cudaGetSymbolAddress((void**)&y0s,  g_y0s);
    cudaGetSymbolAddress((void**)&y1b,  g_y1b);
    cudaGetSymbolAddress((void**)&y1s,  g_y1s);
    cudaGetSymbolAddress((void**)&wAb,  g_wAb);
    cudaGetSymbolAddress((void**)&wAs,  g_wAs);
    cudaGetSymbolAddress((void**)&embb, g_embb);
    cudaGetSymbolAddress((void**)&embs, g_embs);

    const int LSTM_SMEM = 64 * 256 * 2 * (int)sizeof(uint32_t);  // 128 KB dynamic
    cudaFuncSetAttribute(lstm_layer, cudaFuncAttributeMaxDynamicSharedMemorySize, LSTM_SMEM);

    const int M = BB * TT;  // 16384

    cvt_split_kernel<<<512, 256>>>(emb, embb, embs, VV * HH);
    cvt_split_kernel<<<4096, 256>>>(Wih0, wAb, wAs, NG * HH);

    sgemm_sbf16<true, true><<<dim3(NG / 128, M / 128), 256>>>(embb, embs, x, wAb, wAs, b0, gx, M, NG, HH);
    lstm_layer<<<128, 256, LSTM_SMEM>>>(gx, Whh0, h0, c0, y0b, y0s);

    cvt_split_kernel<<<4096, 256>>>(Wih1, wAb, wAs, NG * HH);

    sgemm_sbf16<false, true><<<dim3(NG / 128, M / 128), 256>>>(y0b, y0s, nullptr, wAb, wAs, b1, gx, M, NG, HH);
    lstm_layer<<<128, 256, LSTM_SMEM>>>(gx, Whh1, h0 + BB * HH, c0 + BB * HH, y1b, y1s);

    cvt_split_kernel<<<1024, 256>>>(fcW, wAb, wAs, VV * HH);
    sgemm_sbf16<false, false><<<dim3(VV / 128, M / 128), 256>>>(y1b, y1s, nullptr, wAb, wAs, fcb, out, M, VV, HH);
}

// round 11
// speedup vs baseline: 2.4446x; 1.0507x over previous
#include <cuda_runtime.h>
#include <cuda_bf16.h>
#include <math.h>
#include <stdint.h>

#define BB 64
#define TT 256
#define HH 1024
#define VV 128
#define NG 4096   // 4*H

// ---------------- device scratch (no allocations allowed) ----------------
__device__ float g_gx[BB * TT * NG];              // gate pre-activations, T-major [T][B][4H]
__device__ __nv_bfloat16 g_y0b[BB * TT * HH];     // layer-0 output big
__device__ __nv_bfloat16 g_y0s[BB * TT * HH];     // layer-0 output small
__device__ __nv_bfloat16 g_y1b[BB * TT * HH];     // layer-1 output big
__device__ __nv_bfloat16 g_y1s[BB * TT * HH];     // layer-1 output small
__device__ float g_hbuf[2][BB * HH];              // hidden state double buffer (fp32)
__device__ float g_c[BB * HH];                    // cell state (CTA-private cells)
__device__ float g_part[2][8 * BB * NG];          // k-split partials, double-buffered
__device__ __nv_bfloat16 g_wAb[NG * HH];          // W_ih / fc_W big
__device__ __nv_bfloat16 g_wAs[NG * HH];          // W_ih / fc_W small
__device__ __nv_bfloat16 g_embb[VV * HH];         // embedding big
__device__ __nv_bfloat16 g_embs[VV * HH];         // embedding small
__device__ unsigned g_barc;                       // global barrier arrival counter
__device__ volatile unsigned g_barsf[16 * 8];     // 16 release flags, 32B-spaced
__device__ volatile unsigned g_cnt2[8 * 8];       // per-ks-group h-ready counters (monotonic)

// ---------------- helpers ----------------
__device__ __forceinline__ void bf16_split(float x, __nv_bfloat16& b, __nv_bfloat16& s) {
    b = __float2bfloat16(x);
    s = __float2bfloat16(x - __bfloat162float(b));
}

__device__ __forceinline__ uint32_t pack_bf2(__nv_bfloat16 lo, __nv_bfloat16 hi) {
    __nv_bfloat162 t = __halves2bfloat162(lo, hi);
    return *reinterpret_cast<uint32_t*>(&t);
}

__device__ __forceinline__ int swz(int k2) {
    return 8 * (k2 & 3) + 16 * ((k2 >> 2) & 1);
}

__device__ __forceinline__ void mma_bf16(float* d, const uint32_t* a, const uint32_t* b) {
    asm volatile(
        "mma.sync.aligned.m16n8k16.row.col.f32.bf16.bf16.f32 "
        "{%0,%1,%2,%3}, {%4,%5,%6,%7}, {%8,%9}, {%0,%1,%2,%3};\n"
        : "+f"(d[0]), "+f"(d[1]), "+f"(d[2]), "+f"(d[3])
        : "r"(a[0]), "r"(a[1]), "r"(a[2]), "r"(a[3]), "r"(b[0]), "r"(b[1]));
}

__device__ __forceinline__ float rcp_approx(float d) {
    float r;
    asm("rcp.approx.f32 %0, %1;" : "=f"(r) : "f"(d));
    return r;
}

__device__ __forceinline__ float fast_sigmoid(float x) {   // 1/(1+e^-x)
    const float a = fmaxf(fminf(-x, 40.f), -40.f);
    return rcp_approx(1.f + __expf(a));
}

__device__ __forceinline__ float fast_tanh(float x) {      // 1 - 2/(e^{2x}+1)
    const float a = fmaxf(fminf(2.f * x, 40.f), -40.f);
    return 1.f - 2.f * rcp_approx(__expf(a) + 1.f);
}

// Fused 3-product 16-k chunk: acc += Ab*Bb + Ab*Bs + As*Bb.
template<int LDA>
__device__ __forceinline__ void mma_chunk3(const uint32_t* Ab32, const uint32_t* As32,
                                           const uint32_t* Bb32, const uint32_t* Bs32,
                                           int ldb, int k2b,
                                           float acc[4][4][4],
                                           int mbase, int nbase, int r, int q)
{
    const int s0 = 8 * r;
    const int s1 = 8 * r + 16;
    const int ra0 = (k2b + r) * LDA;
    const int ra1 = (k2b + r + 4) * LDA;
    const int rb0 = (k2b + r) * ldb;
    const int rb1 = (k2b + r + 4) * ldb;
    uint32_t bb[4][2], bs[4][2];
    #pragma unroll
    for (int nf = 0; nf < 4; nf++) {
        const int cb = nbase + nf * 8 + q;
        bb[nf][0] = Bb32[rb0 + (cb ^ s0)];
        bb[nf][1] = Bb32[rb1 + (cb ^ s1)];
        bs[nf][0] = Bs32[rb0 + (cb ^ s0)];
        bs[nf][1] = Bs32[rb1 + (cb ^ s1)];
    }
    {
        uint32_t ab[4][4];
        #pragma unroll
        for (int mf = 0; mf < 4; mf++) {
            const int c0 = mbase + mf * 16 + q;
            ab[mf][0] = Ab32[ra0 + (c0 ^ s0)];
            ab[mf][1] = Ab32[ra0 + ((c0 + 8) ^ s0)];
            ab[mf][2] = Ab32[ra1 + (c0 ^ s1)];
            ab[mf][3] = Ab32[ra1 + ((c0 + 8) ^ s1)];
        }
        #pragma unroll
        for (int mf = 0; mf < 4; mf++)
            #pragma unroll
            for (int nf = 0; nf < 4; nf++)
                mma_bf16(acc[mf][nf], ab[mf], bb[nf]);
        #pragma unroll
        for (int mf = 0; mf < 4; mf++)
            #pragma unroll
            for (int nf = 0; nf < 4; nf++)
                mma_bf16(acc[mf][nf], ab[mf], bs[nf]);
    }
    {
        uint32_t as[4][4];
        #pragma unroll
        for (int mf = 0; mf < 4; mf++) {
            const int c0 = mbase + mf * 16 + q;
            as[mf][0] = As32[ra0 + (c0 ^ s0)];
            as[mf][1] = As32[ra0 + ((c0 + 8) ^ s0)];
            as[mf][2] = As32[ra1 + (c0 ^ s1)];
            as[mf][3] = As32[ra1 + ((c0 + 8) ^ s1)];
        }
        #pragma unroll
        for (int mf = 0; mf < 4; mf++)
            #pragma unroll
            for (int nf = 0; nf < 4; nf++)
                mma_bf16(acc[mf][nf], as[mf], bb[nf]);
    }
}

// ---------------- global barrier: single-atomic arrival, distributed release ----
__device__ __forceinline__ void grid_bar(unsigned* sense) {
    __syncthreads();
    if (threadIdx.x == 0) {
        unsigned s = *sense ^ 1u;
        *sense = s;
        __threadfence();                       // release
        unsigned prev = atomicAdd(&g_barc, 1u);
        if (prev == gridDim.x - 1) {
            g_barc = 0u;
            __threadfence();
            #pragma unroll
            for (int i = 0; i < 16; i++) g_barsf[i * 8] = s;
        } else {
            volatile unsigned* f = &g_barsf[(blockIdx.x >> 3) * 8];
            while (*f != s) { }
            __threadfence();                   // acquire
        }
    }
    __syncthreads();
}

// ---------------- fp32 -> (bf16 big, bf16 small) split ----------------
__global__ void cvt_split_kernel(const float* __restrict__ src,
                                 __nv_bfloat16* __restrict__ dstb,
                                 __nv_bfloat16* __restrict__ dsts, int n) {
    for (int i = blockIdx.x * blockDim.x + threadIdx.x; i < n; i += gridDim.x * blockDim.x) {
        __nv_bfloat16 b, s;
        bf16_split(src[i], b, s);
        dstb[i] = b;
        dsts[i] = s;
    }
}

// ---------------- split-bf16 SGEMM (double-buffered, 2 CTAs/SM): C = A @ W^T + bias ----------------
template <bool GATHER, bool TMAJOR>
__global__ __launch_bounds__(256, 2)
void sgemm_sbf16(const __nv_bfloat16* __restrict__ Ab, const __nv_bfloat16* __restrict__ As_,
                 const int* __restrict__ tok,
                 const __nv_bfloat16* __restrict__ Wb, const __nv_bfloat16* __restrict__ Ws_,
                 const float* __restrict__ bias,
                 float* __restrict__ C, int M, int N, int K)
{
    __shared__ uint32_t Atb[2][8 * 128];
    __shared__ uint32_t Ats[2][8 * 128];
    __shared__ uint32_t Btb[2][8 * 128];
    __shared__ uint32_t Bts[2][8 * 128];

    const int m0 = blockIdx.y * 128;
    const int n0 = blockIdx.x * 128;
    const int tid = threadIdx.x;
    const int warp = tid >> 5;
    const int lane = tid & 31;
    const int r = lane & 3;
    const int q = lane >> 2;
    const int mbase = (warp >> 2) * 64;
    const int nbase = (warp & 3) * 32;

    const int lrow = tid >> 1;          // 0..127
    const int lq   = (tid & 1) * 8;     // 0 or 8 (k offset)
    const int k2q  = lq >> 1;           // 0 or 4

    size_t aoff;
    if (GATHER) aoff = (size_t)tok[m0 + lrow] * K;
    else        aoff = (size_t)(m0 + lrow) * K;
    const __nv_bfloat16* arb = Ab  + aoff + lq;
    const __nv_bfloat16* ars = As_ + aoff + lq;
    const __nv_bfloat16* wrb = Wb  + (size_t)(n0 + lrow) * K + lq;
    const __nv_bfloat16* wrs = Ws_ + (size_t)(n0 + lrow) * K + lq;

    float acc[4][4][4];
    #pragma unroll
    for (int mf = 0; mf < 4; mf++)
        #pragma unroll
        for (int nf = 0; nf < 4; nf++)
            #pragma unroll
            for (int i = 0; i < 4; i++) acc[mf][nf][i] = 0.f;

    uint4 pab = *(const uint4*)(arb);
    uint4 pas = *(const uint4*)(ars);
    uint4 pwb = *(const uint4*)(wrb);
    uint4 pws = *(const uint4*)(wrs);

    const int niter = K / 16;
    for (int it = 0; it < niter; it++) {
        const int buf = it & 1;
        {
            const uint32_t ab[4] = {pab.x, pab.y, pab.z, pab.w};
            const uint32_t as[4] = {pas.x, pas.y, pas.z, pas.w};
            const uint32_t wb[4] = {pwb.x, pwb.y, pwb.z, pwb.w};
            const uint32_t ws[4] = {pws.x, pws.y, pws.z, pws.w};
            #pragma unroll
            for (int j2 = 0; j2 < 4; j2++) {
                const int k2 = k2q + j2;
                const int idx = k2 * 128 + (lrow ^ swz(k2));
                Atb[buf][idx] = ab[j2];
                Ats[buf][idx] = as[j2];
                Btb[buf][idx] = wb[j2];
                Bts[buf][idx] = ws[j2];
            }
        }
        if (it + 1 < niter) {
            const int k0 = (it + 1) * 16;
            pab = *(const uint4*)(arb + k0);
            pas = *(const uint4*)(ars + k0);
            pwb = *(const uint4*)(wrb + k0);
            pws = *(const uint4*)(wrs + k0);
        }
        __syncthreads();
        mma_chunk3<128>(Atb[buf], Ats[buf], Btb[buf], Bts[buf], 128, 0,
                        acc, mbase, nbase, r, q);
    }

    #pragma unroll
    for (int nf = 0; nf < 4; nf++) {
        const int n = n0 + nbase + nf * 8 + 2 * r;
        const float b0v = bias[n];
        const float b1v = bias[n + 1];
        #pragma unroll
        for (int mf = 0; mf < 4; mf++) {
            const int m = m0 + mbase + mf * 16 + q;
            size_t row0, row1;
            if (TMAJOR) {
                row0 = (size_t)((m % TT) * BB + m / TT);
                const int m8 = m + 8;
                row1 = (size_t)((m8 % TT) * BB + m8 / TT);
            } else {
                row0 = (size_t)m;
                row1 = (size_t)(m + 8);
            }
            float2 o0 = {acc[mf][nf][0] + b0v, acc[mf][nf][1] + b1v};
            float2 o1 = {acc[mf][nf][2] + b0v, acc[mf][nf][3] + b1v};
            *(float2*)(C + row0 * N + n) = o0;
            *(float2*)(C + row1 * N + n) = o1;
        }
    }
}

// ---------------- persistent LSTM layer kernel ----------------
// grid = 128 CTAs (16 col tiles x 8 k-splits), 256 threads. W stationary in smem.
// One GLOBAL barrier per step (partials ready); h-readiness via per-ks-group
// monotonic counters (16 producers each). Partials + h double-buffered by t parity.
__global__ __launch_bounds__(256, 1)
void lstm_layer(const float* __restrict__ gx, const float* __restrict__ Whh,
                const float* __restrict__ h0, const float* __restrict__ c0,
                __nv_bfloat16* __restrict__ yb, __nv_bfloat16* __restrict__ ys)
{
    extern __shared__ uint32_t dynsm[];
    uint32_t* Wb_sm = dynsm;              // [64 k2][256]
    uint32_t* Ws_sm = dynsm + 64 * 256;
    __shared__ uint32_t hsb[64 * 64];     // [64 k2][64 b]
    __shared__ uint32_t hss[64 * 64];

    const int tid = threadIdx.x;
    const int bid = blockIdx.x;       // 0..127
    const int cs  = bid & 15;
    const int ks  = bid >> 4;
    const int col0 = cs * 256;
    const int gtid = bid * 256 + tid;

    const int warp = tid >> 5;
    const int lane = tid & 31;
    const int r = lane & 3;
    const int q = lane >> 2;
    const int nbase = warp * 32;

    unsigned sense = g_barsf[(bid >> 3) * 8];

    // ---- one-time W slice load + split ----
    {
        const float* wsrc = Whh + (size_t)(col0 + tid) * HH + ks * 128;
        #pragma unroll
        for (int g = 0; g < 16; g++) {
            float4 v0 = *(const float4*)(wsrc + 8 * g);
            float4 v1 = *(const float4*)(wsrc + 8 * g + 4);
            const float wv[8] = {v0.x, v0.y, v0.z, v0.w, v1.x, v1.y, v1.z, v1.w};
            #pragma unroll
            for (int j = 0; j < 4; j++) {
                __nv_bfloat16 b0, s0, b1, s1;
                bf16_split(wv[2 * j], b0, s0);
                bf16_split(wv[2 * j + 1], b1, s1);
                const int k2 = 4 * g + j;
                const int idx = k2 * 256 + (tid ^ swz(k2));
                Wb_sm[idx] = pack_bf2(b0, b1);
                Ws_sm[idx] = pack_bf2(s0, s1);
            }
        }
    }

    // init state: hbuf[0] = h0, c = c0; reset group counters
    for (int i = gtid; i < BB * HH; i += 128 * 256) {
        g_hbuf[0][i] = h0[i];
        g_c[i] = c0[i];
    }
    if (tid == 0 && bid < 8) *((volatile unsigned*)&g_cnt2[bid * 8]) = 0u;
    grid_bar(&sense);

    const int hrow = tid >> 2;              // b 0..63
    const int hq   = (tid & 3) * 4;         // k offset within 16-chunk
    const int hk2  = hq >> 1;               // local k2 offset {0,2,4,6}

    // phase-B ks-local ownership: b in [4cs,4cs+4), j in [128ks,128ks+128), 2 j per thread
    const int pb_b  = 4 * cs + (tid >> 6);
    const int pb_j  = 128 * ks + (tid & 63) * 2;
    const int cellp = pb_b * 1024 + pb_j;

    for (int t = 0; t < TT; t++) {
        const int par = t & 1;
        float* partp = g_part[par];

        // ---- group wait: own ks-group's h values for this step are ready ----
        if (t > 0) {
            if (tid == 0) {
                const unsigned need = 16u * (unsigned)t;
                volatile unsigned* cp = &g_cnt2[ks * 8];
                while (*cp < need) { }
                __threadfence();               // acquire
            }
            __syncthreads();
        }

        // ---- stage h slice (64 b x 128 k) from hbuf[par], split, one sync ----
        const float* hbase = g_hbuf[par] + (size_t)hrow * HH + ks * 128;
        #pragma unroll
        for (int g8 = 0; g8 < 8; g8++) {
            float4 hv = *(const float4*)(hbase + g8 * 16 + hq);
            __nv_bfloat16 b0, s0v, b1, s1v, b2, s2v, b3, s3v;
            bf16_split(hv.x, b0, s0v);
            bf16_split(hv.y, b1, s1v);
            bf16_split(hv.z, b2, s2v);
            bf16_split(hv.w, b3, s3v);
            const int k2a = g8 * 8 + hk2;
            const int i0 = k2a * 64 + (hrow ^ swz(k2a));
            const int i1 = (k2a + 1) * 64 + (hrow ^ swz(k2a + 1));
            hsb[i0] = pack_bf2(b0, b1);
            hss[i0] = pack_bf2(s0v, s1v);
            hsb[i1] = pack_bf2(b2, b3);
            hss[i1] = pack_bf2(s2v, s3v);
        }
        __syncthreads();

        float acc[4][4][4];
        #pragma unroll
        for (int mf = 0; mf < 4; mf++)
            #pragma unroll
            for (int nf = 0; nf < 4; nf++)
                #pragma unroll
                for (int i = 0; i < 4; i++) acc[mf][nf][i] = 0.f;

        #pragma unroll
        for (int kc = 0; kc < 8; kc++)
            mma_chunk3<64>(hsb, hss, Wb_sm, Ws_sm, 256, kc * 8,
                           acc, 0, nbase, r, q);

        // write partials P[par][ks][b][col]
        #pragma unroll
        for (int nf = 0; nf < 4; nf++) {
            const int col = col0 + nbase + nf * 8 + 2 * r;
            #pragma unroll
            for (int mf = 0; mf < 4; mf++) {
                const int b = mf * 16 + q;
                float2 o0 = {acc[mf][nf][0], acc[mf][nf][1]};
                float2 o1 = {acc[mf][nf][2], acc[mf][nf][3]};
                *(float2*)(&partp[((size_t)ks * BB + b) * NG + col])     = o0;
                *(float2*)(&partp[((size_t)ks * BB + b + 8) * NG + col]) = o1;
            }
        }

        // ---- prefetch gx[t] and c (c cells are CTA-private; program-order safe) ----
        const float* gr = gx + (size_t)t * BB * NG + (size_t)pb_b * NG + pb_j;
        const float2 xg0 = *(const float2*)(gr);
        const float2 xg1 = *(const float2*)(gr + 1024);
        const float2 xg2 = *(const float2*)(gr + 2048);
        const float2 xg3 = *(const float2*)(gr + 3072);
        float2 cv = *(const float2*)(&g_c[cellp]);

        grid_bar(&sense);   // global: all partials for step t ready

        // ---- Phase B: own cells, read partials[par], write hbuf[par^1] ----
        {
            float2 gi = xg0, gf = xg1, gg = xg2, go = xg3;
            #pragma unroll
            for (int s = 0; s < 8; s++) {
                const float* pp = &partp[((size_t)s * BB + pb_b) * NG + pb_j];
                const float2 p0 = *(const float2*)(pp);
                const float2 p1 = *(const float2*)(pp + 1024);
                const float2 p2 = *(const float2*)(pp + 2048);
                const float2 p3 = *(const float2*)(pp + 3072);
                gi.x += p0.x; gi.y += p0.y;
                gf.x += p1.x; gf.y += p1.y;
                gg.x += p2.x; gg.y += p2.y;
                go.x += p3.x; go.y += p3.y;
            }

            const float si0 = fast_sigmoid(gi.x);
            const float si1 = fast_sigmoid(gi.y);
            const float sf0 = fast_sigmoid(gf.x);
            const float sf1 = fast_sigmoid(gf.y);
            const float so0 = fast_sigmoid(go.x);
            const float so1 = fast_sigmoid(go.y);
            cv.x = sf0 * cv.x + si0 * fast_tanh(gg.x);
            cv.y = sf1 * cv.y + si1 * fast_tanh(gg.y);
            const float hv0 = so0 * fast_tanh(cv.x);
            const float hv1 = so1 * fast_tanh(cv.y);
            *(float2*)(&g_c[cellp]) = cv;
            float2 hw = {hv0, hv1};
            *(float2*)(&g_hbuf[par ^ 1][cellp]) = hw;

            __nv_bfloat16 hb0, hs0, hb1, hs1;
            bf16_split(hv0, hb0, hs0);
            bf16_split(hv1, hb1, hs1);
            const size_t yi = ((size_t)pb_b * TT + t) * HH + pb_j;
            *(uint32_t*)(yb + yi) = pack_bf2(hb0, hb1);
            *(uint32_t*)(ys + yi) = pack_bf2(hs0, hs1);
        }

        // ---- signal own group's h contribution for step t+1 ----
        __syncthreads();
        if (tid == 0) {
            __threadfence();                   // release h writes
            atomicAdd((unsigned*)&g_cnt2[ks * 8], 1u);
        }
    }
}

// ---------------- launch ----------------
extern "C" void kernel_launch(void* const* d_in, const int* in_sizes, int n_in,
                              void* d_out, int out_size)
{
    const int*   x    = (const int*)  d_in[0];
    const float* emb  = (const float*)d_in[1];
    const float* Wih0 = (const float*)d_in[2];
    const float* Whh0 = (const float*)d_in[3];
    const float* b0   = (const float*)d_in[4];
    const float* Wih1 = (const float*)d_in[5];
    const float* Whh1 = (const float*)d_in[6];
    const float* b1   = (const float*)d_in[7];
    const float* fcW  = (const float*)d_in[8];
    const float* fcb  = (const float*)d_in[9];
    const float* h0   = (const float*)d_in[10];
    const float* c0   = (const float*)d_in[11];
    float* out = (float*)d_out;

    float *gx;
    __nv_bfloat16 *y0b, *y0s, *y1b, *y1s, *wAb, *wAs, *embb, *embs;
    cudaGetSymbolAddress((void**)&gx,   g_gx);
    cudaGetSymbolAddress((void**)&y0b,  g_y0b);
    cudaGetSymbolAddress((void**)&y0s,  g_y0s);
    cudaGetSymbolAddress((void**)&y1b,  g_y1b);
    cudaGetSymbolAddress((void**)&y1s,  g_y1s);
    cudaGetSymbolAddress((void**)&wAb,  g_wAb);
    cudaGetSymbolAddress((void**)&wAs,  g_wAs);
    cudaGetSymbolAddress((void**)&embb, g_embb);
    cudaGetSymbolAddress((void**)&embs, g_embs);

    const int LSTM_SMEM = 64 * 256 * 2 * (int)sizeof(uint32_t);  // 128 KB dynamic
    cudaFuncSetAttribute(lstm_layer, cudaFuncAttributeMaxDynamicSharedMemorySize, LSTM_SMEM);

    const int M = BB * TT;  // 16384

    cvt_split_kernel<<<512, 256>>>(emb, embb, embs, VV * HH);
    cvt_split_kernel<<<4096, 256>>>(Wih0, wAb, wAs, NG * HH);

    sgemm_sbf16<true, true><<<dim3(NG / 128, M / 128), 256>>>(embb, embs, x, wAb, wAs, b0, gx, M, NG, HH);
    lstm_layer<<<128, 256, LSTM_SMEM>>>(gx, Whh0, h0, c0, y0b, y0s);

    cvt_split_kernel<<<4096, 256>>>(Wih1, wAb, wAs, NG * HH);

    sgemm_sbf16<false, true><<<dim3(NG / 128, M / 128), 256>>>(y0b, y0s, nullptr, wAb, wAs, b1, gx, M, NG, HH);
    lstm_layer<<<128, 256, LSTM_SMEM>>>(gx, Whh1, h0 + BB * HH, c0 + BB * HH, y1b, y1s);

    cvt_split_kernel<<<1024, 256>>>(fcW, wAb, wAs, VV * HH);
    sgemm_sbf16<false, false><<<dim3(VV / 128, M / 128), 256>>>(y1b, y1s, nullptr, wAb, wAs, fcb, out, M, VV, HH);
}

// round 12
// speedup vs baseline: 2.4843x; 1.0162x over previous
#include <cuda_runtime.h>
#include <cuda_bf16.h>
#include <math.h>
#include <stdint.h>

#define BB 64
#define TT 256
#define HH 1024
#define VV 128
#define NG 4096   // 4*H

// ---------------- device scratch (no allocations allowed) ----------------
__device__ float g_gx[BB * TT * NG];              // gate pre-activations, T-major [T][B][4H]
__device__ __nv_bfloat16 g_y0b[BB * TT * HH];     // layer-0 output big
__device__ __nv_bfloat16 g_y0s[BB * TT * HH];     // layer-0 output small
__device__ __nv_bfloat16 g_y1b[BB * TT * HH];     // layer-1 output big
__device__ __nv_bfloat16 g_y1s[BB * TT * HH];     // layer-1 output small
__device__ float g_hbuf[2][BB * HH];              // hidden state double buffer (fp32)
__device__ float g_c[BB * HH];                    // cell state (CTA-private cells)
__device__ float g_part[2][8 * BB * NG];          // k-split partials, double-buffered
__device__ __nv_bfloat16 g_wAb[NG * HH];          // W_ih / fc_W big
__device__ __nv_bfloat16 g_wAs[NG * HH];          // W_ih / fc_W small
__device__ __nv_bfloat16 g_embb[VV * HH];         // embedding big
__device__ __nv_bfloat16 g_embs[VV * HH];         // embedding small
__device__ unsigned g_barc;                       // global barrier arrival counter (init only)
__device__ volatile unsigned g_barsf[16 * 8];     // 16 release flags, 32B-spaced
__device__ volatile unsigned g_cnt2[8 * 8];       // per-ks-group h-ready counters (monotonic)
__device__ volatile unsigned g_cntcs[16 * 8];     // per-col-tile partials-ready counters (monotonic)

// ---------------- helpers ----------------
__device__ __forceinline__ void bf16_split(float x, __nv_bfloat16& b, __nv_bfloat16& s) {
    b = __float2bfloat16(x);
    s = __float2bfloat16(x - __bfloat162float(b));
}

__device__ __forceinline__ uint32_t pack_bf2(__nv_bfloat16 lo, __nv_bfloat16 hi) {
    __nv_bfloat162 t = __halves2bfloat162(lo, hi);
    return *reinterpret_cast<uint32_t*>(&t);
}

__device__ __forceinline__ int swz(int k2) {
    return 8 * (k2 & 3) + 16 * ((k2 >> 2) & 1);
}

__device__ __forceinline__ void mma_bf16(float* d, const uint32_t* a, const uint32_t* b) {
    asm volatile(
        "mma.sync.aligned.m16n8k16.row.col.f32.bf16.bf16.f32 "
        "{%0,%1,%2,%3}, {%4,%5,%6,%7}, {%8,%9}, {%0,%1,%2,%3};\n"
        : "+f"(d[0]), "+f"(d[1]), "+f"(d[2]), "+f"(d[3])
        : "r"(a[0]), "r"(a[1]), "r"(a[2]), "r"(a[3]), "r"(b[0]), "r"(b[1]));
}

__device__ __forceinline__ float rcp_approx(float d) {
    float r;
    asm("rcp.approx.f32 %0, %1;" : "=f"(r) : "f"(d));
    return r;
}

__device__ __forceinline__ float fast_sigmoid(float x) {   // 1/(1+e^-x)
    const float a = fmaxf(fminf(-x, 40.f), -40.f);
    return rcp_approx(1.f + __expf(a));
}

__device__ __forceinline__ float fast_tanh(float x) {      // 1 - 2/(e^{2x}+1)
    const float a = fmaxf(fminf(2.f * x, 40.f), -40.f);
    return 1.f - 2.f * rcp_approx(__expf(a) + 1.f);
}

// Fused 3-product 16-k chunk: acc += Ab*Bb + Ab*Bs + As*Bb.
template<int LDA>
__device__ __forceinline__ void mma_chunk3(const uint32_t* Ab32, const uint32_t* As32,
                                           const uint32_t* Bb32, const uint32_t* Bs32,
                                           int ldb, int k2b,
                                           float acc[4][4][4],
                                           int mbase, int nbase, int r, int q)
{
    const int s0 = 8 * r;
    const int s1 = 8 * r + 16;
    const int ra0 = (k2b + r) * LDA;
    const int ra1 = (k2b + r + 4) * LDA;
    const int rb0 = (k2b + r) * ldb;
    const int rb1 = (k2b + r + 4) * ldb;
    uint32_t bb[4][2], bs[4][2];
    #pragma unroll
    for (int nf = 0; nf < 4; nf++) {
        const int cb = nbase + nf * 8 + q;
        bb[nf][0] = Bb32[rb0 + (cb ^ s0)];
        bb[nf][1] = Bb32[rb1 + (cb ^ s1)];
        bs[nf][0] = Bs32[rb0 + (cb ^ s0)];
        bs[nf][1] = Bs32[rb1 + (cb ^ s1)];
    }
    {
        uint32_t ab[4][4];
        #pragma unroll
        for (int mf = 0; mf < 4; mf++) {
            const int c0 = mbase + mf * 16 + q;
            ab[mf][0] = Ab32[ra0 + (c0 ^ s0)];
            ab[mf][1] = Ab32[ra0 + ((c0 + 8) ^ s0)];
            ab[mf][2] = Ab32[ra1 + (c0 ^ s1)];
            ab[mf][3] = Ab32[ra1 + ((c0 + 8) ^ s1)];
        }
        #pragma unroll
        for (int mf = 0; mf < 4; mf++)
            #pragma unroll
            for (int nf = 0; nf < 4; nf++)
                mma_bf16(acc[mf][nf], ab[mf], bb[nf]);
        #pragma unroll
        for (int mf = 0; mf < 4; mf++)
            #pragma unroll
            for (int nf = 0; nf < 4; nf++)
                mma_bf16(acc[mf][nf], ab[mf], bs[nf]);
    }
    {
        uint32_t as[4][4];
        #pragma unroll
        for (int mf = 0; mf < 4; mf++) {
            const int c0 = mbase + mf * 16 + q;
            as[mf][0] = As32[ra0 + (c0 ^ s0)];
            as[mf][1] = As32[ra0 + ((c0 + 8) ^ s0)];
            as[mf][2] = As32[ra1 + (c0 ^ s1)];
            as[mf][3] = As32[ra1 + ((c0 + 8) ^ s1)];
        }
        #pragma unroll
        for (int mf = 0; mf < 4; mf++)
            #pragma unroll
            for (int nf = 0; nf < 4; nf++)
                mma_bf16(acc[mf][nf], as[mf], bb[nf]);
    }
}

// ---------------- global barrier (init only) ----------------
__device__ __forceinline__ void grid_bar(unsigned* sense) {
    __syncthreads();
    if (threadIdx.x == 0) {
        unsigned s = *sense ^ 1u;
        *sense = s;
        __threadfence();                       // release
        unsigned prev = atomicAdd(&g_barc, 1u);
        if (prev == gridDim.x - 1) {
            g_barc = 0u;
            __threadfence();
            #pragma unroll
            for (int i = 0; i < 16; i++) g_barsf[i * 8] = s;
        } else {
            volatile unsigned* f = &g_barsf[(blockIdx.x >> 3) * 8];
            while (*f != s) { }
            __threadfence();                   // acquire
        }
    }
    __syncthreads();
}

// ---------------- fp32 -> (bf16 big, bf16 small) split ----------------
__global__ void cvt_split_kernel(const float* __restrict__ src,
                                 __nv_bfloat16* __restrict__ dstb,
                                 __nv_bfloat16* __restrict__ dsts, int n) {
    for (int i = blockIdx.x * blockDim.x + threadIdx.x; i < n; i += gridDim.x * blockDim.x) {
        __nv_bfloat16 b, s;
        bf16_split(src[i], b, s);
        dstb[i] = b;
        dsts[i] = s;
    }
}

// ---------------- split-bf16 SGEMM (double-buffered, 2 CTAs/SM): C = A @ W^T + bias ----------------
template <bool GATHER, bool TMAJOR>
__global__ __launch_bounds__(256, 2)
void sgemm_sbf16(const __nv_bfloat16* __restrict__ Ab, const __nv_bfloat16* __restrict__ As_,
                 const int* __restrict__ tok,
                 const __nv_bfloat16* __restrict__ Wb, const __nv_bfloat16* __restrict__ Ws_,
                 const float* __restrict__ bias,
                 float* __restrict__ C, int M, int N, int K)
{
    __shared__ uint32_t Atb[2][8 * 128];
    __shared__ uint32_t Ats[2][8 * 128];
    __shared__ uint32_t Btb[2][8 * 128];
    __shared__ uint32_t Bts[2][8 * 128];

    const int m0 = blockIdx.y * 128;
    const int n0 = blockIdx.x * 128;
    const int tid = threadIdx.x;
    const int warp = tid >> 5;
    const int lane = tid & 31;
    const int r = lane & 3;
    const int q = lane >> 2;
    const int mbase = (warp >> 2) * 64;
    const int nbase = (warp & 3) * 32;

    const int lrow = tid >> 1;          // 0..127
    const int lq   = (tid & 1) * 8;     // 0 or 8 (k offset)
    const int k2q  = lq >> 1;           // 0 or 4

    size_t aoff;
    if (GATHER) aoff = (size_t)tok[m0 + lrow] * K;
    else        aoff = (size_t)(m0 + lrow) * K;
    const __nv_bfloat16* arb = Ab  + aoff + lq;
    const __nv_bfloat16* ars = As_ + aoff + lq;
    const __nv_bfloat16* wrb = Wb  + (size_t)(n0 + lrow) * K + lq;
    const __nv_bfloat16* wrs = Ws_ + (size_t)(n0 + lrow) * K + lq;

    float acc[4][4][4];
    #pragma unroll
    for (int mf = 0; mf < 4; mf++)
        #pragma unroll
        for (int nf = 0; nf < 4; nf++)
            #pragma unroll
            for (int i = 0; i < 4; i++) acc[mf][nf][i] = 0.f;

    uint4 pab = *(const uint4*)(arb);
    uint4 pas = *(const uint4*)(ars);
    uint4 pwb = *(const uint4*)(wrb);
    uint4 pws = *(const uint4*)(wrs);

    const int niter = K / 16;
    for (int it = 0; it < niter; it++) {
        const int buf = it & 1;
        {
            const uint32_t ab[4] = {pab.x, pab.y, pab.z, pab.w};
            const uint32_t as[4] = {pas.x, pas.y, pas.z, pas.w};
            const uint32_t wb[4] = {pwb.x, pwb.y, pwb.z, pwb.w};
            const uint32_t ws[4] = {pws.x, pws.y, pws.z, pws.w};
            #pragma unroll
            for (int j2 = 0; j2 < 4; j2++) {
                const int k2 = k2q + j2;
                const int idx = k2 * 128 + (lrow ^ swz(k2));
                Atb[buf][idx] = ab[j2];
                Ats[buf][idx] = as[j2];
                Btb[buf][idx] = wb[j2];
                Bts[buf][idx] = ws[j2];
            }
        }
        if (it + 1 < niter) {
            const int k0 = (it + 1) * 16;
            pab = *(const uint4*)(arb + k0);
            pas = *(const uint4*)(ars + k0);
            pwb = *(const uint4*)(wrb + k0);
            pws = *(const uint4*)(wrs + k0);
        }
        __syncthreads();
        mma_chunk3<128>(Atb[buf], Ats[buf], Btb[buf], Bts[buf], 128, 0,
                        acc, mbase, nbase, r, q);
    }

    #pragma unroll
    for (int nf = 0; nf < 4; nf++) {
        const int n = n0 + nbase + nf * 8 + 2 * r;
        const float b0v = bias[n];
        const float b1v = bias[n + 1];
        #pragma unroll
        for (int mf = 0; mf < 4; mf++) {
            const int m = m0 + mbase + mf * 16 + q;
            size_t row0, row1;
            if (TMAJOR) {
                row0 = (size_t)((m % TT) * BB + m / TT);
                const int m8 = m + 8;
                row1 = (size_t)((m8 % TT) * BB + m8 / TT);
            } else {
                row0 = (size_t)m;
                row1 = (size_t)(m + 8);
            }
            float2 o0 = {acc[mf][nf][0] + b0v, acc[mf][nf][1] + b1v};
            float2 o1 = {acc[mf][nf][2] + b0v, acc[mf][nf][3] + b1v};
            *(float2*)(C + row0 * N + n) = o0;
            *(float2*)(C + row1 * N + n) = o1;
        }
    }
}

// ---------------- persistent LSTM layer kernel (barrier-free steady state) ----------------
// grid = 128 CTAs (16 col tiles x 8 k-splits), 256 threads. W stationary in smem.
// Per step: h-ready via cnt2[ks] (16 producers), partials-ready via 4 of 16
// per-col-tile counters (8 producers each). No global rendezvous after init.
__global__ __launch_bounds__(256, 1)
void lstm_layer(const float* __restrict__ gx, const float* __restrict__ Whh,
                const float* __restrict__ h0, const float* __restrict__ c0,
                __nv_bfloat16* __restrict__ yb, __nv_bfloat16* __restrict__ ys)
{
    extern __shared__ uint32_t dynsm[];
    uint32_t* Wb_sm = dynsm;              // [64 k2][256]
    uint32_t* Ws_sm = dynsm + 64 * 256;
    __shared__ uint32_t hsb[64 * 64];     // [64 k2][64 b]
    __shared__ uint32_t hss[64 * 64];

    const int tid = threadIdx.x;
    const int bid = blockIdx.x;       // 0..127
    const int cs  = bid & 15;
    const int ks  = bid >> 4;
    const int col0 = cs * 256;
    const int gtid = bid * 256 + tid;

    const int warp = tid >> 5;
    const int lane = tid & 31;
    const int r = lane & 3;
    const int q = lane >> 2;
    const int nbase = warp * 32;

    unsigned sense = g_barsf[(bid >> 3) * 8];

    // ---- one-time W slice load + split ----
    {
        const float* wsrc = Whh + (size_t)(col0 + tid) * HH + ks * 128;
        #pragma unroll
        for (int g = 0; g < 16; g++) {
            float4 v0 = *(const float4*)(wsrc + 8 * g);
            float4 v1 = *(const float4*)(wsrc + 8 * g + 4);
            const float wv[8] = {v0.x, v0.y, v0.z, v0.w, v1.x, v1.y, v1.z, v1.w};
            #pragma unroll
            for (int j = 0; j < 4; j++) {
                __nv_bfloat16 b0, s0, b1, s1;
                bf16_split(wv[2 * j], b0, s0);
                bf16_split(wv[2 * j + 1], b1, s1);
                const int k2 = 4 * g + j;
                const int idx = k2 * 256 + (tid ^ swz(k2));
                Wb_sm[idx] = pack_bf2(b0, b1);
                Ws_sm[idx] = pack_bf2(s0, s1);
            }
        }
    }

    // init state + reset monotonic counters
    for (int i = gtid; i < BB * HH; i += 128 * 256) {
        g_hbuf[0][i] = h0[i];
        g_c[i] = c0[i];
    }
    if (tid == 0 && bid < 8)  *((volatile unsigned*)&g_cnt2[bid * 8])  = 0u;
    if (tid == 0 && bid < 16) *((volatile unsigned*)&g_cntcs[bid * 8]) = 0u;
    grid_bar(&sense);

    const int hrow = tid >> 2;              // b 0..63
    const int hq   = (tid & 3) * 4;         // k offset within 16-chunk
    const int hk2  = hq >> 1;               // local k2 offset {0,2,4,6}

    // phase-B ks-local ownership: b in [4cs,4cs+4), j in [128ks,128ks+128)
    const int pb_b  = 4 * cs + (tid >> 6);
    const int pb_j  = 128 * ks + (tid & 63) * 2;
    const int cellp = pb_b * 1024 + pb_j;
    const int src_tile0 = ks >> 1;          // partials source col tiles: src_tile0 + 4*g

    for (int t = 0; t < TT; t++) {
        const int par = t & 1;
        float* partp = g_part[par];

        // ---- group wait: own ks-group's h values for this step are ready ----
        if (t > 0) {
            if (tid == 0) {
                const unsigned need = 16u * (unsigned)t;
                volatile unsigned* cp = &g_cnt2[ks * 8];
                while (*cp < need) { }
                __threadfence();               // acquire
            }
            __syncthreads();
        }

        // ---- stage h slice (64 b x 128 k) from hbuf[par], split, one sync ----
        const float* hbase = g_hbuf[par] + (size_t)hrow * HH + ks * 128;
        #pragma unroll
        for (int g8 = 0; g8 < 8; g8++) {
            float4 hv = *(const float4*)(hbase + g8 * 16 + hq);
            __nv_bfloat16 b0, s0v, b1, s1v, b2, s2v, b3, s3v;
            bf16_split(hv.x, b0, s0v);
            bf16_split(hv.y, b1, s1v);
            bf16_split(hv.z, b2, s2v);
            bf16_split(hv.w, b3, s3v);
            const int k2a = g8 * 8 + hk2;
            const int i0 = k2a * 64 + (hrow ^ swz(k2a));
            const int i1 = (k2a + 1) * 64 + (hrow ^ swz(k2a + 1));
            hsb[i0] = pack_bf2(b0, b1);
            hss[i0] = pack_bf2(s0v, s1v);
            hsb[i1] = pack_bf2(b2, b3);
            hss[i1] = pack_bf2(s2v, s3v);
        }
        __syncthreads();

        float acc[4][4][4];
        #pragma unroll
        for (int mf = 0; mf < 4; mf++)
            #pragma unroll
            for (int nf = 0; nf < 4; nf++)
                #pragma unroll
                for (int i = 0; i < 4; i++) acc[mf][nf][i] = 0.f;

        #pragma unroll
        for (int kc = 0; kc < 8; kc++)
            mma_chunk3<64>(hsb, hss, Wb_sm, Ws_sm, 256, kc * 8,
                           acc, 0, nbase, r, q);

        // write partials P[par][ks][b][col]
        #pragma unroll
        for (int nf = 0; nf < 4; nf++) {
            const int col = col0 + nbase + nf * 8 + 2 * r;
            #pragma unroll
            for (int mf = 0; mf < 4; mf++) {
                const int b = mf * 16 + q;
                float2 o0 = {acc[mf][nf][0], acc[mf][nf][1]};
                float2 o1 = {acc[mf][nf][2], acc[mf][nf][3]};
                *(float2*)(&partp[((size_t)ks * BB + b) * NG + col])     = o0;
                *(float2*)(&partp[((size_t)ks * BB + b + 8) * NG + col]) = o1;
            }
        }

        // ---- prefetch gx[t] and c (CTA-private cells; program-order safe) ----
        const float* gr = gx + (size_t)t * BB * NG + (size_t)pb_b * NG + pb_j;
        const float2 xg0 = *(const float2*)(gr);
        const float2 xg1 = *(const float2*)(gr + 1024);
        const float2 xg2 = *(const float2*)(gr + 2048);
        const float2 xg3 = *(const float2*)(gr + 3072);
        float2 cv = *(const float2*)(&g_c[cellp]);

        // ---- signal own partials for step t (per-col-tile counter) ----
        __syncthreads();
        if (tid == 0) {
            __threadfence();                   // release partial writes
            atomicAdd((unsigned*)&g_cntcs[cs * 8], 1u);
        }

        // ---- wait: the 4 source col tiles' partials (all 8 k-splits) ready ----
        if (tid < 4) {
            const unsigned need = 8u * (unsigned)(t + 1);
            volatile unsigned* cp = &g_cntcs[(src_tile0 + 4 * tid) * 8];
            while (*cp < need) { }
            __threadfence();                   // acquire
        }
        __syncthreads();

        // ---- Phase B: own cells, read partials[par], write hbuf[par^1] ----
        {
            float2 gi = xg0, gf = xg1, gg = xg2, go = xg3;
            #pragma unroll
            for (int s = 0; s < 8; s++) {
                const float* pp = &partp[((size_t)s * BB + pb_b) * NG + pb_j];
                const float2 p0 = *(const float2*)(pp);
                const float2 p1 = *(const float2*)(pp + 1024);
                const float2 p2 = *(const float2*)(pp + 2048);
                const float2 p3 = *(const float2*)(pp + 3072);
                gi.x += p0.x; gi.y += p0.y;
                gf.x += p1.x; gf.y += p1.y;
                gg.x += p2.x; gg.y += p2.y;
                go.x += p3.x; go.y += p3.y;
            }

            const float si0 = fast_sigmoid(gi.x);
            const float si1 = fast_sigmoid(gi.y);
            const float sf0 = fast_sigmoid(gf.x);
            const float sf1 = fast_sigmoid(gf.y);
            const float so0 = fast_sigmoid(go.x);
            const float so1 = fast_sigmoid(go.y);
            cv.x = sf0 * cv.x + si0 * fast_tanh(gg.x);
            cv.y = sf1 * cv.y + si1 * fast_tanh(gg.y);
            const float hv0 = so0 * fast_tanh(cv.x);
            const float hv1 = so1 * fast_tanh(cv.y);
            *(float2*)(&g_c[cellp]) = cv;
            float2 hw = {hv0, hv1};
            *(float2*)(&g_hbuf[par ^ 1][cellp]) = hw;

            __nv_bfloat16 hb0, hs0, hb1, hs1;
            bf16_split(hv0, hb0, hs0);
            bf16_split(hv1, hb1, hs1);
            const size_t yi = ((size_t)pb_b * TT + t) * HH + pb_j;
            *(uint32_t*)(yb + yi) = pack_bf2(hb0, hb1);
            *(uint32_t*)(ys + yi) = pack_bf2(hs0, hs1);
        }

        // ---- signal own group's h contribution for step t+1 ----
        __syncthreads();
        if (tid == 0) {
            __threadfence();                   // release h writes
            atomicAdd((unsigned*)&g_cnt2[ks * 8], 1u);
        }
    }
}

// ---------------- launch ----------------
extern "C" void kernel_launch(void* const* d_in, const int* in_sizes, int n_in,
                              void* d_out, int out_size)
{
    const int*   x    = (const int*)  d_in[0];
    const float* emb  = (const float*)d_in[1];
    const float* Wih0 = (const float*)d_in[2];
    const float* Whh0 = (const float*)d_in[3];
    const float* b0   = (const float*)d_in[4];
    const float* Wih1 = (const float*)d_in[5];
    const float* Whh1 = (const float*)d_in[6];
    const float* b1   = (const float*)d_in[7];
    const float* fcW  = (const float*)d_in[8];
    const float* fcb  = (const float*)d_in[9];
    const float* h0   = (const float*)d_in[10];
    const float* c0   = (const float*)d_in[11];
    float* out = (float*)d_out;

    float *gx;
    __nv_bfloat16 *y0b, *y0s, *y1b, *y1s, *wAb, *wAs, *embb, *embs;
    cudaGetSymbolAddress((void**)&gx,   g_gx);
    cudaGetSymbolAddress((void**)&y0b,  g_y0b);
    cudaGetSymbolAddress((void**)&y0s,  g_y0s);
    cudaGetSymbolAddress((void**)&y1b,  g_y1b);
    cudaGetSymbolAddress((void**)&y1s,  g_y1s);
    cudaGetSymbolAddress((void**)&wAb,  g_wAb);
    cudaGetSymbolAddress((void**)&wAs,  g_wAs);
    cudaGetSymbolAddress((void**)&embb, g_embb);
    cudaGetSymbolAddress((void**)&embs, g_embs);

    const int LSTM_SMEM = 64 * 256 * 2 * (int)sizeof(uint32_t);  // 128 KB dynamic
    cudaFuncSetAttribute(lstm_layer, cudaFuncAttributeMaxDynamicSharedMemorySize, LSTM_SMEM);

    const int M = BB * TT;  // 16384

    cvt_split_kernel<<<512, 256>>>(emb, embb, embs, VV * HH);
    cvt_split_kernel<<<4096, 256>>>(Wih0, wAb, wAs, NG * HH);

    sgemm_sbf16<true, true><<<dim3(NG / 128, M / 128), 256>>>(embb, embs, x, wAb, wAs, b0, gx, M, NG, HH);
    lstm_layer<<<128, 256, LSTM_SMEM>>>(gx, Whh0, h0, c0, y0b, y0s);

    cvt_split_kernel<<<4096, 256>>>(Wih1, wAb, wAs, NG * HH);

    sgemm_sbf16<false, true><<<dim3(NG / 128, M / 128), 256>>>(y0b, y0s, nullptr, wAb, wAs, b1, gx, M, NG, HH);
    lstm_layer<<<128, 256, LSTM_SMEM>>>(gx, Whh1, h0 + BB * HH, c0 + BB * HH, y1b, y1s);

    cvt_split_kernel<<<1024, 256>>>(fcW, wAb, wAs, VV * HH);
    sgemm_sbf16<false, false><<<dim3(VV / 128, M / 128), 256>>>(y1b, y1s, nullptr, wAb, wAs, fcb, out, M, VV, HH);
}

// round 13
// speedup vs baseline: 2.5753x; 1.0366x over previous
#include <cuda_runtime.h>
#include <cuda_bf16.h>
#include <math.h>
#include <stdint.h>

#define BB 64
#define TT 256
#define HH 1024
#define VV 128
#define NG 4096   // 4*H

// ---------------- device scratch (no allocations allowed) ----------------
__device__ float g_gx[BB * TT * NG];              // gate pre-activations, T-major [T][B][4H]
__device__ __nv_bfloat16 g_y0b[BB * TT * HH];     // layer-0 output big
__device__ __nv_bfloat16 g_y0s[BB * TT * HH];     // layer-0 output small
__device__ __nv_bfloat16 g_y1b[BB * TT * HH];     // layer-1 output big
__device__ __nv_bfloat16 g_y1s[BB * TT * HH];     // layer-1 output small
__device__ float g_hbuf[2][BB * HH];              // hidden state double buffer (fp32)
__device__ float g_c[BB * HH];                    // cell state (CTA-private cells)
__device__ float g_part[2][8 * BB * NG];          // k-split partials, double-buffered
__device__ __nv_bfloat16 g_wAb[NG * HH];          // W_ih / fc_W big
__device__ __nv_bfloat16 g_wAs[NG * HH];          // W_ih / fc_W small
__device__ __nv_bfloat16 g_embb[VV * HH];         // embedding big
__device__ __nv_bfloat16 g_embs[VV * HH];         // embedding small
__device__ unsigned g_barc;                       // global barrier arrival counter (init only)
__device__ volatile unsigned g_barsf[16 * 8];     // 16 release flags, 32B-spaced
__device__ volatile unsigned g_cnt2[8 * 8];       // per-ks-group h-ready counters (monotonic)
__device__ volatile unsigned g_cntcs[16 * 8];     // per-col-tile partials-ready counters (monotonic)

// ---------------- helpers ----------------
__device__ __forceinline__ void bf16_split(float x, __nv_bfloat16& b, __nv_bfloat16& s) {
    b = __float2bfloat16(x);
    s = __float2bfloat16(x - __bfloat162float(b));
}

__device__ __forceinline__ uint32_t pack_bf2(__nv_bfloat16 lo, __nv_bfloat16 hi) {
    __nv_bfloat162 t = __halves2bfloat162(lo, hi);
    return *reinterpret_cast<uint32_t*>(&t);
}

__device__ __forceinline__ int swz(int k2) {
    return 8 * (k2 & 3) + 16 * ((k2 >> 2) & 1);
}

__device__ __forceinline__ uint32_t smem_u32(const void* p) {
    uint32_t a;
    asm("{ .reg .u64 t; cvta.to.shared.u64 t, %1; cvt.u32.u64 %0, t; }" : "=r"(a) : "l"(p));
    return a;
}

__device__ __forceinline__ void mma_bf16(float* d, const uint32_t* a, const uint32_t* b) {
    asm volatile(
        "mma.sync.aligned.m16n8k16.row.col.f32.bf16.bf16.f32 "
        "{%0,%1,%2,%3}, {%4,%5,%6,%7}, {%8,%9}, {%0,%1,%2,%3};\n"
        : "+f"(d[0]), "+f"(d[1]), "+f"(d[2]), "+f"(d[3])
        : "r"(a[0]), "r"(a[1]), "r"(a[2]), "r"(a[3]), "r"(b[0]), "r"(b[1]));
}

__device__ __forceinline__ void ldsm4(uint32_t* r, uint32_t addr) {
    asm volatile(
        "ldmatrix.sync.aligned.m8n8.x4.shared.b16 {%0,%1,%2,%3}, [%4];"
        : "=r"(r[0]), "=r"(r[1]), "=r"(r[2]), "=r"(r[3]) : "r"(addr));
}

__device__ __forceinline__ float rcp_approx(float d) {
    float r;
    asm("rcp.approx.f32 %0, %1;" : "=f"(r) : "f"(d));
    return r;
}

__device__ __forceinline__ float fast_sigmoid(float x) {   // 1/(1+e^-x)
    const float a = fmaxf(fminf(-x, 40.f), -40.f);
    return rcp_approx(1.f + __expf(a));
}

__device__ __forceinline__ float fast_tanh(float x) {      // 1 - 2/(e^{2x}+1)
    const float a = fmaxf(fminf(2.f * x, 40.f), -40.f);
    return 1.f - 2.f * rcp_approx(__expf(a) + 1.f);
}

// Fused 3-product 16-k chunk for the lstm (k-major custom-swizzled layout, unchanged)
template<int LDA>
__device__ __forceinline__ void mma_chunk3(const uint32_t* Ab32, const uint32_t* As32,
                                           const uint32_t* Bb32, const uint32_t* Bs32,
                                           int ldb, int k2b,
                                           float acc[4][4][4],
                                           int mbase, int nbase, int r, int q)
{
    const int s0 = 8 * r;
    const int s1 = 8 * r + 16;
    const int ra0 = (k2b + r) * LDA;
    const int ra1 = (k2b + r + 4) * LDA;
    const int rb0 = (k2b + r) * ldb;
    const int rb1 = (k2b + r + 4) * ldb;
    uint32_t bb[4][2], bs[4][2];
    #pragma unroll
    for (int nf = 0; nf < 4; nf++) {
        const int cb = nbase + nf * 8 + q;
        bb[nf][0] = Bb32[rb0 + (cb ^ s0)];
        bb[nf][1] = Bb32[rb1 + (cb ^ s1)];
        bs[nf][0] = Bs32[rb0 + (cb ^ s0)];
        bs[nf][1] = Bs32[rb1 + (cb ^ s1)];
    }
    {
        uint32_t ab[4][4];
        #pragma unroll
        for (int mf = 0; mf < 4; mf++) {
            const int c0 = mbase + mf * 16 + q;
            ab[mf][0] = Ab32[ra0 + (c0 ^ s0)];
            ab[mf][1] = Ab32[ra0 + ((c0 + 8) ^ s0)];
            ab[mf][2] = Ab32[ra1 + (c0 ^ s1)];
            ab[mf][3] = Ab32[ra1 + ((c0 + 8) ^ s1)];
        }
        #pragma unroll
        for (int mf = 0; mf < 4; mf++)
            #pragma unroll
            for (int nf = 0; nf < 4; nf++)
                mma_bf16(acc[mf][nf], ab[mf], bb[nf]);
        #pragma unroll
        for (int mf = 0; mf < 4; mf++)
            #pragma unroll
            for (int nf = 0; nf < 4; nf++)
                mma_bf16(acc[mf][nf], ab[mf], bs[nf]);
    }
    {
        uint32_t as[4][4];
        #pragma unroll
        for (int mf = 0; mf < 4; mf++) {
            const int c0 = mbase + mf * 16 + q;
            as[mf][0] = As32[ra0 + (c0 ^ s0)];
            as[mf][1] = As32[ra0 + ((c0 + 8) ^ s0)];
            as[mf][2] = As32[ra1 + (c0 ^ s1)];
            as[mf][3] = As32[ra1 + ((c0 + 8) ^ s1)];
        }
        #pragma unroll
        for (int mf = 0; mf < 4; mf++)
            #pragma unroll
            for (int nf = 0; nf < 4; nf++)
                mma_bf16(acc[mf][nf], as[mf], bb[nf]);
    }
}

// ---------------- global barrier (init only) ----------------
__device__ __forceinline__ void grid_bar(unsigned* sense) {
    __syncthreads();
    if (threadIdx.x == 0) {
        unsigned s = *sense ^ 1u;
        *sense = s;
        __threadfence();                       // release
        unsigned prev = atomicAdd(&g_barc, 1u);
        if (prev == gridDim.x - 1) {
            g_barc = 0u;
            __threadfence();
            #pragma unroll
            for (int i = 0; i < 16; i++) g_barsf[i * 8] = s;
        } else {
            volatile unsigned* f = &g_barsf[(blockIdx.x >> 3) * 8];
            while (*f != s) { }
            __threadfence();                   // acquire
        }
    }
    __syncthreads();
}

// ---------------- fp32 -> (bf16 big, bf16 small) split ----------------
__global__ void cvt_split_kernel(const float* __restrict__ src,
                                 __nv_bfloat16* __restrict__ dstb,
                                 __nv_bfloat16* __restrict__ dsts, int n) {
    for (int i = blockIdx.x * blockDim.x + threadIdx.x; i < n; i += gridDim.x * blockDim.x) {
        __nv_bfloat16 b, s;
        bf16_split(src[i], b, s);
        dstb[i] = b;
        dsts[i] = s;
    }
}

// ---------------- ldmatrix split-bf16 SGEMM: C = A @ W^T + bias ----------------
// BM=128, BN=128, BK=32 slices, double-buffered (1 sync/slice), 8 warps (2m x 4n).
// Smem: m/n-major 64-B rows, SW64 swizzle; all fragments via ldmatrix.x4.
// Dyn smem: 2 bufs x [Ab | As | Bb | Bs] x 8 KB = 64 KB.
template <bool GATHER, bool TMAJOR>
__global__ __launch_bounds__(256, 2)
void sgemm_ldsm(const __nv_bfloat16* __restrict__ Ab, const __nv_bfloat16* __restrict__ As_,
                const int* __restrict__ tok,
                const __nv_bfloat16* __restrict__ Wb, const __nv_bfloat16* __restrict__ Ws_,
                const float* __restrict__ bias,
                float* __restrict__ C, int M, int N, int K)
{
    extern __shared__ uint8_t smg_raw[];
    uint8_t* smg = (uint8_t*)(((uintptr_t)smg_raw + 127) & ~(uintptr_t)127);
    const uint32_t smb = smem_u32(smg);

    const int tid = threadIdx.x;
    const int warp = tid >> 5;
    const int lane = tid & 31;
    const int m0 = blockIdx.y * 128;
    const int n0 = blockIdx.x * 128;
    const int mbase = (warp >> 2) * 64;
    const int nbase = (warp & 3) * 32;
    const int r = lane & 3;
    const int q = lane >> 2;

    // ldmatrix per-lane swizzled offsets (kc composes as XOR 32)
    uint32_t offA[4], offB[2];
    {
        const int ar = (lane & 7) + 8 * ((lane >> 3) & 1);
        const int abyt = ((lane >> 4) & 1) * 16;
        #pragma unroll
        for (int mf = 0; mf < 4; mf++) {
            const int off = (mbase + mf * 16 + ar) * 64 + abyt;
            offA[mf] = off ^ ((off >> 3) & 0x30);
        }
        const int br = (lane & 7) + 8 * ((lane >> 4) & 1);
        const int bbyt = ((lane >> 3) & 1) * 16;
        #pragma unroll
        for (int n2 = 0; n2 < 2; n2++) {
            const int off = (nbase + n2 * 16 + br) * 64 + bbyt;
            offB[n2] = off ^ ((off >> 3) & 0x30);
        }
    }

    // staging offsets (identical for all 4 parts): row = tid>>1, 32-B half = tid&1
    const int srow = tid >> 1;
    const int so0i = srow * 64 + (tid & 1) * 32;
    const uint32_t so0 = so0i ^ ((so0i >> 3) & 0x30);
    const int so1i = so0i + 16;
    const uint32_t so1 = so1i ^ ((so1i >> 3) & 0x30);

    size_t aoff;
    if (GATHER) aoff = (size_t)tok[m0 + srow] * K;
    else        aoff = (size_t)(m0 + srow) * K;
    const __nv_bfloat16* arb = Ab  + aoff + (tid & 1) * 16;
    const __nv_bfloat16* ars = As_ + aoff + (tid & 1) * 16;
    const __nv_bfloat16* wrb = Wb  + (size_t)(n0 + srow) * K + (tid & 1) * 16;
    const __nv_bfloat16* wrs = Ws_ + (size_t)(n0 + srow) * K + (tid & 1) * 16;

    float acc[4][4][4];
    #pragma unroll
    for (int mf = 0; mf < 4; mf++)
        #pragma unroll
        for (int nf = 0; nf < 4; nf++)
            #pragma unroll
            for (int i = 0; i < 4; i++) acc[mf][nf][i] = 0.f;

    uint4 pab0 = *(const uint4*)(arb);
    uint4 pab1 = *(const uint4*)(arb + 8);
    uint4 pas0 = *(const uint4*)(ars);
    uint4 pas1 = *(const uint4*)(ars + 8);
    uint4 pwb0 = *(const uint4*)(wrb);
    uint4 pwb1 = *(const uint4*)(wrb + 8);
    uint4 pws0 = *(const uint4*)(wrs);
    uint4 pws1 = *(const uint4*)(wrs + 8);

    const int nslice = K / 32;
    for (int s = 0; s < nslice; s++) {
        const uint32_t bo = (uint32_t)(s & 1) * 32768u;
        *(uint4*)(smg + bo + so0)         = pab0;
        *(uint4*)(smg + bo + so1)         = pab1;
        *(uint4*)(smg + bo + 8192 + so0)  = pas0;
        *(uint4*)(smg + bo + 8192 + so1)  = pas1;
        *(uint4*)(smg + bo + 16384 + so0) = pwb0;
        *(uint4*)(smg + bo + 16384 + so1) = pwb1;
        *(uint4*)(smg + bo + 24576 + so0) = pws0;
        *(uint4*)(smg + bo + 24576 + so1) = pws1;
        if (s + 1 < nslice) {
            const int k0 = (s + 1) * 32;
            pab0 = *(const uint4*)(arb + k0);
            pab1 = *(const uint4*)(arb + k0 + 8);
            pas0 = *(const uint4*)(ars + k0);
            pas1 = *(const uint4*)(ars + k0 + 8);
            pwb0 = *(const uint4*)(wrb + k0);
            pwb1 = *(const uint4*)(wrb + k0 + 8);
            pws0 = *(const uint4*)(wrs + k0);
            pws1 = *(const uint4*)(wrs + k0 + 8);
        }
        __syncthreads();

        const uint32_t bAb = smb + bo;
        const uint32_t bAs = bAb + 8192;
        const uint32_t bBb = bAb + 16384;
        const uint32_t bBs = bAb + 24576;
        #pragma unroll
        for (int kc = 0; kc < 2; kc++) {
            const uint32_t kcb = (uint32_t)kc * 32u;
            uint32_t abf[4][4], bbf[2][4];
            #pragma unroll
            for (int mf = 0; mf < 4; mf++) ldsm4(abf[mf], bAb + (offA[mf] ^ kcb));
            #pragma unroll
            for (int n2 = 0; n2 < 2; n2++) ldsm4(bbf[n2], bBb + (offB[n2] ^ kcb));
            #pragma unroll
            for (int mf = 0; mf < 4; mf++)
                #pragma unroll
                for (int nf = 0; nf < 4; nf++)
                    mma_bf16(acc[mf][nf], abf[mf], &bbf[nf >> 1][(nf & 1) * 2]);
            {
                uint32_t bsf[2][4];
                #pragma unroll
                for (int n2 = 0; n2 < 2; n2++) ldsm4(bsf[n2], bBs + (offB[n2] ^ kcb));
                #pragma unroll
                for (int mf = 0; mf < 4; mf++)
                    #pragma unroll
                    for (int nf = 0; nf < 4; nf++)
                        mma_bf16(acc[mf][nf], abf[mf], &bsf[nf >> 1][(nf & 1) * 2]);
            }
            {
                uint32_t asf[4][4];
                #pragma unroll
                for (int mf = 0; mf < 4; mf++) ldsm4(asf[mf], bAs + (offA[mf] ^ kcb));
                #pragma unroll
                for (int mf = 0; mf < 4; mf++)
                    #pragma unroll
                    for (int nf = 0; nf < 4; nf++)
                        mma_bf16(acc[mf][nf], asf[mf], &bbf[nf >> 1][(nf & 1) * 2]);
            }
        }
    }

    #pragma unroll
    for (int nf = 0; nf < 4; nf++) {
        const int n = n0 + nbase + nf * 8 + 2 * r;
        const float b0v = bias[n];
        const float b1v = bias[n + 1];
        #pragma unroll
        for (int mf = 0; mf < 4; mf++) {
            const int m = m0 + mbase + mf * 16 + q;
            size_t row0, row1;
            if (TMAJOR) {
                row0 = (size_t)((m % TT) * BB + m / TT);
                const int m8 = m + 8;
                row1 = (size_t)((m8 % TT) * BB + m8 / TT);
            } else {
                row0 = (size_t)m;
                row1 = (size_t)(m + 8);
            }
            float2 o0 = {acc[mf][nf][0] + b0v, acc[mf][nf][1] + b1v};
            float2 o1 = {acc[mf][nf][2] + b0v, acc[mf][nf][3] + b1v};
            *(float2*)(C + row0 * N + n) = o0;
            *(float2*)(C + row1 * N + n) = o1;
        }
    }
}

// ---------------- persistent LSTM layer kernel (barrier-free steady state; unchanged R12) ----------------
__global__ __launch_bounds__(256, 1)
void lstm_layer(const float* __restrict__ gx, const float* __restrict__ Whh,
                const float* __restrict__ h0, const float* __restrict__ c0,
                __nv_bfloat16* __restrict__ yb, __nv_bfloat16* __restrict__ ys)
{
    extern __shared__ uint32_t dynsm[];
    uint32_t* Wb_sm = dynsm;              // [64 k2][256]
    uint32_t* Ws_sm = dynsm + 64 * 256;
    __shared__ uint32_t hsb[64 * 64];     // [64 k2][64 b]
    __shared__ uint32_t hss[64 * 64];

    const int tid = threadIdx.x;
    const int bid = blockIdx.x;       // 0..127
    const int cs  = bid & 15;
    const int ks  = bid >> 4;
    const int col0 = cs * 256;
    const int gtid = bid * 256 + tid;

    const int warp = tid >> 5;
    const int lane = tid & 31;
    const int r = lane & 3;
    const int q = lane >> 2;
    const int nbase = warp * 32;

    unsigned sense = g_barsf[(bid >> 3) * 8];

    // ---- one-time W slice load + split ----
    {
        const float* wsrc = Whh + (size_t)(col0 + tid) * HH + ks * 128;
        #pragma unroll
        for (int g = 0; g < 16; g++) {
            float4 v0 = *(const float4*)(wsrc + 8 * g);
            float4 v1 = *(const float4*)(wsrc + 8 * g + 4);
            const float wv[8] = {v0.x, v0.y, v0.z, v0.w, v1.x, v1.y, v1.z, v1.w};
            #pragma unroll
            for (int j = 0; j < 4; j++) {
                __nv_bfloat16 b0, s0, b1, s1;
                bf16_split(wv[2 * j], b0, s0);
                bf16_split(wv[2 * j + 1], b1, s1);
                const int k2 = 4 * g + j;
                const int idx = k2 * 256 + (tid ^ swz(k2));
                Wb_sm[idx] = pack_bf2(b0, b1);
                Ws_sm[idx] = pack_bf2(s0, s1);
            }
        }
    }

    // init state + reset monotonic counters
    for (int i = gtid; i < BB * HH; i += 128 * 256) {
        g_hbuf[0][i] = h0[i];
        g_c[i] = c0[i];
    }
    if (tid == 0 && bid < 8)  *((volatile unsigned*)&g_cnt2[bid * 8])  = 0u;
    if (tid == 0 && bid < 16) *((volatile unsigned*)&g_cntcs[bid * 8]) = 0u;
    grid_bar(&sense);

    const int hrow = tid >> 2;              // b 0..63
    const int hq   = (tid & 3) * 4;         // k offset within 16-chunk
    const int hk2  = hq >> 1;               // local k2 offset {0,2,4,6}

    // phase-B ks-local ownership: b in [4cs,4cs+4), j in [128ks,128ks+128)
    const int pb_b  = 4 * cs + (tid >> 6);
    const int pb_j  = 128 * ks + (tid & 63) * 2;
    const int cellp = pb_b * 1024 + pb_j;
    const int src_tile0 = ks >> 1;          // partials source col tiles: src_tile0 + 4*g

    for (int t = 0; t < TT; t++) {
        const int par = t & 1;
        float* partp = g_part[par];

        // ---- group wait: own ks-group's h values for this step are ready ----
        if (t > 0) {
            if (tid == 0) {
                const unsigned need = 16u * (unsigned)t;
                volatile unsigned* cp = &g_cnt2[ks * 8];
                while (*cp < need) { }
                __threadfence();               // acquire
            }
            __syncthreads();
        }

        // ---- stage h slice (64 b x 128 k) from hbuf[par], split, one sync ----
        const float* hbase = g_hbuf[par] + (size_t)hrow * HH + ks * 128;
        #pragma unroll
        for (int g8 = 0; g8 < 8; g8++) {
            float4 hv = *(const float4*)(hbase + g8 * 16 + hq);
            __nv_bfloat16 b0, s0v, b1, s1v, b2, s2v, b3, s3v;
            bf16_split(hv.x, b0, s0v);
            bf16_split(hv.y, b1, s1v);
            bf16_split(hv.z, b2, s2v);
            bf16_split(hv.w, b3, s3v);
            const int k2a = g8 * 8 + hk2;
            const int i0 = k2a * 64 + (hrow ^ swz(k2a));
            const int i1 = (k2a + 1) * 64 + (hrow ^ swz(k2a + 1));
            hsb[i0] = pack_bf2(b0, b1);
            hss[i0] = pack_bf2(s0v, s1v);
            hsb[i1] = pack_bf2(b2, b3);
            hss[i1] = pack_bf2(s2v, s3v);
        }
        __syncthreads();

        float acc[4][4][4];
        #pragma unroll
        for (int mf = 0; mf < 4; mf++)
            #pragma unroll
            for (int nf = 0; nf < 4; nf++)
                #pragma unroll
                for (int i = 0; i < 4; i++) acc[mf][nf][i] = 0.f;

        #pragma unroll
        for (int kc = 0; kc < 8; kc++)
            mma_chunk3<64>(hsb, hss, Wb_sm, Ws_sm, 256, kc * 8,
                           acc, 0, nbase, r, q);

        // write partials P[par][ks][b][col]
        #pragma unroll
        for (int nf = 0; nf < 4; nf++) {
            const int col = col0 + nbase + nf * 8 + 2 * r;
            #pragma unroll
            for (int mf = 0; mf < 4; mf++) {
                const int b = mf * 16 + q;
                float2 o0 = {acc[mf][nf][0], acc[mf][nf][1]};
                float2 o1 = {acc[mf][nf][2], acc[mf][nf][3]};
                *(float2*)(&partp[((size_t)ks * BB + b) * NG + col])     = o0;
                *(float2*)(&partp[((size_t)ks * BB + b + 8) * NG + col]) = o1;
            }
        }

        // ---- prefetch gx[t] and c (CTA-private cells; program-order safe) ----
        const float* gr = gx + (size_t)t * BB * NG + (size_t)pb_b * NG + pb_j;
        const float2 xg0 = *(const float2*)(gr);
        const float2 xg1 = *(const float2*)(gr + 1024);
        const float2 xg2 = *(const float2*)(gr + 2048);
        const float2 xg3 = *(const float2*)(gr + 3072);
        float2 cv = *(const float2*)(&g_c[cellp]);

        // ---- signal own partials for step t (per-col-tile counter) ----
        __syncthreads();
        if (tid == 0) {
            __threadfence();                   // release partial writes
            atomicAdd((unsigned*)&g_cntcs[cs * 8], 1u);
        }

        // ---- wait: the 4 source col tiles' partials (all 8 k-splits) ready ----
        if (tid < 4) {
            const unsigned need = 8u * (unsigned)(t + 1);
            volatile unsigned* cp = &g_cntcs[(src_tile0 + 4 * tid) * 8];
            while (*cp < need) { }
            __threadfence();                   // acquire
        }
        __syncthreads();

        // ---- Phase B: own cells, read partials[par], write hbuf[par^1] ----
        {
            float2 gi = xg0, gf = xg1, gg = xg2, go = xg3;
            #pragma unroll
            for (int s = 0; s < 8; s++) {
                const float* pp = &partp[((size_t)s * BB + pb_b) * NG + pb_j];
                const float2 p0 = *(const float2*)(pp);
                const float2 p1 = *(const float2*)(pp + 1024);
                const float2 p2 = *(const float2*)(pp + 2048);
                const float2 p3 = *(const float2*)(pp + 3072);
                gi.x += p0.x; gi.y += p0.y;
                gf.x += p1.x; gf.y += p1.y;
                gg.x += p2.x; gg.y += p2.y;
                go.x += p3.x; go.y += p3.y;
            }

            const float si0 = fast_sigmoid(gi.x);
            const float si1 = fast_sigmoid(gi.y);
            const float sf0 = fast_sigmoid(gf.x);
            const float sf1 = fast_sigmoid(gf.y);
            const float so0 = fast_sigmoid(go.x);
            const float so1 = fast_sigmoid(go.y);
            cv.x = sf0 * cv.x + si0 * fast_tanh(gg.x);
            cv.y = sf1 * cv.y + si1 * fast_tanh(gg.y);
            const float hv0 = so0 * fast_tanh(cv.x);
            const float hv1 = so1 * fast_tanh(cv.y);
            *(float2*)(&g_c[cellp]) = cv;
            float2 hw = {hv0, hv1};
            *(float2*)(&g_hbuf[par ^ 1][cellp]) = hw;

            __nv_bfloat16 hb0, hs0, hb1, hs1;
            bf16_split(hv0, hb0, hs0);
            bf16_split(hv1, hb1, hs1);
            const size_t yi = ((size_t)pb_b * TT + t) * HH + pb_j;
            *(uint32_t*)(yb + yi) = pack_bf2(hb0, hb1);
            *(uint32_t*)(ys + yi) = pack_bf2(hs0, hs1);
        }

        // ---- signal own group's h contribution for step t+1 ----
        __syncthreads();
        if (tid == 0) {
            __threadfence();                   // release h writes
            atomicAdd((unsigned*)&g_cnt2[ks * 8], 1u);
        }
    }
}

// ---------------- launch ----------------
extern "C" void kernel_launch(void* const* d_in, const int* in_sizes, int n_in,
                              void* d_out, int out_size)
{
    const int*   x    = (const int*)  d_in[0];
    const float* emb  = (const float*)d_in[1];
    const float* Wih0 = (const float*)d_in[2];
    const float* Whh0 = (const float*)d_in[3];
    const float* b0   = (const float*)d_in[4];
    const float* Wih1 = (const float*)d_in[5];
    const float* Whh1 = (const float*)d_in[6];
    const float* b1   = (const float*)d_in[7];
    const float* fcW  = (const float*)d_in[8];
    const float* fcb  = (const float*)d_in[9];
    const float* h0   = (const float*)d_in[10];
    const float* c0   = (const float*)d_in[11];
    float* out = (float*)d_out;

    float *gx;
    __nv_bfloat16 *y0b, *y0s, *y1b, *y1s, *wAb, *wAs, *embb, *embs;
    cudaGetSymbolAddress((void**)&gx,   g_gx);
    cudaGetSymbolAddress((void**)&y0b,  g_y0b);
    cudaGetSymbolAddress((void**)&y0s,  g_y0s);
    cudaGetSymbolAddress((void**)&y1b,  g_y1b);
    cudaGetSymbolAddress((void**)&y1s,  g_y1s);
    cudaGetSymbolAddress((void**)&wAb,  g_wAb);
    cudaGetSymbolAddress((void**)&wAs,  g_wAs);
    cudaGetSymbolAddress((void**)&embb, g_embb);
    cudaGetSymbolAddress((void**)&embs, g_embs);

    const int LSTM_SMEM = 64 * 256 * 2 * (int)sizeof(uint32_t);  // 128 KB dynamic
    cudaFuncSetAttribute(lstm_layer, cudaFuncAttributeMaxDynamicSharedMemorySize, LSTM_SMEM);

    const int SG_SMEM = 65536 + 128;
    cudaFuncSetAttribute(sgemm_ldsm<true,  true>,  cudaFuncAttributeMaxDynamicSharedMemorySize, SG_SMEM);
    cudaFuncSetAttribute(sgemm_ldsm<false, true>,  cudaFuncAttributeMaxDynamicSharedMemorySize, SG_SMEM);
    cudaFuncSetAttribute(sgemm_ldsm<false, false>, cudaFuncAttributeMaxDynamicSharedMemorySize, SG_SMEM);

    const int M = BB * TT;  // 16384

    cvt_split_kernel<<<512, 256>>>(emb, embb, embs, VV * HH);
    cvt_split_kernel<<<4096, 256>>>(Wih0, wAb, wAs, NG * HH);

    sgemm_ldsm<true, true><<<dim3(NG / 128, M / 128), 256, SG_SMEM>>>(
        embb, embs, x, wAb, wAs, b0, gx, M, NG, HH);
    lstm_layer<<<128, 256, LSTM_SMEM>>>(gx, Whh0, h0, c0, y0b, y0s);

    cvt_split_kernel<<<4096, 256>>>(Wih1, wAb, wAs, NG * HH);

    sgemm_ldsm<false, true><<<dim3(NG / 128, M / 128), 256, SG_SMEM>>>(
        y0b, y0s, nullptr, wAb, wAs, b1, gx, M, NG, HH);
    lstm_layer<<<128, 256, LSTM_SMEM>>>(gx, Whh1, h0 + BB * HH, c0 + BB * HH, y1b, y1s);

    cvt_split_kernel<<<1024, 256>>>(fcW, wAb, wAs, VV * HH);
    sgemm_ldsm<false, false><<<dim3(VV / 128, M / 128), 256, SG_SMEM>>>(
        y1b, y1s, nullptr, wAb, wAs, fcb, out, M, VV, HH);
}